// round 7
// baseline (speedup 1.0000x reference)
#include <cuda_runtime.h>
#include <cuda_bf16.h>
#include <cstdint>
#include <math.h>

#define BATCH 8
#define C 128
#define NN 4096
#define D 16
#define G 32
#define CPG (C / G)
#define EPS 1e-5f
#define SCALE_Q 0.36067376022224085f   // 0.25 * log2(e)

// ---------------- scratch ----------------------------------------------------
__device__ float          g_qt [BATCH * NN * D];   // q [B,N,16] tf32 bits, scaled
__device__ float          g_kt [BATCH * NN * D];   // k [B,N,16] tf32 bits, pair-permuted
__device__ __nv_bfloat16  g_v  [BATCH * C * NN];   // v [B,C,N] bf16
__device__ __nv_bfloat16  g_pwb[C * C];            // p_w bf16 [e][c]
__device__ float          g_st [BATCH * G * 2];    // groupnorm (mean, rstd)

// ---------------- GroupNorm stats only ---------------------------------------
__global__ __launch_bounds__(256) void gn_stats_kernel(
    const float* __restrict__ x, float* __restrict__ st)
{
    const int b = blockIdx.x >> 5;
    const int g = blockIdx.x & 31;
    const float* xp = x + ((size_t)b * C + g * CPG) * NN;

    const int TOT = CPG * NN;
    float s = 0.f, s2 = 0.f;
    for (int idx = threadIdx.x; idx < TOT; idx += 256) {
        float v = xp[idx];
        s += v; s2 += v * v;
    }
    __shared__ float red[16];
    int lane = threadIdx.x & 31, wid = threadIdx.x >> 5;
    #pragma unroll
    for (int o = 16; o > 0; o >>= 1) {
        s  += __shfl_xor_sync(0xffffffffu, s,  o);
        s2 += __shfl_xor_sync(0xffffffffu, s2, o);
    }
    if (lane == 0) { red[wid] = s; red[8 + wid] = s2; }
    __syncthreads();
    if (wid == 0) {
        float a = (lane < 8) ? red[lane] : 0.f;
        float a2 = (lane < 8) ? red[8 + lane] : 0.f;
        #pragma unroll
        for (int o = 4; o > 0; o >>= 1) {
            a  += __shfl_xor_sync(0xffffffffu, a,  o);
            a2 += __shfl_xor_sync(0xffffffffu, a2, o);
        }
        if (lane == 0) {
            const float inv_n = 1.f / (float)TOT;
            float mean = a * inv_n;
            float var = a2 * inv_n - mean * mean;
            st[blockIdx.x * 2]     = mean;
            st[blockIdx.x * 2 + 1] = rsqrtf(var + EPS);
        }
    }
}

// ---------------- p_w -> bf16 ------------------------------------------------
__global__ void pwcvt_kernel(const float* __restrict__ pw,
                             __nv_bfloat16* __restrict__ pwb)
{
    int i = blockIdx.x * 1024 + threadIdx.x;
    pwb[i] = __float2bfloat16_rn(pw[i]);
}

// ---------------- mma helpers ------------------------------------------------
__device__ __forceinline__ uint32_t smem_u32(const void* p) {
    uint32_t a;
    asm("{ .reg .u64 t; cvta.to.shared.u64 t, %1; cvt.u32.u64 %0, t; }" : "=r"(a) : "l"(p));
    return a;
}
__device__ __forceinline__ void cpa16(uint32_t s, const void* g) {
    asm volatile("cp.async.cg.shared.global [%0], [%1], 16;" :: "r"(s), "l"(g));
}
#define CP_COMMIT() asm volatile("cp.async.commit_group;" ::: "memory")
#define CP_WAIT1()  asm volatile("cp.async.wait_group 1;" ::: "memory")
#define CP_WAIT0()  asm volatile("cp.async.wait_group 0;" ::: "memory")

__device__ __forceinline__ uint32_t f2tf(float f) {
    uint32_t u; asm("cvt.rna.tf32.f32 %0, %1;" : "=r"(u) : "f"(f)); return u;
}
__device__ __forceinline__ float ex2f(float f) {
    float r; asm("ex2.approx.f32 %0, %1;" : "=f"(r) : "f"(f)); return r;
}
__device__ __forceinline__ uint32_t bf2(float hi, float lo) {
    uint32_t r; asm("cvt.rn.bf16x2.f32 %0, %1, %2;" : "=r"(r) : "f"(hi), "f"(lo)); return r;
}
__device__ __forceinline__ void mma_tf32(float* c, const uint32_t* a,
                                         uint32_t b0, uint32_t b1) {
    asm volatile(
        "mma.sync.aligned.m16n8k8.row.col.f32.tf32.tf32.f32 "
        "{%0,%1,%2,%3},{%4,%5,%6,%7},{%8,%9},{%0,%1,%2,%3};"
        : "+f"(c[0]), "+f"(c[1]), "+f"(c[2]), "+f"(c[3])
        : "r"(a[0]), "r"(a[1]), "r"(a[2]), "r"(a[3]), "r"(b0), "r"(b1));
}
__device__ __forceinline__ void mma_bf16(float* c, uint32_t a0, uint32_t a1,
                                         uint32_t a2, uint32_t a3,
                                         uint32_t b0, uint32_t b1) {
    asm volatile(
        "mma.sync.aligned.m16n8k16.row.col.f32.bf16.bf16.f32 "
        "{%0,%1,%2,%3},{%4,%5,%6,%7},{%8,%9},{%0,%1,%2,%3};"
        : "+f"(c[0]), "+f"(c[1]), "+f"(c[2]), "+f"(c[3])
        : "r"(a0), "r"(a1), "r"(a2), "r"(a3), "r"(b0), "r"(b1));
}
__device__ __forceinline__ void ldm4(uint32_t& r0, uint32_t& r1, uint32_t& r2,
                                     uint32_t& r3, uint32_t addr) {
    asm volatile("ldmatrix.sync.aligned.m8n8.x4.shared.b16 {%0,%1,%2,%3}, [%4];"
                 : "=r"(r0), "=r"(r1), "=r"(r2), "=r"(r3) : "r"(addr));
}
// k pair-permutation: dim d -> slot; slots (2t,2t+1) hold dims (t, t+4) per 8-block
__device__ __forceinline__ int kperm(int e) {
    return (e & 8) | ((e & 3) << 1) | ((e >> 2) & 1);
}

// ============================================================================
//   fused GN + QKV projection (tf32 mma): q/k written as tf32 bits, v bf16
// ============================================================================
#define PJ_HT   0
#define PJ_WS   67584
#define PJ_BIAS 152064
#define PJ_SC   152704
#define SMEM_PJ 153728

__global__ __launch_bounds__(256) void qkv_proj_kernel(
    const float* __restrict__ qw, const float* __restrict__ qb,
    const float* __restrict__ kw, const float* __restrict__ kb,
    const float* __restrict__ vw, const float* __restrict__ vb,
    const float* __restrict__ gnw, const float* __restrict__ gnb,
    const float* __restrict__ st, const float* __restrict__ x,
    float* __restrict__ qt, float* __restrict__ kt,
    __nv_bfloat16* __restrict__ vout)
{
    extern __shared__ char sm[];
    uint32_t* hT = (uint32_t*)(sm + PJ_HT);
    uint32_t* Ws = (uint32_t*)(sm + PJ_WS);
    float* bs = (float*)(sm + PJ_BIAS);
    float* sc = (float*)(sm + PJ_SC);
    float* sh = sc + 128;
    const int tid = threadIdx.x;
    const int w = tid >> 5, lane = tid & 31;
    const int g = lane >> 2, t = lane & 3;
    const int n0 = blockIdx.x * 128;
    const int b = blockIdx.y;

    if (tid < 128) {
        float mean = st[(b * G + (tid >> 2)) * 2];
        float inv  = st[(b * G + (tid >> 2)) * 2 + 1];
        float s = gnw[tid] * inv;
        sc[tid] = s;
        sh[tid] = gnb[tid] - mean * s;
    }
    for (int u = tid; u < 160 * 128; u += 256) {
        int e = u >> 7, c = u & 127;
        float wv;
        if (e < 16)      wv = qw[e * C + c];
        else if (e < 32) wv = kw[(e - 16) * C + c];
        else             wv = vw[(e - 32) * C + c];
        Ws[e * 132 + c] = f2tf(wv);
    }
    if (tid < 160) {
        float bv;
        if (tid < 16)      bv = qb[tid];
        else if (tid < 32) bv = kb[tid - 16];
        else               bv = vb[tid - 32];
        bs[tid] = bv;
    }
    __syncthreads();

    for (int u = tid; u < 128 * 128; u += 256) {
        int n = u & 127, c = u >> 7;
        float hv = fmaf(x[((size_t)b * C + c) * NN + n0 + n], sc[c], sh[c]);
        hT[n * 132 + c] = f2tf(hv);
    }
    __syncthreads();

    uint32_t af[16][4];
    #pragma unroll
    for (int kc = 0; kc < 16; kc++) {
        af[kc][0] = hT[(16 * w + g    ) * 132 + 8 * kc + t    ];
        af[kc][1] = hT[(16 * w + g + 8) * 132 + 8 * kc + t    ];
        af[kc][2] = hT[(16 * w + g    ) * 132 + 8 * kc + t + 4];
        af[kc][3] = hT[(16 * w + g + 8) * 132 + 8 * kc + t + 4];
    }

    float pr[20][4];
    #pragma unroll
    for (int nb = 0; nb < 20; nb++)
        #pragma unroll
        for (int i = 0; i < 4; i++) pr[nb][i] = 0.f;

    #pragma unroll
    for (int kc = 0; kc < 16; kc++) {
        #pragma unroll
        for (int nb = 0; nb < 20; nb++) {
            uint32_t b0 = Ws[(8 * nb + g) * 132 + 8 * kc + t    ];
            uint32_t b1 = Ws[(8 * nb + g) * 132 + 8 * kc + t + 4];
            mma_tf32(pr[nb], af[kc], b0, b1);
        }
    }

    const int r0 = 16 * w + g, r1 = r0 + 8;
    #pragma unroll
    for (int nb = 0; nb < 4; nb++) {
        int e = 8 * nb + 2 * t;
        float b0 = bs[e], b1 = bs[e + 1];
        if (e < 16) {   // q: unpermuted, pre-scaled tf32 bits
            float2 lo = make_float2(
                __uint_as_float(f2tf((pr[nb][0] + b0) * SCALE_Q)),
                __uint_as_float(f2tf((pr[nb][1] + b1) * SCALE_Q)));
            float2 hi = make_float2(
                __uint_as_float(f2tf((pr[nb][2] + b0) * SCALE_Q)),
                __uint_as_float(f2tf((pr[nb][3] + b1) * SCALE_Q)));
            *(float2*)&qt[((size_t)b * NN + n0 + r0) * D + e] = lo;
            *(float2*)&qt[((size_t)b * NN + n0 + r1) * D + e] = hi;
        } else {        // k: pair-permuted tf32 bits (scalar stores)
            int E = e - 16;
            float* k0 = &kt[((size_t)b * NN + n0 + r0) * D];
            float* k1 = &kt[((size_t)b * NN + n0 + r1) * D];
            k0[kperm(E)]     = __uint_as_float(f2tf(pr[nb][0] + b0));
            k0[kperm(E + 1)] = __uint_as_float(f2tf(pr[nb][1] + b1));
            k1[kperm(E)]     = __uint_as_float(f2tf(pr[nb][2] + b0));
            k1[kperm(E + 1)] = __uint_as_float(f2tf(pr[nb][3] + b1));
        }
    }
    __syncthreads();

    __nv_bfloat16* vstage = (__nv_bfloat16*)(sm + PJ_WS);
    #pragma unroll
    for (int nb = 4; nb < 20; nb++) {
        int e = 8 * nb + 2 * t;
        int cv = e - 32;
        float b0 = bs[e], b1 = bs[e + 1];
        vstage[(cv    ) * 132 + r0] = __float2bfloat16_rn(pr[nb][0] + b0);
        vstage[(cv + 1) * 132 + r0] = __float2bfloat16_rn(pr[nb][1] + b1);
        vstage[(cv    ) * 132 + r1] = __float2bfloat16_rn(pr[nb][2] + b0);
        vstage[(cv + 1) * 132 + r1] = __float2bfloat16_rn(pr[nb][3] + b1);
    }
    __syncthreads();
    for (int u = tid; u < 128 * 32; u += 256) {
        int c = u >> 5, nc = u & 31;
        *(uint64_t*)&vout[((size_t)b * C + c) * NN + n0 + nc * 4] =
            *(const uint64_t*)&vstage[c * 132 + nc * 4];
    }
}

// ============================================================================
//   flash attention v2: PV re-tiled 32 rows x 64 chans/warp, P smem exchange
// ============================================================================
#define OFF_V0  0        // bf16 [128][136] 34816
#define OFF_V1  34816
#define OFF_K   69632    // f32 [128][20]   10240 (single buffer)
#define OFF_PX  79872    // P / O fragment exchange, 32768
#define OFF_LS  112640   // 128 f32 row sums
#define OFF_PW  0        // pw over V0 at tile 31
#define OFF_STG 34816    // f32 [128][132] over V1+K+PX
#define SMEM_FL 113152

__global__ __launch_bounds__(256, 2) void flash_mma_kernel(
    const float* __restrict__ qt, const float* __restrict__ kt,
    const __nv_bfloat16* __restrict__ vb, const __nv_bfloat16* __restrict__ pwb,
    const float* __restrict__ pb, const float* __restrict__ x,
    float* __restrict__ out)
{
    extern __shared__ char sm[];
    const uint32_t sb = smem_u32(sm);
    const int tid = threadIdx.x;
    const int w = tid >> 5;
    const int lane = tid & 31;
    const int g = lane >> 2, t = lane & 3;
    const int b = blockIdx.x >> 5;
    const int q0 = (blockIdx.x & 31) * 128;
    const int wodd = w & 1;

    const int rowsel = (lane & 7) + ((lane >> 4) << 3);
    const int ksel = (lane >> 3) & 1;
    const uint32_t vlane = (uint32_t)(rowsel * 272 + ksel * 16);
    const uint32_t chanoff = (uint32_t)(wodd * 17408);   // 64*272

    // ---- prologue: K(0)+V(0)
    {
        uint32_t kdst = sb + OFF_K;
        #pragma unroll
        for (int u = tid; u < 512; u += 256) {
            int row = u >> 2, cc = u & 3;
            cpa16(kdst + row * 80 + cc * 16, kt + ((size_t)(b * NN + row)) * D + cc * 4);
        }
        uint32_t vdst = sb + OFF_V0;
        #pragma unroll
        for (int u = tid; u < 2048; u += 256) {
            int c = u >> 4, cc = u & 15;
            cpa16(vdst + c * 272 + cc * 16, vb + ((size_t)(b * C + c)) * NN + cc * 8);
        }
        CP_COMMIT();
    }

    // ---- Q fragments direct from gmem (tf32 bits, once)
    uint32_t qa[2][4];
    {
        const uint32_t* qg0 = (const uint32_t*)qt + ((size_t)(b * NN + q0 + 16 * w + g)) * D;
        const uint32_t* qg1 = qg0 + 8 * D;
        #pragma unroll
        for (int kc = 0; kc < 2; kc++) {
            qa[kc][0] = __ldg(qg0 + 8 * kc + t);
            qa[kc][1] = __ldg(qg1 + 8 * kc + t);
            qa[kc][2] = __ldg(qg0 + 8 * kc + t + 4);
            qa[kc][3] = __ldg(qg1 + 8 * kc + t + 4);
        }
    }

    float o[2][8][4];
    #pragma unroll
    for (int rb = 0; rb < 2; rb++)
        #pragma unroll
        for (int cb = 0; cb < 8; cb++)
            #pragma unroll
            for (int i = 0; i < 4; i++) o[rb][cb][i] = 0.f;
    float rs0 = 0.f, rs1 = 0.f;

    for (int tt = 0; tt < 32; tt++) {
        const int buf = tt & 1;
        __syncthreads();   // prior PV done: safe to overwrite V(buf^1) / V0

        if (tt < 31) {   // V(t+1)
            uint32_t vdst = sb + (buf ? OFF_V0 : OFF_V1);
            const __nv_bfloat16* vsrc = vb + (size_t)b * C * NN + (tt + 1) * 128;
            #pragma unroll
            for (int u = tid; u < 2048; u += 256) {
                int c = u >> 4, cc = u & 15;
                cpa16(vdst + c * 272 + cc * 16, vsrc + (size_t)c * NN + cc * 8);
            }
        } else {          // pw -> V0
            #pragma unroll
            for (int u = tid; u < 2048; u += 256) {
                int row = u >> 4, cc = u & 15;
                cpa16(sb + OFF_PW + row * 272 + cc * 16, pwb + row * C + cc * 8);
            }
        }
        CP_COMMIT();
        CP_WAIT1();       // K(t), V(t) arrived
        __syncthreads();

        // ---- S = Q K^T (tf32) fused exp2 -> A-frag packs (rows 16w..16w+15)
        const char* sKb = sm + OFF_K;
        uint32_t pa[16], pbv[16];
        #pragma unroll
        for (int nb = 0; nb < 16; nb++) {
            float scv[4] = {0.f, 0.f, 0.f, 0.f};
            #pragma unroll
            for (int kc = 0; kc < 2; kc++) {
                uint2 kk = *(const uint2*)(sKb + (8 * nb + g) * 80 + 32 * kc + 8 * t);
                mma_tf32(scv, qa[kc], kk.x, kk.y);
            }
            float e0 = ex2f(scv[0]);
            float e1 = ex2f(scv[1]);
            float e2 = ex2f(scv[2]);
            float e3 = ex2f(scv[3]);
            rs0 += e0 + e1;
            rs1 += e2 + e3;
            pa[nb]  = bf2(e1, e0);
            pbv[nb] = bf2(e3, e2);
        }

        // ---- publish own P-frags for partner warp
        #pragma unroll
        for (int s = 0; s < 8; s++) {
            *(uint4*)(sm + OFF_PX + ((w * 8 + s) << 9) + lane * 16) =
                make_uint4(pa[2*s], pbv[2*s], pa[2*s+1], pbv[2*s+1]);
        }
        __syncthreads();   // P visible; all warps done reading K

        if (tt < 31) {     // refill K with K(t+1), hidden under PV
            uint32_t kdst = sb + OFF_K;
            const float* ksrc = kt + ((size_t)(b * NN + (tt + 1) * 128)) * D;
            #pragma unroll
            for (int u = tid; u < 512; u += 256) {
                int row = u >> 2, cc = u & 3;
                cpa16(kdst + row * 80 + cc * 16, ksrc + (size_t)row * D + cc * 4);
            }
            CP_COMMIT();
        }

        // ---- O += P V^T : 32 rows x 64 chans per warp
        const uint32_t vbase = sb + (buf ? OFF_V1 : OFF_V0) + chanoff + vlane;
        #pragma unroll
        for (int s = 0; s < 8; s++) {
            uint4 pq = *(const uint4*)(sm + OFF_PX + (((w ^ 1) * 8 + s) << 9) + lane * 16);
            uint4 ownq = make_uint4(pa[2*s], pbv[2*s], pa[2*s+1], pbv[2*s+1]);
            uint4 A0 = wodd ? pq : ownq;
            uint4 A1 = wodd ? ownq : pq;
            #pragma unroll
            for (int nbp = 0; nbp < 4; nbp++) {
                uint32_t r0, r1, r2, r3;
                ldm4(r0, r1, r2, r3, vbase + (uint32_t)(nbp * 4352 + s * 32));
                mma_bf16(o[0][2*nbp],     A0.x, A0.y, A0.z, A0.w, r0, r1);
                mma_bf16(o[0][2*nbp + 1], A0.x, A0.y, A0.z, A0.w, r2, r3);
                mma_bf16(o[1][2*nbp],     A1.x, A1.y, A1.z, A1.w, r0, r1);
                mma_bf16(o[1][2*nbp + 1], A1.x, A1.y, A1.z, A1.w, r2, r3);
            }
        }
    }

    CP_WAIT0();            // pw arrived
    __syncthreads();       // all PV(31) partner reads done

    // ---- row sums -> smem
    rs0 += __shfl_xor_sync(0xffffffffu, rs0, 1);
    rs0 += __shfl_xor_sync(0xffffffffu, rs0, 2);
    rs1 += __shfl_xor_sync(0xffffffffu, rs1, 1);
    rs1 += __shfl_xor_sync(0xffffffffu, rs1, 2);
    float* l_s = (float*)(sm + OFF_LS);
    if (t == 0) {
        l_s[16 * w + g]     = rs0;
        l_s[16 * w + g + 8] = rs1;
    }
    __syncthreads();

    // ---- normalize + publish O A-frags (bf16) to PX
    const int rowbase = 32 * (w >> 1);
    #pragma unroll
    for (int rb = 0; rb < 2; rb++) {
        float il0 = __fdividef(1.f, l_s[rowbase + 16 * rb + g]);
        float il1 = __fdividef(1.f, l_s[rowbase + 16 * rb + g + 8]);
        int r = (w & ~1) | rb;
        #pragma unroll
        for (int kbl = 0; kbl < 4; kbl++) {
            uint32_t a0 = bf2(o[rb][2*kbl][1] * il0, o[rb][2*kbl][0] * il0);
            uint32_t a1 = bf2(o[rb][2*kbl][3] * il1, o[rb][2*kbl][2] * il1);
            uint32_t a2 = bf2(o[rb][2*kbl+1][1] * il0, o[rb][2*kbl+1][0] * il0);
            uint32_t a3 = bf2(o[rb][2*kbl+1][3] * il1, o[rb][2*kbl+1][2] * il1);
            int kb = 4 * wodd + kbl;
            *(uint4*)(sm + OFF_PX + ((r * 8 + kb) << 9) + lane * 16) =
                make_uint4(a0, a1, a2, a3);
        }
    }
    __syncthreads();

    // ---- fused projection: rows 16w..16w+15, all 128 e (A from PX, B = pw)
    float pr[16][4];
    #pragma unroll
    for (int nb = 0; nb < 16; nb++)
        #pragma unroll
        for (int i = 0; i < 4; i++) pr[nb][i] = 0.f;
    const uint32_t pwl = sb + OFF_PW + vlane;
    #pragma unroll
    for (int kb = 0; kb < 8; kb++) {
        uint4 aq = *(const uint4*)(sm + OFF_PX + ((w * 8 + kb) << 9) + lane * 16);
        #pragma unroll
        for (int nbp = 0; nbp < 8; nbp++) {
            uint32_t r0, r1, r2, r3;
            ldm4(r0, r1, r2, r3, pwl + (uint32_t)(nbp * 4352 + kb * 32));
            mma_bf16(pr[2*nbp],     aq.x, aq.y, aq.z, aq.w, r0, r1);
            mma_bf16(pr[2*nbp + 1], aq.x, aq.y, aq.z, aq.w, r2, r3);
        }
    }
    __syncthreads();   // PX reads done before stg overlay

    // ---- stage [e][q], then bias + residual + STG
    float* stg = (float*)(sm + OFF_STG);
    #pragma unroll
    for (int nb = 0; nb < 16; nb++) {
        int e = 8*nb + 2*t;
        stg[(e    ) * 132 + 16*w + g    ] = pr[nb][0];
        stg[(e + 1) * 132 + 16*w + g    ] = pr[nb][1];
        stg[(e    ) * 132 + 16*w + g + 8] = pr[nb][2];
        stg[(e + 1) * 132 + 16*w + g + 8] = pr[nb][3];
    }
    __syncthreads();

    #pragma unroll
    for (int it = 0; it < 16; it++) {
        int idx = tid + it * 256;
        int e = idx >> 5, qq = idx & 31;
        float4 v4 = *(float4*)&stg[e * 132 + qq * 4];
        float bias = __ldg(pb + e);
        size_t gi = ((size_t)b * C + e) * NN + q0 + qq * 4;
        float4 xr = *(const float4*)&x[gi];
        v4.x += bias + xr.x; v4.y += bias + xr.y;
        v4.z += bias + xr.z; v4.w += bias + xr.w;
        *(float4*)&out[gi] = v4;
    }
}

// ---------------- launch -----------------------------------------------------
extern "C" void kernel_launch(void* const* d_in, const int* in_sizes, int n_in,
                              void* d_out, int out_size)
{
    const float* x    = (const float*)d_in[0];
    const float* gn_w = (const float*)d_in[1];
    const float* gn_b = (const float*)d_in[2];
    const float* q_w  = (const float*)d_in[3];
    const float* q_b  = (const float*)d_in[4];
    const float* k_w  = (const float*)d_in[5];
    const float* k_b  = (const float*)d_in[6];
    const float* v_w  = (const float*)d_in[7];
    const float* v_b  = (const float*)d_in[8];
    const float* p_w  = (const float*)d_in[9];
    const float* p_b  = (const float*)d_in[10];
    float* out = (float*)d_out;

    float *qt, *kt, *st;
    __nv_bfloat16 *v, *pwb;
    cudaGetSymbolAddress((void**)&qt,  g_qt);
    cudaGetSymbolAddress((void**)&kt,  g_kt);
    cudaGetSymbolAddress((void**)&v,   g_v);
    cudaGetSymbolAddress((void**)&pwb, g_pwb);
    cudaGetSymbolAddress((void**)&st,  g_st);

    cudaFuncSetAttribute(flash_mma_kernel,
                         cudaFuncAttributeMaxDynamicSharedMemorySize, SMEM_FL);
    cudaFuncSetAttribute(qkv_proj_kernel,
                         cudaFuncAttributeMaxDynamicSharedMemorySize, SMEM_PJ);

    gn_stats_kernel<<<BATCH * G, 256>>>(x, st);
    pwcvt_kernel<<<16, 1024>>>(p_w, pwb);

    qkv_proj_kernel<<<dim3(NN / 128, BATCH), 256, SMEM_PJ>>>(
        q_w, q_b, k_w, k_b, v_w, v_b, gn_w, gn_b, st, x, qt, kt, v);

    flash_mma_kernel<<<BATCH * 32, 256, SMEM_FL>>>(qt, kt, v, pwb, p_b, x, out);
}

// round 9
// speedup vs baseline: 1.1111x; 1.1111x over previous
#include <cuda_runtime.h>
#include <cuda_bf16.h>
#include <cstdint>
#include <math.h>

#define BATCH 8
#define C 128
#define NN 4096
#define D 16
#define G 32
#define CPG (C / G)
#define EPS 1e-5f
#define SCALE_Q 0.36067376022224085f   // 0.25 * log2(e)

// ---------------- scratch ----------------------------------------------------
__device__ float          g_qt [BATCH * NN * D];   // q [B,N,16] tf32 bits, scaled
__device__ float          g_kt [BATCH * NN * D];   // k [B,N,16] tf32 bits
__device__ __nv_bfloat16  g_v  [BATCH * C * NN];   // v [B,C,N] bf16
__device__ __nv_bfloat16  g_pwb[C * C];            // p_w bf16 [e][c]
__device__ float          g_st [BATCH * G * 2];    // groupnorm (mean, rstd)

// ---------------- GroupNorm stats only ---------------------------------------
__global__ __launch_bounds__(256) void gn_stats_kernel(
    const float* __restrict__ x, float* __restrict__ st)
{
    const int b = blockIdx.x >> 5;
    const int g = blockIdx.x & 31;
    const float* xp = x + ((size_t)b * C + g * CPG) * NN;

    const int TOT = CPG * NN;
    float s = 0.f, s2 = 0.f;
    for (int idx = threadIdx.x; idx < TOT; idx += 256) {
        float v = xp[idx];
        s += v; s2 += v * v;
    }
    __shared__ float red[16];
    int lane = threadIdx.x & 31, wid = threadIdx.x >> 5;
    #pragma unroll
    for (int o = 16; o > 0; o >>= 1) {
        s  += __shfl_xor_sync(0xffffffffu, s,  o);
        s2 += __shfl_xor_sync(0xffffffffu, s2, o);
    }
    if (lane == 0) { red[wid] = s; red[8 + wid] = s2; }
    __syncthreads();
    if (wid == 0) {
        float a = (lane < 8) ? red[lane] : 0.f;
        float a2 = (lane < 8) ? red[8 + lane] : 0.f;
        #pragma unroll
        for (int o = 4; o > 0; o >>= 1) {
            a  += __shfl_xor_sync(0xffffffffu, a,  o);
            a2 += __shfl_xor_sync(0xffffffffu, a2, o);
        }
        if (lane == 0) {
            const float inv_n = 1.f / (float)TOT;
            float mean = a * inv_n;
            float var = a2 * inv_n - mean * mean;
            st[blockIdx.x * 2]     = mean;
            st[blockIdx.x * 2 + 1] = rsqrtf(var + EPS);
        }
    }
}

// ---------------- p_w -> bf16 ------------------------------------------------
__global__ void pwcvt_kernel(const float* __restrict__ pw,
                             __nv_bfloat16* __restrict__ pwb)
{
    int i = blockIdx.x * 1024 + threadIdx.x;
    pwb[i] = __float2bfloat16_rn(pw[i]);
}

// ---------------- mma helpers ------------------------------------------------
__device__ __forceinline__ uint32_t smem_u32(const void* p) {
    uint32_t a;
    asm("{ .reg .u64 t; cvta.to.shared.u64 t, %1; cvt.u32.u64 %0, t; }" : "=r"(a) : "l"(p));
    return a;
}
__device__ __forceinline__ void cpa16(uint32_t s, const void* g) {
    asm volatile("cp.async.cg.shared.global [%0], [%1], 16;" :: "r"(s), "l"(g));
}
#define CP_COMMIT() asm volatile("cp.async.commit_group;" ::: "memory")
#define CP_WAIT1()  asm volatile("cp.async.wait_group 1;" ::: "memory")
#define CP_WAIT0()  asm volatile("cp.async.wait_group 0;" ::: "memory")

__device__ __forceinline__ uint32_t f2tf(float f) {
    uint32_t u; asm("cvt.rna.tf32.f32 %0, %1;" : "=r"(u) : "f"(f)); return u;
}
__device__ __forceinline__ float ex2f(float f) {
    float r; asm("ex2.approx.f32 %0, %1;" : "=f"(r) : "f"(f)); return r;
}
__device__ __forceinline__ uint32_t bf2(float hi, float lo) {
    uint32_t r; asm("cvt.rn.bf16x2.f32 %0, %1, %2;" : "=r"(r) : "f"(hi), "f"(lo)); return r;
}
__device__ __forceinline__ void mma_tf32(float* c, const uint32_t* a,
                                         uint32_t b0, uint32_t b1) {
    asm volatile(
        "mma.sync.aligned.m16n8k8.row.col.f32.tf32.tf32.f32 "
        "{%0,%1,%2,%3},{%4,%5,%6,%7},{%8,%9},{%0,%1,%2,%3};"
        : "+f"(c[0]), "+f"(c[1]), "+f"(c[2]), "+f"(c[3])
        : "r"(a[0]), "r"(a[1]), "r"(a[2]), "r"(a[3]), "r"(b0), "r"(b1));
}
__device__ __forceinline__ void mma_bf16(float* c, uint32_t a0, uint32_t a1,
                                         uint32_t a2, uint32_t a3,
                                         uint32_t b0, uint32_t b1) {
    asm volatile(
        "mma.sync.aligned.m16n8k16.row.col.f32.bf16.bf16.f32 "
        "{%0,%1,%2,%3},{%4,%5,%6,%7},{%8,%9},{%0,%1,%2,%3};"
        : "+f"(c[0]), "+f"(c[1]), "+f"(c[2]), "+f"(c[3])
        : "r"(a0), "r"(a1), "r"(a2), "r"(a3), "r"(b0), "r"(b1));
}
__device__ __forceinline__ void ldm4(uint32_t& r0, uint32_t& r1, uint32_t& r2,
                                     uint32_t& r3, uint32_t addr) {
    asm volatile("ldmatrix.sync.aligned.m8n8.x4.shared.b16 {%0,%1,%2,%3}, [%4];"
                 : "=r"(r0), "=r"(r1), "=r"(r2), "=r"(r3) : "r"(addr));
}

// ============================================================================
//   fused GN + QKV projection (tf32 mma): q/k written as tf32 bits, v bf16
// ============================================================================
#define PJ_HT   0
#define PJ_WS   67584
#define PJ_BIAS 152064
#define PJ_SC   152704
#define SMEM_PJ 153728

__global__ __launch_bounds__(256) void qkv_proj_kernel(
    const float* __restrict__ qw, const float* __restrict__ qb,
    const float* __restrict__ kw, const float* __restrict__ kb,
    const float* __restrict__ vw, const float* __restrict__ vb,
    const float* __restrict__ gnw, const float* __restrict__ gnb,
    const float* __restrict__ st, const float* __restrict__ x,
    float* __restrict__ qt, float* __restrict__ kt,
    __nv_bfloat16* __restrict__ vout)
{
    extern __shared__ char sm[];
    uint32_t* hT = (uint32_t*)(sm + PJ_HT);
    uint32_t* Ws = (uint32_t*)(sm + PJ_WS);
    float* bs = (float*)(sm + PJ_BIAS);
    float* sc = (float*)(sm + PJ_SC);
    float* sh = sc + 128;
    const int tid = threadIdx.x;
    const int w = tid >> 5, lane = tid & 31;
    const int g = lane >> 2, t = lane & 3;
    const int n0 = blockIdx.x * 128;
    const int b = blockIdx.y;

    if (tid < 128) {
        float mean = st[(b * G + (tid >> 2)) * 2];
        float inv  = st[(b * G + (tid >> 2)) * 2 + 1];
        float s = gnw[tid] * inv;
        sc[tid] = s;
        sh[tid] = gnb[tid] - mean * s;
    }
    for (int u = tid; u < 160 * 128; u += 256) {
        int e = u >> 7, c = u & 127;
        float wv;
        if (e < 16)      wv = qw[e * C + c];
        else if (e < 32) wv = kw[(e - 16) * C + c];
        else             wv = vw[(e - 32) * C + c];
        Ws[e * 132 + c] = f2tf(wv);
    }
    if (tid < 160) {
        float bv;
        if (tid < 16)      bv = qb[tid];
        else if (tid < 32) bv = kb[tid - 16];
        else               bv = vb[tid - 32];
        bs[tid] = bv;
    }
    __syncthreads();

    for (int u = tid; u < 128 * 128; u += 256) {
        int n = u & 127, c = u >> 7;
        float hv = fmaf(x[((size_t)b * C + c) * NN + n0 + n], sc[c], sh[c]);
        hT[n * 132 + c] = f2tf(hv);
    }
    __syncthreads();

    uint32_t af[16][4];
    #pragma unroll
    for (int kc = 0; kc < 16; kc++) {
        af[kc][0] = hT[(16 * w + g    ) * 132 + 8 * kc + t    ];
        af[kc][1] = hT[(16 * w + g + 8) * 132 + 8 * kc + t    ];
        af[kc][2] = hT[(16 * w + g    ) * 132 + 8 * kc + t + 4];
        af[kc][3] = hT[(16 * w + g + 8) * 132 + 8 * kc + t + 4];
    }

    float pr[20][4];
    #pragma unroll
    for (int nb = 0; nb < 20; nb++)
        #pragma unroll
        for (int i = 0; i < 4; i++) pr[nb][i] = 0.f;

    #pragma unroll
    for (int kc = 0; kc < 16; kc++) {
        #pragma unroll
        for (int nb = 0; nb < 20; nb++) {
            uint32_t b0 = Ws[(8 * nb + g) * 132 + 8 * kc + t    ];
            uint32_t b1 = Ws[(8 * nb + g) * 132 + 8 * kc + t + 4];
            mma_tf32(pr[nb], af[kc], b0, b1);
        }
    }

    const int r0 = 16 * w + g, r1 = r0 + 8;
    #pragma unroll
    for (int nb = 0; nb < 4; nb++) {
        int e = 8 * nb + 2 * t;
        float b0 = bs[e], b1 = bs[e + 1];
        if (e < 16) {
            float2 lo = make_float2(
                __uint_as_float(f2tf((pr[nb][0] + b0) * SCALE_Q)),
                __uint_as_float(f2tf((pr[nb][1] + b1) * SCALE_Q)));
            float2 hi = make_float2(
                __uint_as_float(f2tf((pr[nb][2] + b0) * SCALE_Q)),
                __uint_as_float(f2tf((pr[nb][3] + b1) * SCALE_Q)));
            *(float2*)&qt[((size_t)b * NN + n0 + r0) * D + e] = lo;
            *(float2*)&qt[((size_t)b * NN + n0 + r1) * D + e] = hi;
        } else {
            float2 lo = make_float2(
                __uint_as_float(f2tf(pr[nb][0] + b0)),
                __uint_as_float(f2tf(pr[nb][1] + b1)));
            float2 hi = make_float2(
                __uint_as_float(f2tf(pr[nb][2] + b0)),
                __uint_as_float(f2tf(pr[nb][3] + b1)));
            *(float2*)&kt[((size_t)b * NN + n0 + r0) * D + e - 16] = lo;
            *(float2*)&kt[((size_t)b * NN + n0 + r1) * D + e - 16] = hi;
        }
    }
    __syncthreads();

    __nv_bfloat16* vstage = (__nv_bfloat16*)(sm + PJ_WS);
    #pragma unroll
    for (int nb = 4; nb < 20; nb++) {
        int e = 8 * nb + 2 * t;
        int cv = e - 32;
        float b0 = bs[e], b1 = bs[e + 1];
        vstage[(cv    ) * 132 + r0] = __float2bfloat16_rn(pr[nb][0] + b0);
        vstage[(cv + 1) * 132 + r0] = __float2bfloat16_rn(pr[nb][1] + b1);
        vstage[(cv    ) * 132 + r1] = __float2bfloat16_rn(pr[nb][2] + b0);
        vstage[(cv + 1) * 132 + r1] = __float2bfloat16_rn(pr[nb][3] + b1);
    }
    __syncthreads();
    for (int u = tid; u < 128 * 32; u += 256) {
        int c = u >> 5, nc = u & 31;
        *(uint64_t*)&vout[((size_t)b * C + c) * NN + n0 + nc * 4] =
            *(const uint64_t*)&vstage[c * 132 + nc * 4];
    }
}

// ============================================================================
//   flash attention (fused S/exp/PV per s-block; p_w loaded AFTER mainloop)
// ============================================================================
#define OFF_Q   0
#define OFF_K0  10240
#define OFF_K1  20480
#define OFF_V0  30720
#define OFF_V1  65536
#define OFF_PW  0
#define OFF_STG 34816
#define SMEM_FL 102400

__device__ __forceinline__ void issue_tile(uint32_t sb, int buf,
    const float* __restrict__ kt, const __nv_bfloat16* __restrict__ vb,
    int b, int j0, int tid)
{
    uint32_t kdst = sb + (buf ? OFF_K1 : OFF_K0);
    #pragma unroll
    for (int u = tid; u < 512; u += 256) {
        int row = u >> 2, cc = u & 3;
        cpa16(kdst + row * 80 + cc * 16,
              kt + ((size_t)(b * NN + j0 + row)) * D + cc * 4);
    }
    uint32_t vdst = sb + (buf ? OFF_V1 : OFF_V0);
    #pragma unroll
    for (int u = tid; u < 2048; u += 256) {
        int c = u >> 4, cc = u & 15;
        cpa16(vdst + c * 272 + cc * 16,
              vb + ((size_t)(b * C + c)) * NN + j0 + cc * 8);
    }
}

__global__ __launch_bounds__(256, 2) void flash_mma_kernel(
    const float* __restrict__ qt, const float* __restrict__ kt,
    const __nv_bfloat16* __restrict__ vb, const __nv_bfloat16* __restrict__ pwb,
    const float* __restrict__ pb, const float* __restrict__ x,
    float* __restrict__ out)
{
    extern __shared__ char sm[];
    const uint32_t sb = smem_u32(sm);
    const int tid = threadIdx.x;
    const int w = tid >> 5;
    const int lane = tid & 31;
    const int g = lane >> 2, t = lane & 3;
    const int b = blockIdx.x >> 5;
    const int q0 = (blockIdx.x & 31) * 128;

    const int rowsel = (lane & 7) + ((lane >> 4) << 3);
    const int ksel = (lane >> 3) & 1;
    const uint32_t vlane = (uint32_t)(rowsel * 272 + ksel * 16);

    #pragma unroll
    for (int u = tid; u < 512; u += 256) {
        int row = u >> 2, cc = u & 3;
        cpa16(sb + OFF_Q + row * 80 + cc * 16,
              qt + ((size_t)(b * NN + q0 + row)) * D + cc * 4);
    }
    issue_tile(sb, 0, kt, vb, b, 0, tid);
    CP_COMMIT();

    const uint32_t* sQ = (const uint32_t*)(sm + OFF_Q);
    uint32_t qa[2][4];
    float o[16][4];
    #pragma unroll
    for (int nb = 0; nb < 16; nb++)
        #pragma unroll
        for (int i = 0; i < 4; i++) o[nb][i] = 0.f;
    float rs0 = 0.f, rs1 = 0.f;

    for (int tt = 0; tt < 32; tt++) {
        const int buf = tt & 1;
        if (tt < 31) {
            issue_tile(sb, buf ^ 1, kt, vb, b, (tt + 1) * 128, tid);
            CP_COMMIT();
            CP_WAIT1();
        } else {
            CP_WAIT0();
        }
        __syncthreads();

        if (tt == 0) {
            #pragma unroll
            for (int kc = 0; kc < 2; kc++) {
                qa[kc][0] = sQ[(16*w + g    ) * 20 + 8*kc + t    ];
                qa[kc][1] = sQ[(16*w + g + 8) * 20 + 8*kc + t    ];
                qa[kc][2] = sQ[(16*w + g    ) * 20 + 8*kc + t + 4];
                qa[kc][3] = sQ[(16*w + g + 8) * 20 + 8*kc + t + 4];
            }
        }

        const uint32_t* sK = (const uint32_t*)(sm + (buf ? OFF_K1 : OFF_K0));
        const uint32_t vbase = sb + (buf ? OFF_V1 : OFF_V0) + vlane;

        // ---- fused per-s-block pipeline: S (tf32) -> exp2 -> PV (bf16)
        #pragma unroll
        for (int s = 0; s < 8; s++) {
            float sc0[4] = {0.f, 0.f, 0.f, 0.f};
            float sc1[4] = {0.f, 0.f, 0.f, 0.f};
            #pragma unroll
            for (int kc = 0; kc < 2; kc++) {
                uint32_t b0 = sK[(16*s + g) * 20 + 8*kc + t    ];
                uint32_t b1 = sK[(16*s + g) * 20 + 8*kc + t + 4];
                mma_tf32(sc0, qa[kc], b0, b1);
                uint32_t c0 = sK[(16*s + 8 + g) * 20 + 8*kc + t    ];
                uint32_t c1 = sK[(16*s + 8 + g) * 20 + 8*kc + t + 4];
                mma_tf32(sc1, qa[kc], c0, c1);
            }
            float e0 = ex2f(sc0[0]);
            float e1 = ex2f(sc0[1]);
            float e2 = ex2f(sc0[2]);
            float e3 = ex2f(sc0[3]);
            float f0 = ex2f(sc1[0]);
            float f1 = ex2f(sc1[1]);
            float f2 = ex2f(sc1[2]);
            float f3 = ex2f(sc1[3]);
            rs0 += e0 + e1 + f0 + f1;
            rs1 += e2 + e3 + f2 + f3;
            uint32_t a0 = bf2(e1, e0);   // rows g,    k 0-7  (j 16s..16s+7)
            uint32_t a1 = bf2(e3, e2);   // rows g+8,  k 0-7
            uint32_t a2 = bf2(f1, f0);   // rows g,    k 8-15 (j 16s+8..15)
            uint32_t a3 = bf2(f3, f2);   // rows g+8,  k 8-15
            #pragma unroll
            for (int nbp = 0; nbp < 8; nbp++) {
                uint32_t r0, r1, r2, r3;
                ldm4(r0, r1, r2, r3, vbase + (uint32_t)(nbp * 4352 + s * 32));
                mma_bf16(o[2*nbp],     a0, a1, a2, a3, r0, r1);
                mma_bf16(o[2*nbp + 1], a0, a1, a2, a3, r2, r3);
            }
        }
        __syncthreads();
    }

    // ---- p_w (bf16) over dead Q/K region — AFTER all K reads are done
    #pragma unroll
    for (int u = tid; u < 2048; u += 256) {
        int row = u >> 4, cc = u & 15;
        cpa16(sb + OFF_PW + row * 272 + cc * 16, pwb + row * C + cc * 8);
    }
    CP_COMMIT();

    rs0 += __shfl_xor_sync(0xffffffffu, rs0, 1);
    rs0 += __shfl_xor_sync(0xffffffffu, rs0, 2);
    rs1 += __shfl_xor_sync(0xffffffffu, rs1, 1);
    rs1 += __shfl_xor_sync(0xffffffffu, rs1, 2);
    const float il0 = 1.f / rs0, il1 = 1.f / rs1;

    uint32_t oa0[16], oa1[16];
    #pragma unroll
    for (int nb = 0; nb < 16; nb++) {
        oa0[nb] = bf2(o[nb][1] * il0, o[nb][0] * il0);
        oa1[nb] = bf2(o[nb][3] * il1, o[nb][2] * il1);
    }

    CP_WAIT0();
    __syncthreads();

    float pr[16][4];
    #pragma unroll
    for (int nb = 0; nb < 16; nb++)
        #pragma unroll
        for (int i = 0; i < 4; i++) pr[nb][i] = 0.f;
    const uint32_t pwbase = sb + OFF_PW;
    #pragma unroll
    for (int s = 0; s < 8; s++) {
        const uint32_t a0 = oa0[2*s], a1 = oa1[2*s];
        const uint32_t a2 = oa0[2*s+1], a3 = oa1[2*s+1];
        #pragma unroll
        for (int nbp = 0; nbp < 8; nbp++) {
            uint32_t r0, r1, r2, r3;
            ldm4(r0, r1, r2, r3, pwbase + (uint32_t)(nbp * 4352 + s * 32) + vlane);
            mma_bf16(pr[2*nbp],     a0, a1, a2, a3, r0, r1);
            mma_bf16(pr[2*nbp + 1], a0, a1, a2, a3, r2, r3);
        }
    }
    __syncthreads();   // p_w reads done before stg overlay (STG overlaps V1 only,
                       // but keep ordering for the PW region reads vs nothing)

    float* stg = (float*)(sm + OFF_STG);
    #pragma unroll
    for (int nb = 0; nb < 16; nb++) {
        int e = 8*nb + 2*t;
        stg[(e    ) * 132 + 16*w + g    ] = pr[nb][0];
        stg[(e + 1) * 132 + 16*w + g    ] = pr[nb][1];
        stg[(e    ) * 132 + 16*w + g + 8] = pr[nb][2];
        stg[(e + 1) * 132 + 16*w + g + 8] = pr[nb][3];
    }
    __syncthreads();

    #pragma unroll
    for (int it = 0; it < 16; it++) {
        int idx = tid + it * 256;
        int e = idx >> 5, qq = idx & 31;
        float4 v4 = *(float4*)&stg[e * 132 + qq * 4];
        float bias = __ldg(pb + e);
        size_t gi = ((size_t)b * C + e) * NN + q0 + qq * 4;
        float4 xr = *(const float4*)&x[gi];
        v4.x += bias + xr.x; v4.y += bias + xr.y;
        v4.z += bias + xr.z; v4.w += bias + xr.w;
        *(float4*)&out[gi] = v4;
    }
}

// ---------------- launch -----------------------------------------------------
extern "C" void kernel_launch(void* const* d_in, const int* in_sizes, int n_in,
                              void* d_out, int out_size)
{
    const float* x    = (const float*)d_in[0];
    const float* gn_w = (const float*)d_in[1];
    const float* gn_b = (const float*)d_in[2];
    const float* q_w  = (const float*)d_in[3];
    const float* q_b  = (const float*)d_in[4];
    const float* k_w  = (const float*)d_in[5];
    const float* k_b  = (const float*)d_in[6];
    const float* v_w  = (const float*)d_in[7];
    const float* v_b  = (const float*)d_in[8];
    const float* p_w  = (const float*)d_in[9];
    const float* p_b  = (const float*)d_in[10];
    float* out = (float*)d_out;

    float *qt, *kt, *st;
    __nv_bfloat16 *v, *pwb;
    cudaGetSymbolAddress((void**)&qt,  g_qt);
    cudaGetSymbolAddress((void**)&kt,  g_kt);
    cudaGetSymbolAddress((void**)&v,   g_v);
    cudaGetSymbolAddress((void**)&pwb, g_pwb);
    cudaGetSymbolAddress((void**)&st,  g_st);

    cudaFuncSetAttribute(flash_mma_kernel,
                         cudaFuncAttributeMaxDynamicSharedMemorySize, SMEM_FL);
    cudaFuncSetAttribute(qkv_proj_kernel,
                         cudaFuncAttributeMaxDynamicSharedMemorySize, SMEM_PJ);

    gn_stats_kernel<<<BATCH * G, 256>>>(x, st);
    pwcvt_kernel<<<16, 1024>>>(p_w, pwb);

    qkv_proj_kernel<<<dim3(NN / 128, BATCH), 256, SMEM_PJ>>>(
        q_w, q_b, k_w, k_b, v_w, v_b, gn_w, gn_b, st, x, qt, kt, v);

    flash_mma_kernel<<<BATCH * 32, 256, SMEM_FL>>>(qt, kt, v, pwb, p_b, x, out);
}

// round 10
// speedup vs baseline: 1.1754x; 1.0579x over previous
#include <cuda_runtime.h>
#include <cuda_bf16.h>
#include <cstdint>
#include <math.h>

#define BATCH 8
#define C 128
#define NN 4096
#define D 16
#define G 32
#define CPG (C / G)
#define EPS 1e-5f
#define SCALE_Q 0.36067376022224085f   // 0.25 * log2(e)

// ---------------- scratch ----------------------------------------------------
__device__ __nv_bfloat16  g_qt [BATCH * NN * D];   // q [B,N,16] bf16, pre-scaled
__device__ __nv_bfloat16  g_kt [BATCH * NN * D];   // k [B,N,16] bf16
__device__ __nv_bfloat16  g_v  [BATCH * C * NN];   // v [B,C,N] bf16
__device__ __nv_bfloat16  g_pwb[C * C];            // p_w bf16 [e][c]
__device__ float          g_st [BATCH * G * 2];    // groupnorm (mean, rstd)

// ---------------- GroupNorm stats (+ p_w bf16 convert piggyback) -------------
__global__ __launch_bounds__(256) void gn_stats_kernel(
    const float* __restrict__ x, float* __restrict__ st,
    const float* __restrict__ pw, __nv_bfloat16* __restrict__ pwb)
{
    const int b = blockIdx.x >> 5;
    const int g = blockIdx.x & 31;
    const float* xp = x + ((size_t)b * C + g * CPG) * NN;

    if (threadIdx.x < 64) {   // 256 blocks x 64 = 16384 = C*C
        int i = blockIdx.x * 64 + threadIdx.x;
        pwb[i] = __float2bfloat16_rn(pw[i]);
    }

    const int TOT = CPG * NN;
    float s = 0.f, s2 = 0.f;
    for (int idx = threadIdx.x; idx < TOT; idx += 256) {
        float v = xp[idx];
        s += v; s2 += v * v;
    }
    __shared__ float red[16];
    int lane = threadIdx.x & 31, wid = threadIdx.x >> 5;
    #pragma unroll
    for (int o = 16; o > 0; o >>= 1) {
        s  += __shfl_xor_sync(0xffffffffu, s,  o);
        s2 += __shfl_xor_sync(0xffffffffu, s2, o);
    }
    if (lane == 0) { red[wid] = s; red[8 + wid] = s2; }
    __syncthreads();
    if (wid == 0) {
        float a = (lane < 8) ? red[lane] : 0.f;
        float a2 = (lane < 8) ? red[8 + lane] : 0.f;
        #pragma unroll
        for (int o = 4; o > 0; o >>= 1) {
            a  += __shfl_xor_sync(0xffffffffu, a,  o);
            a2 += __shfl_xor_sync(0xffffffffu, a2, o);
        }
        if (lane == 0) {
            const float inv_n = 1.f / (float)TOT;
            float mean = a * inv_n;
            float var = a2 * inv_n - mean * mean;
            st[blockIdx.x * 2]     = mean;
            st[blockIdx.x * 2 + 1] = rsqrtf(var + EPS);
        }
    }
}

// ---------------- mma helpers ------------------------------------------------
__device__ __forceinline__ uint32_t smem_u32(const void* p) {
    uint32_t a;
    asm("{ .reg .u64 t; cvta.to.shared.u64 t, %1; cvt.u32.u64 %0, t; }" : "=r"(a) : "l"(p));
    return a;
}
__device__ __forceinline__ void cpa16(uint32_t s, const void* g) {
    asm volatile("cp.async.cg.shared.global [%0], [%1], 16;" :: "r"(s), "l"(g));
}
#define CP_COMMIT() asm volatile("cp.async.commit_group;" ::: "memory")
#define CP_WAIT1()  asm volatile("cp.async.wait_group 1;" ::: "memory")
#define CP_WAIT0()  asm volatile("cp.async.wait_group 0;" ::: "memory")

__device__ __forceinline__ uint32_t f2tf(float f) {
    uint32_t u; asm("cvt.rna.tf32.f32 %0, %1;" : "=r"(u) : "f"(f)); return u;
}
__device__ __forceinline__ float ex2f(float f) {
    float r; asm("ex2.approx.f32 %0, %1;" : "=f"(r) : "f"(f)); return r;
}
__device__ __forceinline__ uint32_t bf2(float hi, float lo) {
    uint32_t r; asm("cvt.rn.bf16x2.f32 %0, %1, %2;" : "=r"(r) : "f"(hi), "f"(lo)); return r;
}
__device__ __forceinline__ void mma_tf32(float* c, const uint32_t* a,
                                         uint32_t b0, uint32_t b1) {
    asm volatile(
        "mma.sync.aligned.m16n8k8.row.col.f32.tf32.tf32.f32 "
        "{%0,%1,%2,%3},{%4,%5,%6,%7},{%8,%9},{%0,%1,%2,%3};"
        : "+f"(c[0]), "+f"(c[1]), "+f"(c[2]), "+f"(c[3])
        : "r"(a[0]), "r"(a[1]), "r"(a[2]), "r"(a[3]), "r"(b0), "r"(b1));
}
__device__ __forceinline__ void mma_bf16(float* c, uint32_t a0, uint32_t a1,
                                         uint32_t a2, uint32_t a3,
                                         uint32_t b0, uint32_t b1) {
    asm volatile(
        "mma.sync.aligned.m16n8k16.row.col.f32.bf16.bf16.f32 "
        "{%0,%1,%2,%3},{%4,%5,%6,%7},{%8,%9},{%0,%1,%2,%3};"
        : "+f"(c[0]), "+f"(c[1]), "+f"(c[2]), "+f"(c[3])
        : "r"(a0), "r"(a1), "r"(a2), "r"(a3), "r"(b0), "r"(b1));
}
__device__ __forceinline__ void ldm4(uint32_t& r0, uint32_t& r1, uint32_t& r2,
                                     uint32_t& r3, uint32_t addr) {
    asm volatile("ldmatrix.sync.aligned.m8n8.x4.shared.b16 {%0,%1,%2,%3}, [%4];"
                 : "=r"(r0), "=r"(r1), "=r"(r2), "=r"(r3) : "r"(addr));
}

// ============================================================================
//   fused GN + QKV projection (tf32 mma): q/k written as bf16, v bf16
// ============================================================================
#define PJ_HT   0
#define PJ_WS   67584
#define PJ_BIAS 152064
#define PJ_SC   152704
#define SMEM_PJ 153728

__global__ __launch_bounds__(256) void qkv_proj_kernel(
    const float* __restrict__ qw, const float* __restrict__ qb,
    const float* __restrict__ kw, const float* __restrict__ kb,
    const float* __restrict__ vw, const float* __restrict__ vb,
    const float* __restrict__ gnw, const float* __restrict__ gnb,
    const float* __restrict__ st, const float* __restrict__ x,
    __nv_bfloat16* __restrict__ qt, __nv_bfloat16* __restrict__ kt,
    __nv_bfloat16* __restrict__ vout)
{
    extern __shared__ char sm[];
    uint32_t* hT = (uint32_t*)(sm + PJ_HT);
    uint32_t* Ws = (uint32_t*)(sm + PJ_WS);
    float* bs = (float*)(sm + PJ_BIAS);
    float* sc = (float*)(sm + PJ_SC);
    float* sh = sc + 128;
    const int tid = threadIdx.x;
    const int w = tid >> 5, lane = tid & 31;
    const int g = lane >> 2, t = lane & 3;
    const int n0 = blockIdx.x * 128;
    const int b = blockIdx.y;

    if (tid < 128) {
        float mean = st[(b * G + (tid >> 2)) * 2];
        float inv  = st[(b * G + (tid >> 2)) * 2 + 1];
        float s = gnw[tid] * inv;
        sc[tid] = s;
        sh[tid] = gnb[tid] - mean * s;
    }
    for (int u = tid; u < 160 * 128; u += 256) {
        int e = u >> 7, c = u & 127;
        float wv;
        if (e < 16)      wv = qw[e * C + c];
        else if (e < 32) wv = kw[(e - 16) * C + c];
        else             wv = vw[(e - 32) * C + c];
        Ws[e * 132 + c] = f2tf(wv);
    }
    if (tid < 160) {
        float bv;
        if (tid < 16)      bv = qb[tid];
        else if (tid < 32) bv = kb[tid - 16];
        else               bv = vb[tid - 32];
        bs[tid] = bv;
    }
    __syncthreads();

    for (int u = tid; u < 128 * 128; u += 256) {
        int n = u & 127, c = u >> 7;
        float hv = fmaf(x[((size_t)b * C + c) * NN + n0 + n], sc[c], sh[c]);
        hT[n * 132 + c] = f2tf(hv);
    }
    __syncthreads();

    uint32_t af[16][4];
    #pragma unroll
    for (int kc = 0; kc < 16; kc++) {
        af[kc][0] = hT[(16 * w + g    ) * 132 + 8 * kc + t    ];
        af[kc][1] = hT[(16 * w + g + 8) * 132 + 8 * kc + t    ];
        af[kc][2] = hT[(16 * w + g    ) * 132 + 8 * kc + t + 4];
        af[kc][3] = hT[(16 * w + g + 8) * 132 + 8 * kc + t + 4];
    }

    float pr[20][4];
    #pragma unroll
    for (int nb = 0; nb < 20; nb++)
        #pragma unroll
        for (int i = 0; i < 4; i++) pr[nb][i] = 0.f;

    #pragma unroll
    for (int kc = 0; kc < 16; kc++) {
        #pragma unroll
        for (int nb = 0; nb < 20; nb++) {
            uint32_t b0 = Ws[(8 * nb + g) * 132 + 8 * kc + t    ];
            uint32_t b1 = Ws[(8 * nb + g) * 132 + 8 * kc + t + 4];
            mma_tf32(pr[nb], af[kc], b0, b1);
        }
    }

    const int r0 = 16 * w + g, r1 = r0 + 8;
    #pragma unroll
    for (int nb = 0; nb < 4; nb++) {
        int e = 8 * nb + 2 * t;
        float b0 = bs[e], b1 = bs[e + 1];
        if (e < 16) {   // q: pre-scaled by 0.25*log2e, bf16x2 packed
            *(uint32_t*)&qt[((size_t)b * NN + n0 + r0) * D + e] =
                bf2((pr[nb][1] + b1) * SCALE_Q, (pr[nb][0] + b0) * SCALE_Q);
            *(uint32_t*)&qt[((size_t)b * NN + n0 + r1) * D + e] =
                bf2((pr[nb][3] + b1) * SCALE_Q, (pr[nb][2] + b0) * SCALE_Q);
        } else {        // k: bf16x2 packed
            int E = e - 16;
            *(uint32_t*)&kt[((size_t)b * NN + n0 + r0) * D + E] =
                bf2(pr[nb][1] + b1, pr[nb][0] + b0);
            *(uint32_t*)&kt[((size_t)b * NN + n0 + r1) * D + E] =
                bf2(pr[nb][3] + b1, pr[nb][2] + b0);
        }
    }
    __syncthreads();

    __nv_bfloat16* vstage = (__nv_bfloat16*)(sm + PJ_WS);
    #pragma unroll
    for (int nb = 4; nb < 20; nb++) {
        int e = 8 * nb + 2 * t;
        int cv = e - 32;
        float b0 = bs[e], b1 = bs[e + 1];
        vstage[(cv    ) * 132 + r0] = __float2bfloat16_rn(pr[nb][0] + b0);
        vstage[(cv + 1) * 132 + r0] = __float2bfloat16_rn(pr[nb][1] + b1);
        vstage[(cv    ) * 132 + r1] = __float2bfloat16_rn(pr[nb][2] + b0);
        vstage[(cv + 1) * 132 + r1] = __float2bfloat16_rn(pr[nb][3] + b1);
    }
    __syncthreads();
    for (int u = tid; u < 128 * 32; u += 256) {
        int c = u >> 5, nc = u & 31;
        *(uint64_t*)&vout[((size_t)b * C + c) * NN + n0 + nc * 4] =
            *(const uint64_t*)&vstage[c * 132 + nc * 4];
    }
}

// ============================================================================
//   flash attention: bf16 S (k16 mma + ldmatrix K), bf16 PV, fused bf16 proj
// ============================================================================
#define OFF_Q   0        // bf16 [128][16]  4096
#define OFF_K0  4096     // bf16 [128][16]  4096
#define OFF_K1  8192
#define OFF_V0  12288    // bf16 [128][136] 34816 (pw overlay at tt==31)
#define OFF_V1  47104
#define OFF_STG 0        // f32 [128][132]  67584 (over Q/K/pw/V1-head, post-proj)
#define SMEM_FL 81920

__device__ __forceinline__ void issue_tile(uint32_t sb, int buf,
    const __nv_bfloat16* __restrict__ kt, const __nv_bfloat16* __restrict__ vb,
    int b, int j0, int tid)
{
    uint32_t kdst = sb + (buf ? OFF_K1 : OFF_K0);
    {
        int row = tid >> 1, cc = tid & 1;
        cpa16(kdst + row * 32 + cc * 16,
              kt + ((size_t)(b * NN + j0 + row)) * D + cc * 8);
    }
    uint32_t vdst = sb + (buf ? OFF_V1 : OFF_V0);
    #pragma unroll
    for (int u = tid; u < 2048; u += 256) {
        int c = u >> 4, cc = u & 15;
        cpa16(vdst + c * 272 + cc * 16,
              vb + ((size_t)(b * C + c)) * NN + j0 + cc * 8);
    }
}

__global__ __launch_bounds__(256, 2) void flash_mma_kernel(
    const __nv_bfloat16* __restrict__ qt, const __nv_bfloat16* __restrict__ kt,
    const __nv_bfloat16* __restrict__ vb, const __nv_bfloat16* __restrict__ pwb,
    const float* __restrict__ pb, const float* __restrict__ x,
    float* __restrict__ out)
{
    extern __shared__ char sm[];
    const uint32_t sb = smem_u32(sm);
    const int tid = threadIdx.x;
    const int w = tid >> 5;
    const int lane = tid & 31;
    const int g = lane >> 2, t = lane & 3;
    const int b = blockIdx.x >> 5;
    const int q0 = (blockIdx.x & 31) * 128;

    // ldmatrix lane offsets
    const int rowsel = (lane & 7) + ((lane >> 4) << 3);
    const int ksel = (lane >> 3) & 1;
    const uint32_t vlane = (uint32_t)(rowsel * 272 + ksel * 16);        // V/pw tiles
    const uint32_t klane = (uint32_t)(rowsel * 32 + ksel * 16);         // K tiles
    const uint32_t qlane = (uint32_t)(
        (16 * w + (lane & 7) + (((lane >> 3) & 1) << 3)) * 32 + ((lane >> 4) & 1) * 16);

    // prologue: Q + tile 0
    {
        int row = tid >> 1, cc = tid & 1;
        cpa16(sb + OFF_Q + row * 32 + cc * 16,
              qt + ((size_t)(b * NN + q0 + row)) * D + cc * 8);
    }
    issue_tile(sb, 0, kt, vb, b, 0, tid);
    CP_COMMIT();

    uint32_t qa[4];
    float o[16][4];
    #pragma unroll
    for (int nb = 0; nb < 16; nb++)
        #pragma unroll
        for (int i = 0; i < 4; i++) o[nb][i] = 0.f;
    float rs0 = 0.f, rs1 = 0.f;

    for (int tt = 0; tt < 32; tt++) {
        const int buf = tt & 1;
        if (tt < 31) {
            issue_tile(sb, buf ^ 1, kt, vb, b, (tt + 1) * 128, tid);
            CP_COMMIT();
            CP_WAIT1();
        } else {
            CP_WAIT0();
        }
        __syncthreads();

        if (tt == 0) {   // Q A-fragments via one ldmatrix.x4
            ldm4(qa[0], qa[1], qa[2], qa[3], sb + OFF_Q + qlane);
        }
        if (tt == 31) {
            // V0 dead (last used by tile 30, protected by this tile's barrier):
            // load p_w (bf16, V-layout) into it, overlapped with tile-31 compute
            #pragma unroll
            for (int u = tid; u < 2048; u += 256) {
                int row = u >> 4, cc = u & 15;
                cpa16(sb + OFF_V0 + row * 272 + cc * 16, pwb + row * C + cc * 8);
            }
            CP_COMMIT();
        }

        const uint32_t kbase = sb + (buf ? OFF_K1 : OFF_K0) + klane;
        const uint32_t vbase = sb + (buf ? OFF_V1 : OFF_V0) + vlane;

        // ---- fused per-s-block pipeline: S (bf16 k16) -> exp2 -> PV (bf16)
        #pragma unroll
        for (int s = 0; s < 8; s++) {
            uint32_t kb0, kb1, kb2, kb3;
            ldm4(kb0, kb1, kb2, kb3, kbase + (uint32_t)(s * 512));
            float sc0[4] = {0.f, 0.f, 0.f, 0.f};
            float sc1[4] = {0.f, 0.f, 0.f, 0.f};
            mma_bf16(sc0, qa[0], qa[1], qa[2], qa[3], kb0, kb1);
            mma_bf16(sc1, qa[0], qa[1], qa[2], qa[3], kb2, kb3);
            float e0 = ex2f(sc0[0]);
            float e1 = ex2f(sc0[1]);
            float e2 = ex2f(sc0[2]);
            float e3 = ex2f(sc0[3]);
            float f0 = ex2f(sc1[0]);
            float f1 = ex2f(sc1[1]);
            float f2 = ex2f(sc1[2]);
            float f3 = ex2f(sc1[3]);
            rs0 += e0 + e1 + f0 + f1;
            rs1 += e2 + e3 + f2 + f3;
            uint32_t a0 = bf2(e1, e0);
            uint32_t a1 = bf2(e3, e2);
            uint32_t a2 = bf2(f1, f0);
            uint32_t a3 = bf2(f3, f2);
            #pragma unroll
            for (int nbp = 0; nbp < 8; nbp++) {
                uint32_t r0, r1, r2, r3;
                ldm4(r0, r1, r2, r3, vbase + (uint32_t)(nbp * 4352 + s * 32));
                mma_bf16(o[2*nbp],     a0, a1, a2, a3, r0, r1);
                mma_bf16(o[2*nbp + 1], a0, a1, a2, a3, r2, r3);
            }
        }
        __syncthreads();
    }

    rs0 += __shfl_xor_sync(0xffffffffu, rs0, 1);
    rs0 += __shfl_xor_sync(0xffffffffu, rs0, 2);
    rs1 += __shfl_xor_sync(0xffffffffu, rs1, 1);
    rs1 += __shfl_xor_sync(0xffffffffu, rs1, 2);
    const float il0 = 1.f / rs0, il1 = 1.f / rs1;

    uint32_t oa0[16], oa1[16];
    #pragma unroll
    for (int nb = 0; nb < 16; nb++) {
        oa0[nb] = bf2(o[nb][1] * il0, o[nb][0] * il0);
        oa1[nb] = bf2(o[nb][3] * il1, o[nb][2] * il1);
    }

    CP_WAIT0();          // p_w arrived in V0
    __syncthreads();

    // ---- fused projection (bf16): proj[q][e] = sum_c O[q][c] pw[e][c]
    float pr[16][4];
    #pragma unroll
    for (int nb = 0; nb < 16; nb++)
        #pragma unroll
        for (int i = 0; i < 4; i++) pr[nb][i] = 0.f;
    const uint32_t pwbase = sb + OFF_V0 + vlane;
    #pragma unroll
    for (int s = 0; s < 8; s++) {
        const uint32_t a0 = oa0[2*s], a1 = oa1[2*s];
        const uint32_t a2 = oa0[2*s+1], a3 = oa1[2*s+1];
        #pragma unroll
        for (int nbp = 0; nbp < 8; nbp++) {
            uint32_t r0, r1, r2, r3;
            ldm4(r0, r1, r2, r3, pwbase + (uint32_t)(nbp * 4352 + s * 32));
            mma_bf16(pr[2*nbp],     a0, a1, a2, a3, r0, r1);
            mma_bf16(pr[2*nbp + 1], a0, a1, a2, a3, r2, r3);
        }
    }
    __syncthreads();   // all pw reads done before stage overlay

    float* stg = (float*)(sm + OFF_STG);
    #pragma unroll
    for (int nb = 0; nb < 16; nb++) {
        int e = 8*nb + 2*t;
        stg[(e    ) * 132 + 16*w + g    ] = pr[nb][0];
        stg[(e + 1) * 132 + 16*w + g    ] = pr[nb][1];
        stg[(e    ) * 132 + 16*w + g + 8] = pr[nb][2];
        stg[(e + 1) * 132 + 16*w + g + 8] = pr[nb][3];
    }
    __syncthreads();

    #pragma unroll
    for (int it = 0; it < 16; it++) {
        int idx = tid + it * 256;
        int e = idx >> 5, qq = idx & 31;
        float4 v4 = *(float4*)&stg[e * 132 + qq * 4];
        float bias = __ldg(pb + e);
        size_t gi = ((size_t)b * C + e) * NN + q0 + qq * 4;
        float4 xr = *(const float4*)&x[gi];
        v4.x += bias + xr.x; v4.y += bias + xr.y;
        v4.z += bias + xr.z; v4.w += bias + xr.w;
        *(float4*)&out[gi] = v4;
    }
}

// ---------------- launch -----------------------------------------------------
extern "C" void kernel_launch(void* const* d_in, const int* in_sizes, int n_in,
                              void* d_out, int out_size)
{
    const float* x    = (const float*)d_in[0];
    const float* gn_w = (const float*)d_in[1];
    const float* gn_b = (const float*)d_in[2];
    const float* q_w  = (const float*)d_in[3];
    const float* q_b  = (const float*)d_in[4];
    const float* k_w  = (const float*)d_in[5];
    const float* k_b  = (const float*)d_in[6];
    const float* v_w  = (const float*)d_in[7];
    const float* v_b  = (const float*)d_in[8];
    const float* p_w  = (const float*)d_in[9];
    const float* p_b  = (const float*)d_in[10];
    float* out = (float*)d_out;

    float* st;
    __nv_bfloat16 *qt, *kt, *v, *pwb;
    cudaGetSymbolAddress((void**)&qt,  g_qt);
    cudaGetSymbolAddress((void**)&kt,  g_kt);
    cudaGetSymbolAddress((void**)&v,   g_v);
    cudaGetSymbolAddress((void**)&pwb, g_pwb);
    cudaGetSymbolAddress((void**)&st,  g_st);

    cudaFuncSetAttribute(flash_mma_kernel,
                         cudaFuncAttributeMaxDynamicSharedMemorySize, SMEM_FL);
    cudaFuncSetAttribute(qkv_proj_kernel,
                         cudaFuncAttributeMaxDynamicSharedMemorySize, SMEM_PJ);

    gn_stats_kernel<<<BATCH * G, 256>>>(x, st, p_w, pwb);

    qkv_proj_kernel<<<dim3(NN / 128, BATCH), 256, SMEM_PJ>>>(
        q_w, q_b, k_w, k_b, v_w, v_b, gn_w, gn_b, st, x, qt, kt, v);

    flash_mma_kernel<<<BATCH * 32, 256, SMEM_FL>>>(qt, kt, v, pwb, p_b, x, out);
}

// round 11
// speedup vs baseline: 1.1998x; 1.0208x over previous
#include <cuda_runtime.h>
#include <cuda_bf16.h>
#include <cstdint>
#include <math.h>

#define BATCH 8
#define C 128
#define NN 4096
#define D 16
#define G 32
#define CPG (C / G)
#define EPS 1e-5f
#define SCALE_Q 0.36067376022224085f   // 0.25 * log2(e)

// ---------------- scratch ----------------------------------------------------
__device__ __nv_bfloat16  g_qt [BATCH * NN * D];   // q [B,N,16] bf16, pre-scaled
__device__ __nv_bfloat16  g_kt [BATCH * NN * D];   // k [B,N,16] bf16
__device__ __nv_bfloat16  g_v  [BATCH * C * NN];   // v [B,C,N] bf16
__device__ __nv_bfloat16  g_pwb[C * C];            // p_w bf16 [e][c]
__device__ float          g_st [BATCH * G * 2];    // groupnorm (mean, rstd)

// ---------------- GroupNorm stats (+ p_w bf16 convert piggyback) -------------
__global__ __launch_bounds__(256) void gn_stats_kernel(
    const float* __restrict__ x, float* __restrict__ st,
    const float* __restrict__ pw, __nv_bfloat16* __restrict__ pwb)
{
    const int b = blockIdx.x >> 5;
    const int g = blockIdx.x & 31;
    const float* xp = x + ((size_t)b * C + g * CPG) * NN;

    if (threadIdx.x < 64) {   // 256 blocks x 64 = 16384 = C*C
        int i = blockIdx.x * 64 + threadIdx.x;
        pwb[i] = __float2bfloat16_rn(pw[i]);
    }

    const int TOT = CPG * NN;
    float s = 0.f, s2 = 0.f;
    for (int idx = threadIdx.x; idx < TOT; idx += 256) {
        float v = xp[idx];
        s += v; s2 += v * v;
    }
    __shared__ float red[16];
    int lane = threadIdx.x & 31, wid = threadIdx.x >> 5;
    #pragma unroll
    for (int o = 16; o > 0; o >>= 1) {
        s  += __shfl_xor_sync(0xffffffffu, s,  o);
        s2 += __shfl_xor_sync(0xffffffffu, s2, o);
    }
    if (lane == 0) { red[wid] = s; red[8 + wid] = s2; }
    __syncthreads();
    if (wid == 0) {
        float a = (lane < 8) ? red[lane] : 0.f;
        float a2 = (lane < 8) ? red[8 + lane] : 0.f;
        #pragma unroll
        for (int o = 4; o > 0; o >>= 1) {
            a  += __shfl_xor_sync(0xffffffffu, a,  o);
            a2 += __shfl_xor_sync(0xffffffffu, a2, o);
        }
        if (lane == 0) {
            const float inv_n = 1.f / (float)TOT;
            float mean = a * inv_n;
            float var = a2 * inv_n - mean * mean;
            st[blockIdx.x * 2]     = mean;
            st[blockIdx.x * 2 + 1] = rsqrtf(var + EPS);
        }
    }
}

// ---------------- mma helpers ------------------------------------------------
__device__ __forceinline__ uint32_t smem_u32(const void* p) {
    uint32_t a;
    asm("{ .reg .u64 t; cvta.to.shared.u64 t, %1; cvt.u32.u64 %0, t; }" : "=r"(a) : "l"(p));
    return a;
}
__device__ __forceinline__ void cpa16(uint32_t s, const void* g) {
    asm volatile("cp.async.cg.shared.global [%0], [%1], 16;" :: "r"(s), "l"(g));
}
#define CP_COMMIT() asm volatile("cp.async.commit_group;" ::: "memory")
#define CP_WAIT1()  asm volatile("cp.async.wait_group 1;" ::: "memory")
#define CP_WAIT0()  asm volatile("cp.async.wait_group 0;" ::: "memory")

__device__ __forceinline__ uint32_t f2tf(float f) {
    uint32_t u; asm("cvt.rna.tf32.f32 %0, %1;" : "=r"(u) : "f"(f)); return u;
}
__device__ __forceinline__ float ex2f(float f) {
    float r; asm("ex2.approx.f32 %0, %1;" : "=f"(r) : "f"(f)); return r;
}
__device__ __forceinline__ uint32_t bf2(float hi, float lo) {
    uint32_t r; asm("cvt.rn.bf16x2.f32 %0, %1, %2;" : "=r"(r) : "f"(hi), "f"(lo)); return r;
}
__device__ __forceinline__ void mma_tf32(float* c, const uint32_t* a,
                                         uint32_t b0, uint32_t b1) {
    asm volatile(
        "mma.sync.aligned.m16n8k8.row.col.f32.tf32.tf32.f32 "
        "{%0,%1,%2,%3},{%4,%5,%6,%7},{%8,%9},{%0,%1,%2,%3};"
        : "+f"(c[0]), "+f"(c[1]), "+f"(c[2]), "+f"(c[3])
        : "r"(a[0]), "r"(a[1]), "r"(a[2]), "r"(a[3]), "r"(b0), "r"(b1));
}
__device__ __forceinline__ void mma_bf16(float* c, uint32_t a0, uint32_t a1,
                                         uint32_t a2, uint32_t a3,
                                         uint32_t b0, uint32_t b1) {
    asm volatile(
        "mma.sync.aligned.m16n8k16.row.col.f32.bf16.bf16.f32 "
        "{%0,%1,%2,%3},{%4,%5,%6,%7},{%8,%9},{%0,%1,%2,%3};"
        : "+f"(c[0]), "+f"(c[1]), "+f"(c[2]), "+f"(c[3])
        : "r"(a0), "r"(a1), "r"(a2), "r"(a3), "r"(b0), "r"(b1));
}
__device__ __forceinline__ void ldm4(uint32_t& r0, uint32_t& r1, uint32_t& r2,
                                     uint32_t& r3, uint32_t addr) {
    asm volatile("ldmatrix.sync.aligned.m8n8.x4.shared.b16 {%0,%1,%2,%3}, [%4];"
                 : "=r"(r0), "=r"(r1), "=r"(r2), "=r"(r3) : "r"(addr));
}

// ============================================================================
//   fused GN + QKV projection (tf32 mma): q/k written as bf16, v bf16
// ============================================================================
#define PJ_HT   0
#define PJ_WS   67584
#define PJ_BIAS 152064
#define PJ_SC   152704
#define SMEM_PJ 153728

__global__ __launch_bounds__(256) void qkv_proj_kernel(
    const float* __restrict__ qw, const float* __restrict__ qb,
    const float* __restrict__ kw, const float* __restrict__ kb,
    const float* __restrict__ vw, const float* __restrict__ vb,
    const float* __restrict__ gnw, const float* __restrict__ gnb,
    const float* __restrict__ st, const float* __restrict__ x,
    __nv_bfloat16* __restrict__ qt, __nv_bfloat16* __restrict__ kt,
    __nv_bfloat16* __restrict__ vout)
{
    extern __shared__ char sm[];
    uint32_t* hT = (uint32_t*)(sm + PJ_HT);
    uint32_t* Ws = (uint32_t*)(sm + PJ_WS);
    float* bs = (float*)(sm + PJ_BIAS);
    float* sc = (float*)(sm + PJ_SC);
    float* sh = sc + 128;
    const int tid = threadIdx.x;
    const int w = tid >> 5, lane = tid & 31;
    const int g = lane >> 2, t = lane & 3;
    const int n0 = blockIdx.x * 128;
    const int b = blockIdx.y;

    if (tid < 128) {
        float mean = st[(b * G + (tid >> 2)) * 2];
        float inv  = st[(b * G + (tid >> 2)) * 2 + 1];
        float s = gnw[tid] * inv;
        sc[tid] = s;
        sh[tid] = gnb[tid] - mean * s;
    }
    for (int u = tid; u < 160 * 128; u += 256) {
        int e = u >> 7, c = u & 127;
        float wv;
        if (e < 16)      wv = qw[e * C + c];
        else if (e < 32) wv = kw[(e - 16) * C + c];
        else             wv = vw[(e - 32) * C + c];
        Ws[e * 132 + c] = f2tf(wv);
    }
    if (tid < 160) {
        float bv;
        if (tid < 16)      bv = qb[tid];
        else if (tid < 32) bv = kb[tid - 16];
        else               bv = vb[tid - 32];
        bs[tid] = bv;
    }
    __syncthreads();

    for (int u = tid; u < 128 * 128; u += 256) {
        int n = u & 127, c = u >> 7;
        float hv = fmaf(x[((size_t)b * C + c) * NN + n0 + n], sc[c], sh[c]);
        hT[n * 132 + c] = f2tf(hv);
    }
    __syncthreads();

    uint32_t af[16][4];
    #pragma unroll
    for (int kc = 0; kc < 16; kc++) {
        af[kc][0] = hT[(16 * w + g    ) * 132 + 8 * kc + t    ];
        af[kc][1] = hT[(16 * w + g + 8) * 132 + 8 * kc + t    ];
        af[kc][2] = hT[(16 * w + g    ) * 132 + 8 * kc + t + 4];
        af[kc][3] = hT[(16 * w + g + 8) * 132 + 8 * kc + t + 4];
    }

    float pr[20][4];
    #pragma unroll
    for (int nb = 0; nb < 20; nb++)
        #pragma unroll
        for (int i = 0; i < 4; i++) pr[nb][i] = 0.f;

    #pragma unroll
    for (int kc = 0; kc < 16; kc++) {
        #pragma unroll
        for (int nb = 0; nb < 20; nb++) {
            uint32_t b0 = Ws[(8 * nb + g) * 132 + 8 * kc + t    ];
            uint32_t b1 = Ws[(8 * nb + g) * 132 + 8 * kc + t + 4];
            mma_tf32(pr[nb], af[kc], b0, b1);
        }
    }

    const int r0 = 16 * w + g, r1 = r0 + 8;
    #pragma unroll
    for (int nb = 0; nb < 4; nb++) {
        int e = 8 * nb + 2 * t;
        float b0 = bs[e], b1 = bs[e + 1];
        if (e < 16) {   // q: pre-scaled by 0.25*log2e, bf16x2 packed
            *(uint32_t*)&qt[((size_t)b * NN + n0 + r0) * D + e] =
                bf2((pr[nb][1] + b1) * SCALE_Q, (pr[nb][0] + b0) * SCALE_Q);
            *(uint32_t*)&qt[((size_t)b * NN + n0 + r1) * D + e] =
                bf2((pr[nb][3] + b1) * SCALE_Q, (pr[nb][2] + b0) * SCALE_Q);
        } else {        // k: bf16x2 packed
            int E = e - 16;
            *(uint32_t*)&kt[((size_t)b * NN + n0 + r0) * D + E] =
                bf2(pr[nb][1] + b1, pr[nb][0] + b0);
            *(uint32_t*)&kt[((size_t)b * NN + n0 + r1) * D + E] =
                bf2(pr[nb][3] + b1, pr[nb][2] + b0);
        }
    }
    __syncthreads();

    __nv_bfloat16* vstage = (__nv_bfloat16*)(sm + PJ_WS);
    #pragma unroll
    for (int nb = 4; nb < 20; nb++) {
        int e = 8 * nb + 2 * t;
        int cv = e - 32;
        float b0 = bs[e], b1 = bs[e + 1];
        vstage[(cv    ) * 132 + r0] = __float2bfloat16_rn(pr[nb][0] + b0);
        vstage[(cv + 1) * 132 + r0] = __float2bfloat16_rn(pr[nb][1] + b1);
        vstage[(cv    ) * 132 + r1] = __float2bfloat16_rn(pr[nb][2] + b0);
        vstage[(cv + 1) * 132 + r1] = __float2bfloat16_rn(pr[nb][3] + b1);
    }
    __syncthreads();
    for (int u = tid; u < 128 * 32; u += 256) {
        int c = u >> 5, nc = u & 31;
        *(uint64_t*)&vout[((size_t)b * C + c) * NN + n0 + nc * 4] =
            *(const uint64_t*)&vstage[c * 132 + nc * 4];
    }
}

// ============================================================================
//   flash attention: bf16 S + ldmatrix K, bf16 PV, row-sums via ones-mma
// ============================================================================
#define OFF_Q   0        // bf16 [128][16]  4096
#define OFF_K0  4096     // bf16 [128][16]  4096
#define OFF_K1  8192
#define OFF_V0  12288    // bf16 [128][136] 34816 (pw overlay at tt==31)
#define OFF_V1  47104
#define OFF_STG 0        // f32 [128][132]  67584 (post-proj overlay)
#define SMEM_FL 81920

__device__ __forceinline__ void issue_tile(uint32_t sb, int buf,
    const __nv_bfloat16* __restrict__ kt, const __nv_bfloat16* __restrict__ vb,
    int b, int j0, int tid)
{
    uint32_t kdst = sb + (buf ? OFF_K1 : OFF_K0);
    {
        int row = tid >> 1, cc = tid & 1;
        cpa16(kdst + row * 32 + cc * 16,
              kt + ((size_t)(b * NN + j0 + row)) * D + cc * 8);
    }
    uint32_t vdst = sb + (buf ? OFF_V1 : OFF_V0);
    #pragma unroll
    for (int u = tid; u < 2048; u += 256) {
        int c = u >> 4, cc = u & 15;
        cpa16(vdst + c * 272 + cc * 16,
              vb + ((size_t)(b * C + c)) * NN + j0 + cc * 8);
    }
}

__global__ __launch_bounds__(256, 2) void flash_mma_kernel(
    const __nv_bfloat16* __restrict__ qt, const __nv_bfloat16* __restrict__ kt,
    const __nv_bfloat16* __restrict__ vb, const __nv_bfloat16* __restrict__ pwb,
    const float* __restrict__ pb, const float* __restrict__ x,
    float* __restrict__ out)
{
    extern __shared__ char sm[];
    const uint32_t sb = smem_u32(sm);
    const int tid = threadIdx.x;
    const int w = tid >> 5;
    const int lane = tid & 31;
    const int g = lane >> 2, t = lane & 3;
    const int b = blockIdx.x >> 5;
    const int q0 = (blockIdx.x & 31) * 128;

    const int rowsel = (lane & 7) + ((lane >> 4) << 3);
    const int ksel = (lane >> 3) & 1;
    const uint32_t vlane = (uint32_t)(rowsel * 272 + ksel * 16);
    const uint32_t klane = (uint32_t)(rowsel * 32 + ksel * 16);
    const uint32_t qlane = (uint32_t)(
        (16 * w + (lane & 7) + (((lane >> 3) & 1) << 3)) * 32 + ((lane >> 4) & 1) * 16);

    {
        int row = tid >> 1, cc = tid & 1;
        cpa16(sb + OFF_Q + row * 32 + cc * 16,
              qt + ((size_t)(b * NN + q0 + row)) * D + cc * 8);
    }
    issue_tile(sb, 0, kt, vb, b, 0, tid);
    CP_COMMIT();

    uint32_t qa[4];
    float o[16][4];
    #pragma unroll
    for (int nb = 0; nb < 16; nb++)
        #pragma unroll
        for (int i = 0; i < 4; i++) o[nb][i] = 0.f;
    float ls[4] = {0.f, 0.f, 0.f, 0.f};     // row-sum C-frag (cols replicated)
    const uint32_t ONES2 = 0x3F803F80u;      // bf16 {1.0, 1.0}

    for (int tt = 0; tt < 32; tt++) {
        const int buf = tt & 1;
        if (tt < 31) {
            issue_tile(sb, buf ^ 1, kt, vb, b, (tt + 1) * 128, tid);
            CP_COMMIT();
            CP_WAIT1();
        } else {
            CP_WAIT0();
        }
        __syncthreads();

        if (tt == 0) {
            ldm4(qa[0], qa[1], qa[2], qa[3], sb + OFF_Q + qlane);
        }
        if (tt == 31) {
            // V0 dead (last used tile 30, protected by this tile's barrier)
            #pragma unroll
            for (int u = tid; u < 2048; u += 256) {
                int row = u >> 4, cc = u & 15;
                cpa16(sb + OFF_V0 + row * 272 + cc * 16, pwb + row * C + cc * 8);
            }
            CP_COMMIT();
        }

        const uint32_t kbase = sb + (buf ? OFF_K1 : OFF_K0) + klane;
        const uint32_t vbase = sb + (buf ? OFF_V1 : OFF_V0) + vlane;

        // ---- fused per-s-block: S (bf16) -> exp2 -> rowsum-mma + PV
        #pragma unroll
        for (int s = 0; s < 8; s++) {
            uint32_t kb0, kb1, kb2, kb3;
            ldm4(kb0, kb1, kb2, kb3, kbase + (uint32_t)(s * 512));
            float sc0[4] = {0.f, 0.f, 0.f, 0.f};
            float sc1[4] = {0.f, 0.f, 0.f, 0.f};
            mma_bf16(sc0, qa[0], qa[1], qa[2], qa[3], kb0, kb1);
            mma_bf16(sc1, qa[0], qa[1], qa[2], qa[3], kb2, kb3);
            uint32_t a0 = bf2(ex2f(sc0[1]), ex2f(sc0[0]));
            uint32_t a1 = bf2(ex2f(sc0[3]), ex2f(sc0[2]));
            uint32_t a2 = bf2(ex2f(sc1[1]), ex2f(sc1[0]));
            uint32_t a3 = bf2(ex2f(sc1[3]), ex2f(sc1[2]));
            // row sums: P x ones (every output column = rowsum contribution)
            mma_bf16(ls, a0, a1, a2, a3, ONES2, ONES2);
            #pragma unroll
            for (int nbp = 0; nbp < 8; nbp++) {
                uint32_t r0, r1, r2, r3;
                ldm4(r0, r1, r2, r3, vbase + (uint32_t)(nbp * 4352 + s * 32));
                mma_bf16(o[2*nbp],     a0, a1, a2, a3, r0, r1);
                mma_bf16(o[2*nbp + 1], a0, a1, a2, a3, r2, r3);
            }
        }
        __syncthreads();
    }

    // row sums complete per-lane (columns replicated): no shuffles needed
    const float il0 = 1.f / ls[0], il1 = 1.f / ls[2];

    uint32_t oa0[16], oa1[16];
    #pragma unroll
    for (int nb = 0; nb < 16; nb++) {
        oa0[nb] = bf2(o[nb][1] * il0, o[nb][0] * il0);
        oa1[nb] = bf2(o[nb][3] * il1, o[nb][2] * il1);
    }

    CP_WAIT0();          // p_w arrived in V0
    __syncthreads();

    // ---- fused projection (bf16): proj[q][e] = sum_c O[q][c] pw[e][c]
    float pr[16][4];
    #pragma unroll
    for (int nb = 0; nb < 16; nb++)
        #pragma unroll
        for (int i = 0; i < 4; i++) pr[nb][i] = 0.f;
    const uint32_t pwbase = sb + OFF_V0 + vlane;
    #pragma unroll
    for (int s = 0; s < 8; s++) {
        const uint32_t a0 = oa0[2*s], a1 = oa1[2*s];
        const uint32_t a2 = oa0[2*s+1], a3 = oa1[2*s+1];
        #pragma unroll
        for (int nbp = 0; nbp < 8; nbp++) {
            uint32_t r0, r1, r2, r3;
            ldm4(r0, r1, r2, r3, pwbase + (uint32_t)(nbp * 4352 + s * 32));
            mma_bf16(pr[2*nbp],     a0, a1, a2, a3, r0, r1);
            mma_bf16(pr[2*nbp + 1], a0, a1, a2, a3, r2, r3);
        }
    }
    __syncthreads();   // all pw reads done before stage overlay

    float* stg = (float*)(sm + OFF_STG);
    #pragma unroll
    for (int nb = 0; nb < 16; nb++) {
        int e = 8*nb + 2*t;
        stg[(e    ) * 132 + 16*w + g    ] = pr[nb][0];
        stg[(e + 1) * 132 + 16*w + g    ] = pr[nb][1];
        stg[(e    ) * 132 + 16*w + g + 8] = pr[nb][2];
        stg[(e + 1) * 132 + 16*w + g + 8] = pr[nb][3];
    }
    __syncthreads();

    #pragma unroll
    for (int it = 0; it < 16; it++) {
        int idx = tid + it * 256;
        int e = idx >> 5, qq = idx & 31;
        float4 v4 = *(float4*)&stg[e * 132 + qq * 4];
        float bias = __ldg(pb + e);
        size_t gi = ((size_t)b * C + e) * NN + q0 + qq * 4;
        float4 xr = *(const float4*)&x[gi];
        v4.x += bias + xr.x; v4.y += bias + xr.y;
        v4.z += bias + xr.z; v4.w += bias + xr.w;
        *(float4*)&out[gi] = v4;
    }
}

// ---------------- launch -----------------------------------------------------
extern "C" void kernel_launch(void* const* d_in, const int* in_sizes, int n_in,
                              void* d_out, int out_size)
{
    const float* x    = (const float*)d_in[0];
    const float* gn_w = (const float*)d_in[1];
    const float* gn_b = (const float*)d_in[2];
    const float* q_w  = (const float*)d_in[3];
    const float* q_b  = (const float*)d_in[4];
    const float* k_w  = (const float*)d_in[5];
    const float* k_b  = (const float*)d_in[6];
    const float* v_w  = (const float*)d_in[7];
    const float* v_b  = (const float*)d_in[8];
    const float* p_w  = (const float*)d_in[9];
    const float* p_b  = (const float*)d_in[10];
    float* out = (float*)d_out;

    float* st;
    __nv_bfloat16 *qt, *kt, *v, *pwb;
    cudaGetSymbolAddress((void**)&qt,  g_qt);
    cudaGetSymbolAddress((void**)&kt,  g_kt);
    cudaGetSymbolAddress((void**)&v,   g_v);
    cudaGetSymbolAddress((void**)&pwb, g_pwb);
    cudaGetSymbolAddress((void**)&st,  g_st);

    cudaFuncSetAttribute(flash_mma_kernel,
                         cudaFuncAttributeMaxDynamicSharedMemorySize, SMEM_FL);
    cudaFuncSetAttribute(qkv_proj_kernel,
                         cudaFuncAttributeMaxDynamicSharedMemorySize, SMEM_PJ);

    gn_stats_kernel<<<BATCH * G, 256>>>(x, st, p_w, pwb);

    qkv_proj_kernel<<<dim3(NN / 128, BATCH), 256, SMEM_PJ>>>(
        q_w, q_b, k_w, k_b, v_w, v_b, gn_w, gn_b, st, x, qt, kt, v);

    flash_mma_kernel<<<BATCH * 32, 256, SMEM_FL>>>(qt, kt, v, pwb, p_b, x, out);
}

// round 12
// speedup vs baseline: 1.4517x; 1.2099x over previous
#include <cuda_runtime.h>
#include <cuda_bf16.h>
#include <cstdint>
#include <math.h>

#define BATCH 8
#define C 128
#define NN 4096
#define D 16
#define G 32
#define CPG (C / G)
#define EPS 1e-5f
#define SCALE_Q 0.36067376022224085f   // 0.25 * log2(e)

// ---------------- scratch ----------------------------------------------------
__device__ __nv_bfloat16  g_qt [BATCH * NN * D];   // q [B,N,16] bf16, pre-scaled
__device__ __nv_bfloat16  g_kt [BATCH * NN * D];   // k [B,N,16] bf16
__device__ __nv_bfloat16  g_v  [BATCH * C * NN];   // v [B,C,N] bf16
__device__ __nv_bfloat16  g_pwb[C * C];            // p_w bf16 [e][c]
__device__ float          g_st [BATCH * G * 2];    // groupnorm (mean, rstd)

// ---------------- GroupNorm stats (+ p_w bf16 convert piggyback) -------------
__global__ __launch_bounds__(256) void gn_stats_kernel(
    const float* __restrict__ x, float* __restrict__ st,
    const float* __restrict__ pw, __nv_bfloat16* __restrict__ pwb)
{
    const int b = blockIdx.x >> 5;
    const int g = blockIdx.x & 31;
    const float4* xp = (const float4*)(x + ((size_t)b * C + g * CPG) * NN);

    if (threadIdx.x < 64) {
        int i = blockIdx.x * 64 + threadIdx.x;
        pwb[i] = __float2bfloat16_rn(pw[i]);
    }

    const int TOT4 = CPG * NN / 4;   // 4096 float4
    float s = 0.f, s2 = 0.f;
    for (int idx = threadIdx.x; idx < TOT4; idx += 256) {
        float4 v = xp[idx];
        s  += v.x + v.y + v.z + v.w;
        s2 += v.x * v.x + v.y * v.y + v.z * v.z + v.w * v.w;
    }
    __shared__ float red[16];
    int lane = threadIdx.x & 31, wid = threadIdx.x >> 5;
    #pragma unroll
    for (int o = 16; o > 0; o >>= 1) {
        s  += __shfl_xor_sync(0xffffffffu, s,  o);
        s2 += __shfl_xor_sync(0xffffffffu, s2, o);
    }
    if (lane == 0) { red[wid] = s; red[8 + wid] = s2; }
    __syncthreads();
    if (wid == 0) {
        float a = (lane < 8) ? red[lane] : 0.f;
        float a2 = (lane < 8) ? red[8 + lane] : 0.f;
        #pragma unroll
        for (int o = 4; o > 0; o >>= 1) {
            a  += __shfl_xor_sync(0xffffffffu, a,  o);
            a2 += __shfl_xor_sync(0xffffffffu, a2, o);
        }
        if (lane == 0) {
            const float inv_n = 1.f / (float)(CPG * NN);
            float mean = a * inv_n;
            float var = a2 * inv_n - mean * mean;
            st[blockIdx.x * 2]     = mean;
            st[blockIdx.x * 2 + 1] = rsqrtf(var + EPS);
        }
    }
}

// ---------------- mma helpers ------------------------------------------------
__device__ __forceinline__ uint32_t smem_u32(const void* p) {
    uint32_t a;
    asm("{ .reg .u64 t; cvta.to.shared.u64 t, %1; cvt.u32.u64 %0, t; }" : "=r"(a) : "l"(p));
    return a;
}
__device__ __forceinline__ void cpa16(uint32_t s, const void* g) {
    asm volatile("cp.async.cg.shared.global [%0], [%1], 16;" :: "r"(s), "l"(g));
}
#define CP_COMMIT() asm volatile("cp.async.commit_group;" ::: "memory")
#define CP_WAIT1()  asm volatile("cp.async.wait_group 1;" ::: "memory")
#define CP_WAIT0()  asm volatile("cp.async.wait_group 0;" ::: "memory")

__device__ __forceinline__ float ex2f(float f) {
    float r; asm("ex2.approx.f32 %0, %1;" : "=f"(r) : "f"(f)); return r;
}
__device__ __forceinline__ uint32_t bf2(float hi, float lo) {
    uint32_t r; asm("cvt.rn.bf16x2.f32 %0, %1, %2;" : "=r"(r) : "f"(hi), "f"(lo)); return r;
}
__device__ __forceinline__ void mma_bf16(float* c, uint32_t a0, uint32_t a1,
                                         uint32_t a2, uint32_t a3,
                                         uint32_t b0, uint32_t b1) {
    asm volatile(
        "mma.sync.aligned.m16n8k16.row.col.f32.bf16.bf16.f32 "
        "{%0,%1,%2,%3},{%4,%5,%6,%7},{%8,%9},{%0,%1,%2,%3};"
        : "+f"(c[0]), "+f"(c[1]), "+f"(c[2]), "+f"(c[3])
        : "r"(a0), "r"(a1), "r"(a2), "r"(a3), "r"(b0), "r"(b1));
}
__device__ __forceinline__ void ldm4(uint32_t& r0, uint32_t& r1, uint32_t& r2,
                                     uint32_t& r3, uint32_t addr) {
    asm volatile("ldmatrix.sync.aligned.m8n8.x4.shared.b16 {%0,%1,%2,%3}, [%4];"
                 : "=r"(r0), "=r"(r1), "=r"(r2), "=r"(r3) : "r"(addr));
}

// ============================================================================
//   fused GN + QKV projection (bf16 mma, 2 CTAs/SM)
//   smem: hT [128n][68] u32 (bf16x2 pairs) | Ws [160e][68] u32 | bias | sc/sh
// ============================================================================
#define PJ_HT   0                  // 34816
#define PJ_WS   34816              // 43520 (vstage overlay in epilogue)
#define PJ_BIAS 78336              // 640
#define PJ_SC   79104              // 1024
#define SMEM_PJ 80128

__global__ __launch_bounds__(256, 2) void qkv_proj_kernel(
    const float* __restrict__ qw, const float* __restrict__ qb,
    const float* __restrict__ kw, const float* __restrict__ kb,
    const float* __restrict__ vw, const float* __restrict__ vb,
    const float* __restrict__ gnw, const float* __restrict__ gnb,
    const float* __restrict__ st, const float* __restrict__ x,
    __nv_bfloat16* __restrict__ qt, __nv_bfloat16* __restrict__ kt,
    __nv_bfloat16* __restrict__ vout)
{
    extern __shared__ char sm[];
    uint32_t* hT = (uint32_t*)(sm + PJ_HT);    // [n][68] bf16x2 of (2c,2c+1)
    uint32_t* Ws = (uint32_t*)(sm + PJ_WS);    // [e][68] bf16x2
    float* bs = (float*)(sm + PJ_BIAS);
    float* sc = (float*)(sm + PJ_SC);
    float* sh = sc + 128;
    const int tid = threadIdx.x;
    const int w = tid >> 5, lane = tid & 31;
    const int g = lane >> 2, t = lane & 3;
    const int n0 = blockIdx.x * 128;
    const int b = blockIdx.y;

    if (tid < 128) {
        float mean = st[(b * G + (tid >> 2)) * 2];
        float inv  = st[(b * G + (tid >> 2)) * 2 + 1];
        float s = gnw[tid] * inv;
        sc[tid] = s;
        sh[tid] = gnb[tid] - mean * s;
    }
    // weights bf16x2 [e][68]
    for (int u = tid; u < 160 * 64; u += 256) {
        int e = u >> 6, c2 = u & 63;
        const float* wsrc;
        if (e < 16)      wsrc = qw + e * C;
        else if (e < 32) wsrc = kw + (e - 16) * C;
        else             wsrc = vw + (e - 32) * C;
        Ws[e * 68 + c2] = bf2(wsrc[2 * c2 + 1], wsrc[2 * c2]);
    }
    if (tid < 160) {
        float bv;
        if (tid < 16)      bv = qb[tid];
        else if (tid < 32) bv = kb[tid - 16];
        else               bv = vb[tid - 32];
        bs[tid] = bv;
    }
    __syncthreads();   // sc/sh ready

    // h tile transposed + normalized -> hT[n][c2] bf16x2
    for (int u = tid; u < 128 * 64; u += 256) {
        int n = u & 127, c2 = u >> 7;
        float h0 = fmaf(x[((size_t)b * C + 2 * c2)     * NN + n0 + n], sc[2 * c2],     sh[2 * c2]);
        float h1 = fmaf(x[((size_t)b * C + 2 * c2 + 1) * NN + n0 + n], sc[2 * c2 + 1], sh[2 * c2 + 1]);
        hT[n * 68 + c2] = bf2(h1, h0);
    }
    __syncthreads();

    float pr[20][4];
    #pragma unroll
    for (int nb = 0; nb < 20; nb++)
        #pragma unroll
        for (int i = 0; i < 4; i++) pr[nb][i] = 0.f;

    #pragma unroll
    for (int kc = 0; kc < 8; kc++) {
        uint32_t a0 = hT[(16 * w + g    ) * 68 + 8 * kc + t    ];
        uint32_t a1 = hT[(16 * w + g + 8) * 68 + 8 * kc + t    ];
        uint32_t a2 = hT[(16 * w + g    ) * 68 + 8 * kc + t + 4];
        uint32_t a3 = hT[(16 * w + g + 8) * 68 + 8 * kc + t + 4];
        #pragma unroll
        for (int nb = 0; nb < 20; nb++) {
            uint32_t b0 = Ws[(8 * nb + g) * 68 + 8 * kc + t    ];
            uint32_t b1 = Ws[(8 * nb + g) * 68 + 8 * kc + t + 4];
            mma_bf16(pr[nb], a0, a1, a2, a3, b0, b1);
        }
    }

    const int r0 = 16 * w + g, r1 = r0 + 8;
    #pragma unroll
    for (int nb = 0; nb < 4; nb++) {
        int e = 8 * nb + 2 * t;
        float b0 = bs[e], b1 = bs[e + 1];
        if (e < 16) {   // q: pre-scaled, bf16x2 packed
            *(uint32_t*)&qt[((size_t)b * NN + n0 + r0) * D + e] =
                bf2((pr[nb][1] + b1) * SCALE_Q, (pr[nb][0] + b0) * SCALE_Q);
            *(uint32_t*)&qt[((size_t)b * NN + n0 + r1) * D + e] =
                bf2((pr[nb][3] + b1) * SCALE_Q, (pr[nb][2] + b0) * SCALE_Q);
        } else {        // k
            int E = e - 16;
            *(uint32_t*)&kt[((size_t)b * NN + n0 + r0) * D + E] =
                bf2(pr[nb][1] + b1, pr[nb][0] + b0);
            *(uint32_t*)&kt[((size_t)b * NN + n0 + r1) * D + E] =
                bf2(pr[nb][3] + b1, pr[nb][2] + b0);
        }
    }
    __syncthreads();   // Ws reads done before vstage overlay

    __nv_bfloat16* vstage = (__nv_bfloat16*)(sm + PJ_WS);   // [c][132] bf16
    #pragma unroll
    for (int nb = 4; nb < 20; nb++) {
        int e = 8 * nb + 2 * t;
        int cv = e - 32;
        float b0 = bs[e], b1 = bs[e + 1];
        vstage[(cv    ) * 132 + r0] = __float2bfloat16_rn(pr[nb][0] + b0);
        vstage[(cv + 1) * 132 + r0] = __float2bfloat16_rn(pr[nb][1] + b1);
        vstage[(cv    ) * 132 + r1] = __float2bfloat16_rn(pr[nb][2] + b0);
        vstage[(cv + 1) * 132 + r1] = __float2bfloat16_rn(pr[nb][3] + b1);
    }
    __syncthreads();
    for (int u = tid; u < 128 * 32; u += 256) {
        int c = u >> 5, nc = u & 31;
        *(uint64_t*)&vout[((size_t)b * C + c) * NN + n0 + nc * 4] =
            *(const uint64_t*)&vstage[c * 132 + nc * 4];
    }
}

// ============================================================================
//   flash attention: bf16 S + pipelined ldmatrix K, bf16 PV, ones-mma rowsums
// ============================================================================
#define OFF_Q   0        // bf16 [128][16]  4096
#define OFF_K0  4096
#define OFF_K1  8192
#define OFF_V0  12288    // bf16 [128][136] 34816 (pw overlay at tt==31)
#define OFF_V1  47104
#define OFF_STG 0        // f32 [128][132] 67584 (post-proj overlay)
#define SMEM_FL 81920

__device__ __forceinline__ void issue_tile(uint32_t sb, int buf,
    const __nv_bfloat16* __restrict__ kt, const __nv_bfloat16* __restrict__ vb,
    int b, int j0, int tid)
{
    uint32_t kdst = sb + (buf ? OFF_K1 : OFF_K0);
    {
        int row = tid >> 1, cc = tid & 1;
        cpa16(kdst + row * 32 + cc * 16,
              kt + ((size_t)(b * NN + j0 + row)) * D + cc * 8);
    }
    uint32_t vdst = sb + (buf ? OFF_V1 : OFF_V0);
    #pragma unroll
    for (int u = tid; u < 2048; u += 256) {
        int c = u >> 4, cc = u & 15;
        cpa16(vdst + c * 272 + cc * 16,
              vb + ((size_t)(b * C + c)) * NN + j0 + cc * 8);
    }
}

__global__ __launch_bounds__(256, 2) void flash_mma_kernel(
    const __nv_bfloat16* __restrict__ qt, const __nv_bfloat16* __restrict__ kt,
    const __nv_bfloat16* __restrict__ vb, const __nv_bfloat16* __restrict__ pwb,
    const float* __restrict__ pb, const float* __restrict__ x,
    float* __restrict__ out)
{
    extern __shared__ char sm[];
    const uint32_t sb = smem_u32(sm);
    const int tid = threadIdx.x;
    const int w = tid >> 5;
    const int lane = tid & 31;
    const int g = lane >> 2, t = lane & 3;
    const int b = blockIdx.x >> 5;
    const int q0 = (blockIdx.x & 31) * 128;

    const int rowsel = (lane & 7) + ((lane >> 4) << 3);
    const int ksel = (lane >> 3) & 1;
    const uint32_t vlane = (uint32_t)(rowsel * 272 + ksel * 16);
    const uint32_t klane = (uint32_t)(rowsel * 32 + ksel * 16);
    const uint32_t qlane = (uint32_t)(
        (16 * w + (lane & 7) + (((lane >> 3) & 1) << 3)) * 32 + ((lane >> 4) & 1) * 16);

    {
        int row = tid >> 1, cc = tid & 1;
        cpa16(sb + OFF_Q + row * 32 + cc * 16,
              qt + ((size_t)(b * NN + q0 + row)) * D + cc * 8);
    }
    issue_tile(sb, 0, kt, vb, b, 0, tid);
    CP_COMMIT();

    uint32_t qa[4];
    float o[16][4];
    #pragma unroll
    for (int nb = 0; nb < 16; nb++)
        #pragma unroll
        for (int i = 0; i < 4; i++) o[nb][i] = 0.f;
    float ls[4] = {0.f, 0.f, 0.f, 0.f};
    const uint32_t ONES2 = 0x3F803F80u;

    for (int tt = 0; tt < 32; tt++) {
        const int buf = tt & 1;
        if (tt < 31) {
            issue_tile(sb, buf ^ 1, kt, vb, b, (tt + 1) * 128, tid);
            CP_COMMIT();
            CP_WAIT1();
        } else {
            CP_WAIT0();
        }
        __syncthreads();

        if (tt == 0) {
            ldm4(qa[0], qa[1], qa[2], qa[3], sb + OFF_Q + qlane);
        }
        if (tt == 31) {
            #pragma unroll
            for (int u = tid; u < 2048; u += 256) {
                int row = u >> 4, cc = u & 15;
                cpa16(sb + OFF_V0 + row * 272 + cc * 16, pwb + row * C + cc * 8);
            }
            CP_COMMIT();
        }

        const uint32_t kbase = sb + (buf ? OFF_K1 : OFF_K0) + klane;
        const uint32_t vbase = sb + (buf ? OFF_V1 : OFF_V0) + vlane;

        // ---- fused per-s-block, K-frag software pipelined
        uint32_t kf0, kf1, kf2, kf3;
        ldm4(kf0, kf1, kf2, kf3, kbase);
        #pragma unroll
        for (int s = 0; s < 8; s++) {
            float sc0[4] = {0.f, 0.f, 0.f, 0.f};
            float sc1[4] = {0.f, 0.f, 0.f, 0.f};
            mma_bf16(sc0, qa[0], qa[1], qa[2], qa[3], kf0, kf1);
            mma_bf16(sc1, qa[0], qa[1], qa[2], qa[3], kf2, kf3);
            if (s < 7) ldm4(kf0, kf1, kf2, kf3, kbase + (uint32_t)((s + 1) * 512));
            uint32_t a0 = bf2(ex2f(sc0[1]), ex2f(sc0[0]));
            uint32_t a1 = bf2(ex2f(sc0[3]), ex2f(sc0[2]));
            uint32_t a2 = bf2(ex2f(sc1[1]), ex2f(sc1[0]));
            uint32_t a3 = bf2(ex2f(sc1[3]), ex2f(sc1[2]));
            mma_bf16(ls, a0, a1, a2, a3, ONES2, ONES2);
            #pragma unroll
            for (int nbp = 0; nbp < 8; nbp++) {
                uint32_t r0, r1, r2, r3;
                ldm4(r0, r1, r2, r3, vbase + (uint32_t)(nbp * 4352 + s * 32));
                mma_bf16(o[2*nbp],     a0, a1, a2, a3, r0, r1);
                mma_bf16(o[2*nbp + 1], a0, a1, a2, a3, r2, r3);
            }
        }
        __syncthreads();
    }

    const float il0 = 1.f / ls[0], il1 = 1.f / ls[2];

    uint32_t oa0[16], oa1[16];
    #pragma unroll
    for (int nb = 0; nb < 16; nb++) {
        oa0[nb] = bf2(o[nb][1] * il0, o[nb][0] * il0);
        oa1[nb] = bf2(o[nb][3] * il1, o[nb][2] * il1);
    }

    CP_WAIT0();
    __syncthreads();

    float pr[16][4];
    #pragma unroll
    for (int nb = 0; nb < 16; nb++)
        #pragma unroll
        for (int i = 0; i < 4; i++) pr[nb][i] = 0.f;
    const uint32_t pwbase = sb + OFF_V0 + vlane;
    #pragma unroll
    for (int s = 0; s < 8; s++) {
        const uint32_t a0 = oa0[2*s], a1 = oa1[2*s];
        const uint32_t a2 = oa0[2*s+1], a3 = oa1[2*s+1];
        #pragma unroll
        for (int nbp = 0; nbp < 8; nbp++) {
            uint32_t r0, r1, r2, r3;
            ldm4(r0, r1, r2, r3, pwbase + (uint32_t)(nbp * 4352 + s * 32));
            mma_bf16(pr[2*nbp],     a0, a1, a2, a3, r0, r1);
            mma_bf16(pr[2*nbp + 1], a0, a1, a2, a3, r2, r3);
        }
    }
    __syncthreads();

    float* stg = (float*)(sm + OFF_STG);
    #pragma unroll
    for (int nb = 0; nb < 16; nb++) {
        int e = 8*nb + 2*t;
        stg[(e    ) * 132 + 16*w + g    ] = pr[nb][0];
        stg[(e + 1) * 132 + 16*w + g    ] = pr[nb][1];
        stg[(e    ) * 132 + 16*w + g + 8] = pr[nb][2];
        stg[(e + 1) * 132 + 16*w + g + 8] = pr[nb][3];
    }
    __syncthreads();

    #pragma unroll
    for (int it = 0; it < 16; it++) {
        int idx = tid + it * 256;
        int e = idx >> 5, qq = idx & 31;
        float4 v4 = *(float4*)&stg[e * 132 + qq * 4];
        float bias = __ldg(pb + e);
        size_t gi = ((size_t)b * C + e) * NN + q0 + qq * 4;
        float4 xr = *(const float4*)&x[gi];
        v4.x += bias + xr.x; v4.y += bias + xr.y;
        v4.z += bias + xr.z; v4.w += bias + xr.w;
        *(float4*)&out[gi] = v4;
    }
}

// ---------------- launch -----------------------------------------------------
extern "C" void kernel_launch(void* const* d_in, const int* in_sizes, int n_in,
                              void* d_out, int out_size)
{
    const float* x    = (const float*)d_in[0];
    const float* gn_w = (const float*)d_in[1];
    const float* gn_b = (const float*)d_in[2];
    const float* q_w  = (const float*)d_in[3];
    const float* q_b  = (const float*)d_in[4];
    const float* k_w  = (const float*)d_in[5];
    const float* k_b  = (const float*)d_in[6];
    const float* v_w  = (const float*)d_in[7];
    const float* v_b  = (const float*)d_in[8];
    const float* p_w  = (const float*)d_in[9];
    const float* p_b  = (const float*)d_in[10];
    float* out = (float*)d_out;

    float* st;
    __nv_bfloat16 *qt, *kt, *v, *pwb;
    cudaGetSymbolAddress((void**)&qt,  g_qt);
    cudaGetSymbolAddress((void**)&kt,  g_kt);
    cudaGetSymbolAddress((void**)&v,   g_v);
    cudaGetSymbolAddress((void**)&pwb, g_pwb);
    cudaGetSymbolAddress((void**)&st,  g_st);

    cudaFuncSetAttribute(flash_mma_kernel,
                         cudaFuncAttributeMaxDynamicSharedMemorySize, SMEM_FL);
    cudaFuncSetAttribute(qkv_proj_kernel,
                         cudaFuncAttributeMaxDynamicSharedMemorySize, SMEM_PJ);

    gn_stats_kernel<<<BATCH * G, 256>>>(x, st, p_w, pwb);

    qkv_proj_kernel<<<dim3(NN / 128, BATCH), 256, SMEM_PJ>>>(
        q_w, q_b, k_w, k_b, v_w, v_b, gn_w, gn_b, st, x, qt, kt, v);

    flash_mma_kernel<<<BATCH * 32, 256, SMEM_FL>>>(qt, kt, v, pwb, p_b, x, out);
}

// round 13
// speedup vs baseline: 1.4584x; 1.0046x over previous
#include <cuda_runtime.h>
#include <cuda_bf16.h>
#include <cstdint>
#include <math.h>

#define BATCH 8
#define C 128
#define NN 4096
#define D 16
#define G 32
#define CPG (C / G)
#define EPS 1e-5f
#define SCALE_Q 0.36067376022224085f   // 0.25 * log2(e)

// ---------------- scratch ----------------------------------------------------
__device__ __nv_bfloat16  g_qt [BATCH * NN * D];   // q [B,N,16] bf16, pre-scaled
__device__ __nv_bfloat16  g_kt [BATCH * NN * D];   // k [B,N,16] bf16
__device__ __nv_bfloat16  g_v  [BATCH * C * NN];   // v [B,C,N] bf16
__device__ __nv_bfloat16  g_pwb[C * C];            // p_w bf16 [e][c]
__device__ float          g_st [BATCH * G * 2];    // groupnorm (mean, rstd)

// ---------------- GroupNorm stats (+ p_w bf16 convert piggyback) -------------
__global__ __launch_bounds__(256) void gn_stats_kernel(
    const float* __restrict__ x, float* __restrict__ st,
    const float* __restrict__ pw, __nv_bfloat16* __restrict__ pwb)
{
    const int b = blockIdx.x >> 5;
    const int g = blockIdx.x & 31;
    const float* xp = x + ((size_t)b * C + g * CPG) * NN;

    if (threadIdx.x < 64) {   // 256 blocks x 64 = 16384 = C*C
        int i = blockIdx.x * 64 + threadIdx.x;
        pwb[i] = __float2bfloat16_rn(pw[i]);
    }

    const int TOT = CPG * NN;
    float s = 0.f, s2 = 0.f;
    for (int idx = threadIdx.x; idx < TOT; idx += 256) {
        float v = xp[idx];
        s += v; s2 += v * v;
    }
    __shared__ float red[16];
    int lane = threadIdx.x & 31, wid = threadIdx.x >> 5;
    #pragma unroll
    for (int o = 16; o > 0; o >>= 1) {
        s  += __shfl_xor_sync(0xffffffffu, s,  o);
        s2 += __shfl_xor_sync(0xffffffffu, s2, o);
    }
    if (lane == 0) { red[wid] = s; red[8 + wid] = s2; }
    __syncthreads();
    if (wid == 0) {
        float a = (lane < 8) ? red[lane] : 0.f;
        float a2 = (lane < 8) ? red[8 + lane] : 0.f;
        #pragma unroll
        for (int o = 4; o > 0; o >>= 1) {
            a  += __shfl_xor_sync(0xffffffffu, a,  o);
            a2 += __shfl_xor_sync(0xffffffffu, a2, o);
        }
        if (lane == 0) {
            const float inv_n = 1.f / (float)TOT;
            float mean = a * inv_n;
            float var = a2 * inv_n - mean * mean;
            st[blockIdx.x * 2]     = mean;
            st[blockIdx.x * 2 + 1] = rsqrtf(var + EPS);
        }
    }
}

// ---------------- mma helpers ------------------------------------------------
__device__ __forceinline__ uint32_t smem_u32(const void* p) {
    uint32_t a;
    asm("{ .reg .u64 t; cvta.to.shared.u64 t, %1; cvt.u32.u64 %0, t; }" : "=r"(a) : "l"(p));
    return a;
}
__device__ __forceinline__ void cpa16(uint32_t s, const void* g) {
    asm volatile("cp.async.cg.shared.global [%0], [%1], 16;" :: "r"(s), "l"(g));
}
#define CP_COMMIT() asm volatile("cp.async.commit_group;" ::: "memory")
#define CP_WAIT1()  asm volatile("cp.async.wait_group 1;" ::: "memory")
#define CP_WAIT0()  asm volatile("cp.async.wait_group 0;" ::: "memory")

__device__ __forceinline__ float ex2f(float f) {
    float r; asm("ex2.approx.f32 %0, %1;" : "=f"(r) : "f"(f)); return r;
}
__device__ __forceinline__ uint32_t bf2(float hi, float lo) {
    uint32_t r; asm("cvt.rn.bf16x2.f32 %0, %1, %2;" : "=r"(r) : "f"(hi), "f"(lo)); return r;
}
__device__ __forceinline__ void mma_bf16(float* c, uint32_t a0, uint32_t a1,
                                         uint32_t a2, uint32_t a3,
                                         uint32_t b0, uint32_t b1) {
    asm volatile(
        "mma.sync.aligned.m16n8k16.row.col.f32.bf16.bf16.f32 "
        "{%0,%1,%2,%3},{%4,%5,%6,%7},{%8,%9},{%0,%1,%2,%3};"
        : "+f"(c[0]), "+f"(c[1]), "+f"(c[2]), "+f"(c[3])
        : "r"(a0), "r"(a1), "r"(a2), "r"(a3), "r"(b0), "r"(b1));
}
__device__ __forceinline__ void ldm4(uint32_t& r0, uint32_t& r1, uint32_t& r2,
                                     uint32_t& r3, uint32_t addr) {
    asm volatile("ldmatrix.sync.aligned.m8n8.x4.shared.b16 {%0,%1,%2,%3}, [%4];"
                 : "=r"(r0), "=r"(r1), "=r"(r2), "=r"(r3) : "r"(addr));
}

// ============================================================================
//   fused GN + QKV projection (bf16 mma, 2 CTAs/SM)
// ============================================================================
#define PJ_HT   0                  // 34816
#define PJ_WS   34816              // 43520 (vstage overlay in epilogue)
#define PJ_BIAS 78336              // 640
#define PJ_SC   79104              // 1024
#define SMEM_PJ 80128

__global__ __launch_bounds__(256, 2) void qkv_proj_kernel(
    const float* __restrict__ qw, const float* __restrict__ qb,
    const float* __restrict__ kw, const float* __restrict__ kb,
    const float* __restrict__ vw, const float* __restrict__ vb,
    const float* __restrict__ gnw, const float* __restrict__ gnb,
    const float* __restrict__ st, const float* __restrict__ x,
    __nv_bfloat16* __restrict__ qt, __nv_bfloat16* __restrict__ kt,
    __nv_bfloat16* __restrict__ vout)
{
    extern __shared__ char sm[];
    uint32_t* hT = (uint32_t*)(sm + PJ_HT);    // [n][68] bf16x2 of (2c,2c+1)
    uint32_t* Ws = (uint32_t*)(sm + PJ_WS);    // [e][68] bf16x2
    float* bs = (float*)(sm + PJ_BIAS);
    float* sc = (float*)(sm + PJ_SC);
    float* sh = sc + 128;
    const int tid = threadIdx.x;
    const int w = tid >> 5, lane = tid & 31;
    const int g = lane >> 2, t = lane & 3;
    const int n0 = blockIdx.x * 128;
    const int b = blockIdx.y;

    if (tid < 128) {
        float mean = st[(b * G + (tid >> 2)) * 2];
        float inv  = st[(b * G + (tid >> 2)) * 2 + 1];
        float s = gnw[tid] * inv;
        sc[tid] = s;
        sh[tid] = gnb[tid] - mean * s;
    }
    for (int u = tid; u < 160 * 64; u += 256) {
        int e = u >> 6, c2 = u & 63;
        const float* wsrc;
        if (e < 16)      wsrc = qw + e * C;
        else if (e < 32) wsrc = kw + (e - 16) * C;
        else             wsrc = vw + (e - 32) * C;
        Ws[e * 68 + c2] = bf2(wsrc[2 * c2 + 1], wsrc[2 * c2]);
    }
    if (tid < 160) {
        float bv;
        if (tid < 16)      bv = qb[tid];
        else if (tid < 32) bv = kb[tid - 16];
        else               bv = vb[tid - 32];
        bs[tid] = bv;
    }
    __syncthreads();

    for (int u = tid; u < 128 * 64; u += 256) {
        int n = u & 127, c2 = u >> 7;
        float h0 = fmaf(x[((size_t)b * C + 2 * c2)     * NN + n0 + n], sc[2 * c2],     sh[2 * c2]);
        float h1 = fmaf(x[((size_t)b * C + 2 * c2 + 1) * NN + n0 + n], sc[2 * c2 + 1], sh[2 * c2 + 1]);
        hT[n * 68 + c2] = bf2(h1, h0);
    }
    __syncthreads();

    float pr[20][4];
    #pragma unroll
    for (int nb = 0; nb < 20; nb++)
        #pragma unroll
        for (int i = 0; i < 4; i++) pr[nb][i] = 0.f;

    #pragma unroll
    for (int kc = 0; kc < 8; kc++) {
        uint32_t a0 = hT[(16 * w + g    ) * 68 + 8 * kc + t    ];
        uint32_t a1 = hT[(16 * w + g + 8) * 68 + 8 * kc + t    ];
        uint32_t a2 = hT[(16 * w + g    ) * 68 + 8 * kc + t + 4];
        uint32_t a3 = hT[(16 * w + g + 8) * 68 + 8 * kc + t + 4];
        #pragma unroll
        for (int nb = 0; nb < 20; nb++) {
            uint32_t b0 = Ws[(8 * nb + g) * 68 + 8 * kc + t    ];
            uint32_t b1 = Ws[(8 * nb + g) * 68 + 8 * kc + t + 4];
            mma_bf16(pr[nb], a0, a1, a2, a3, b0, b1);
        }
    }

    const int r0 = 16 * w + g, r1 = r0 + 8;
    #pragma unroll
    for (int nb = 0; nb < 4; nb++) {
        int e = 8 * nb + 2 * t;
        float b0 = bs[e], b1 = bs[e + 1];
        if (e < 16) {
            *(uint32_t*)&qt[((size_t)b * NN + n0 + r0) * D + e] =
                bf2((pr[nb][1] + b1) * SCALE_Q, (pr[nb][0] + b0) * SCALE_Q);
            *(uint32_t*)&qt[((size_t)b * NN + n0 + r1) * D + e] =
                bf2((pr[nb][3] + b1) * SCALE_Q, (pr[nb][2] + b0) * SCALE_Q);
        } else {
            int E = e - 16;
            *(uint32_t*)&kt[((size_t)b * NN + n0 + r0) * D + E] =
                bf2(pr[nb][1] + b1, pr[nb][0] + b0);
            *(uint32_t*)&kt[((size_t)b * NN + n0 + r1) * D + E] =
                bf2(pr[nb][3] + b1, pr[nb][2] + b0);
        }
    }
    __syncthreads();

    __nv_bfloat16* vstage = (__nv_bfloat16*)(sm + PJ_WS);
    #pragma unroll
    for (int nb = 4; nb < 20; nb++) {
        int e = 8 * nb + 2 * t;
        int cv = e - 32;
        float b0 = bs[e], b1 = bs[e + 1];
        vstage[(cv    ) * 132 + r0] = __float2bfloat16_rn(pr[nb][0] + b0);
        vstage[(cv + 1) * 132 + r0] = __float2bfloat16_rn(pr[nb][1] + b1);
        vstage[(cv    ) * 132 + r1] = __float2bfloat16_rn(pr[nb][2] + b0);
        vstage[(cv + 1) * 132 + r1] = __float2bfloat16_rn(pr[nb][3] + b1);
    }
    __syncthreads();
    for (int u = tid; u < 128 * 32; u += 256) {
        int c = u >> 5, nc = u & 31;
        *(uint64_t*)&vout[((size_t)b * C + c) * NN + n0 + nc * 4] =
            *(const uint64_t*)&vstage[c * 132 + nc * 4];
    }
}

// ============================================================================
//   flash attention: bf16 S/PV, pipelined ldmatrix (K and V), ones-mma rowsums
// ============================================================================
#define OFF_Q   0        // bf16 [128][16]  4096
#define OFF_K0  4096
#define OFF_K1  8192
#define OFF_V0  12288    // bf16 [128][136] 34816 (pw overlay at tt==31)
#define OFF_V1  47104
#define OFF_STG 0        // f32 [128][132] 67584 (post-proj overlay)
#define SMEM_FL 81920

__device__ __forceinline__ void issue_tile(uint32_t sb, int buf,
    const __nv_bfloat16* __restrict__ kt, const __nv_bfloat16* __restrict__ vb,
    int b, int j0, int tid)
{
    uint32_t kdst = sb + (buf ? OFF_K1 : OFF_K0);
    {
        int row = tid >> 1, cc = tid & 1;
        cpa16(kdst + row * 32 + cc * 16,
              kt + ((size_t)(b * NN + j0 + row)) * D + cc * 8);
    }
    uint32_t vdst = sb + (buf ? OFF_V1 : OFF_V0);
    #pragma unroll
    for (int u = tid; u < 2048; u += 256) {
        int c = u >> 4, cc = u & 15;
        cpa16(vdst + c * 272 + cc * 16,
              vb + ((size_t)(b * C + c)) * NN + j0 + cc * 8);
    }
}

__global__ __launch_bounds__(256, 2) void flash_mma_kernel(
    const __nv_bfloat16* __restrict__ qt, const __nv_bfloat16* __restrict__ kt,
    const __nv_bfloat16* __restrict__ vb, const __nv_bfloat16* __restrict__ pwb,
    const float* __restrict__ pb, const float* __restrict__ x,
    float* __restrict__ out)
{
    extern __shared__ char sm[];
    const uint32_t sb = smem_u32(sm);
    const int tid = threadIdx.x;
    const int w = tid >> 5;
    const int lane = tid & 31;
    const int g = lane >> 2, t = lane & 3;
    const int b = blockIdx.x >> 5;
    const int q0 = (blockIdx.x & 31) * 128;

    const int rowsel = (lane & 7) + ((lane >> 4) << 3);
    const int ksel = (lane >> 3) & 1;
    const uint32_t vlane = (uint32_t)(rowsel * 272 + ksel * 16);
    const uint32_t klane = (uint32_t)(rowsel * 32 + ksel * 16);
    const uint32_t qlane = (uint32_t)(
        (16 * w + (lane & 7) + (((lane >> 3) & 1) << 3)) * 32 + ((lane >> 4) & 1) * 16);

    {
        int row = tid >> 1, cc = tid & 1;
        cpa16(sb + OFF_Q + row * 32 + cc * 16,
              qt + ((size_t)(b * NN + q0 + row)) * D + cc * 8);
    }
    issue_tile(sb, 0, kt, vb, b, 0, tid);
    CP_COMMIT();

    uint32_t qa[4];
    float o[16][4];
    #pragma unroll
    for (int nb = 0; nb < 16; nb++)
        #pragma unroll
        for (int i = 0; i < 4; i++) o[nb][i] = 0.f;
    float ls[4] = {0.f, 0.f, 0.f, 0.f};
    const uint32_t ONES2 = 0x3F803F80u;

    for (int tt = 0; tt < 32; tt++) {
        const int buf = tt & 1;
        if (tt < 31) {
            issue_tile(sb, buf ^ 1, kt, vb, b, (tt + 1) * 128, tid);
            CP_COMMIT();
            CP_WAIT1();
        } else {
            CP_WAIT0();
        }
        __syncthreads();

        if (tt == 0) {
            ldm4(qa[0], qa[1], qa[2], qa[3], sb + OFF_Q + qlane);
        }
        if (tt == 31) {
            #pragma unroll
            for (int u = tid; u < 2048; u += 256) {
                int row = u >> 4, cc = u & 15;
                cpa16(sb + OFF_V0 + row * 272 + cc * 16, pwb + row * C + cc * 8);
            }
            CP_COMMIT();
        }

        const uint32_t kbase = sb + (buf ? OFF_K1 : OFF_K0) + klane;
        const uint32_t vbase = sb + (buf ? OFF_V1 : OFF_V0) + vlane;

        // ---- fused per-s-block, K-frag and V-frag software pipelined
        uint32_t kf0, kf1, kf2, kf3;
        ldm4(kf0, kf1, kf2, kf3, kbase);
        #pragma unroll
        for (int s = 0; s < 8; s++) {
            float sc0[4] = {0.f, 0.f, 0.f, 0.f};
            float sc1[4] = {0.f, 0.f, 0.f, 0.f};
            mma_bf16(sc0, qa[0], qa[1], qa[2], qa[3], kf0, kf1);
            mma_bf16(sc1, qa[0], qa[1], qa[2], qa[3], kf2, kf3);
            if (s < 7) ldm4(kf0, kf1, kf2, kf3, kbase + (uint32_t)((s + 1) * 512));
            uint32_t a0 = bf2(ex2f(sc0[1]), ex2f(sc0[0]));
            uint32_t a1 = bf2(ex2f(sc0[3]), ex2f(sc0[2]));
            uint32_t a2 = bf2(ex2f(sc1[1]), ex2f(sc1[0]));
            uint32_t a3 = bf2(ex2f(sc1[3]), ex2f(sc1[2]));
            mma_bf16(ls, a0, a1, a2, a3, ONES2, ONES2);
            // V-frag pipeline: prefetch nbp+1 before mma of nbp
            uint32_t r0, r1, r2, r3;
            ldm4(r0, r1, r2, r3, vbase + (uint32_t)(s * 32));
            #pragma unroll
            for (int nbp = 0; nbp < 8; nbp++) {
                uint32_t n0r = r0, n1r = r1, n2r = r2, n3r = r3;
                if (nbp < 7)
                    ldm4(r0, r1, r2, r3, vbase + (uint32_t)((nbp + 1) * 4352 + s * 32));
                mma_bf16(o[2*nbp],     a0, a1, a2, a3, n0r, n1r);
                mma_bf16(o[2*nbp + 1], a0, a1, a2, a3, n2r, n3r);
            }
        }
        __syncthreads();
    }

    const float il0 = 1.f / ls[0], il1 = 1.f / ls[2];

    uint32_t oa0[16], oa1[16];
    #pragma unroll
    for (int nb = 0; nb < 16; nb++) {
        oa0[nb] = bf2(o[nb][1] * il0, o[nb][0] * il0);
        oa1[nb] = bf2(o[nb][3] * il1, o[nb][2] * il1);
    }

    CP_WAIT0();
    __syncthreads();

    float pr[16][4];
    #pragma unroll
    for (int nb = 0; nb < 16; nb++)
        #pragma unroll
        for (int i = 0; i < 4; i++) pr[nb][i] = 0.f;
    const uint32_t pwbase = sb + OFF_V0 + vlane;
    #pragma unroll
    for (int s = 0; s < 8; s++) {
        const uint32_t a0 = oa0[2*s], a1 = oa1[2*s];
        const uint32_t a2 = oa0[2*s+1], a3 = oa1[2*s+1];
        uint32_t r0, r1, r2, r3;
        ldm4(r0, r1, r2, r3, pwbase + (uint32_t)(s * 32));
        #pragma unroll
        for (int nbp = 0; nbp < 8; nbp++) {
            uint32_t n0r = r0, n1r = r1, n2r = r2, n3r = r3;
            if (nbp < 7)
                ldm4(r0, r1, r2, r3, pwbase + (uint32_t)((nbp + 1) * 4352 + s * 32));
            mma_bf16(pr[2*nbp],     a0, a1, a2, a3, n0r, n1r);
            mma_bf16(pr[2*nbp + 1], a0, a1, a2, a3, n2r, n3r);
        }
    }
    __syncthreads();

    float* stg = (float*)(sm + OFF_STG);
    #pragma unroll
    for (int nb = 0; nb < 16; nb++) {
        int e = 8*nb + 2*t;
        stg[(e    ) * 132 + 16*w + g    ] = pr[nb][0];
        stg[(e + 1) * 132 + 16*w + g    ] = pr[nb][1];
        stg[(e    ) * 132 + 16*w + g + 8] = pr[nb][2];
        stg[(e + 1) * 132 + 16*w + g + 8] = pr[nb][3];
    }
    __syncthreads();

    #pragma unroll
    for (int it = 0; it < 16; it++) {
        int idx = tid + it * 256;
        int e = idx >> 5, qq = idx & 31;
        float4 v4 = *(float4*)&stg[e * 132 + qq * 4];
        float bias = __ldg(pb + e);
        size_t gi = ((size_t)b * C + e) * NN + q0 + qq * 4;
        float4 xr = *(const float4*)&x[gi];
        v4.x += bias + xr.x; v4.y += bias + xr.y;
        v4.z += bias + xr.z; v4.w += bias + xr.w;
        *(float4*)&out[gi] = v4;
    }
}

// ---------------- launch -----------------------------------------------------
extern "C" void kernel_launch(void* const* d_in, const int* in_sizes, int n_in,
                              void* d_out, int out_size)
{
    const float* x    = (const float*)d_in[0];
    const float* gn_w = (const float*)d_in[1];
    const float* gn_b = (const float*)d_in[2];
    const float* q_w  = (const float*)d_in[3];
    const float* q_b  = (const float*)d_in[4];
    const float* k_w  = (const float*)d_in[5];
    const float* k_b  = (const float*)d_in[6];
    const float* v_w  = (const float*)d_in[7];
    const float* v_b  = (const float*)d_in[8];
    const float* p_w  = (const float*)d_in[9];
    const float* p_b  = (const float*)d_in[10];
    float* out = (float*)d_out;

    float* st;
    __nv_bfloat16 *qt, *kt, *v, *pwb;
    cudaGetSymbolAddress((void**)&qt,  g_qt);
    cudaGetSymbolAddress((void**)&kt,  g_kt);
    cudaGetSymbolAddress((void**)&v,   g_v);
    cudaGetSymbolAddress((void**)&pwb, g_pwb);
    cudaGetSymbolAddress((void**)&st,  g_st);

    cudaFuncSetAttribute(flash_mma_kernel,
                         cudaFuncAttributeMaxDynamicSharedMemorySize, SMEM_FL);
    cudaFuncSetAttribute(qkv_proj_kernel,
                         cudaFuncAttributeMaxDynamicSharedMemorySize, SMEM_PJ);

    gn_stats_kernel<<<BATCH * G, 256>>>(x, st, p_w, pwb);

    qkv_proj_kernel<<<dim3(NN / 128, BATCH), 256, SMEM_PJ>>>(
        q_w, q_b, k_w, k_b, v_w, v_b, gn_w, gn_b, st, x, qt, kt, v);

    flash_mma_kernel<<<BATCH * 32, 256, SMEM_FL>>>(qt, kt, v, pwb, p_b, x, out);
}

// round 14
// speedup vs baseline: 1.4739x; 1.0106x over previous
#include <cuda_runtime.h>
#include <cuda_bf16.h>
#include <cstdint>
#include <math.h>

#define BATCH 8
#define C 128
#define NN 4096
#define D 16
#define G 32
#define CPG (C / G)
#define EPS 1e-5f
#define SCALE_Q 0.36067376022224085f   // 0.25 * log2(e)

// ---------------- scratch ----------------------------------------------------
__device__ __nv_bfloat16  g_qt [BATCH * NN * D];   // q [B,N,16] bf16, pre-scaled
__device__ __nv_bfloat16  g_kt [BATCH * NN * D];   // k [B,N,16] bf16
__device__ __nv_bfloat16  g_v  [BATCH * C * NN];   // v [B,C,N] bf16
__device__ __nv_bfloat16  g_pwb[C * C];            // p_w bf16 [e][c]
__device__ float          g_st [BATCH * G * 2];    // groupnorm (mean, rstd)

// ---------------- GroupNorm stats (+ p_w bf16 convert piggyback) -------------
__global__ __launch_bounds__(256) void gn_stats_kernel(
    const float* __restrict__ x, float* __restrict__ st,
    const float* __restrict__ pw, __nv_bfloat16* __restrict__ pwb)
{
    const int b = blockIdx.x >> 5;
    const int g = blockIdx.x & 31;
    const float* xp = x + ((size_t)b * C + g * CPG) * NN;

    if (threadIdx.x < 64) {   // 256 blocks x 64 = 16384 = C*C
        int i = blockIdx.x * 64 + threadIdx.x;
        pwb[i] = __float2bfloat16_rn(pw[i]);
    }

    const int TOT = CPG * NN;
    float s = 0.f, s2 = 0.f;
    for (int idx = threadIdx.x; idx < TOT; idx += 256) {
        float v = xp[idx];
        s += v; s2 += v * v;
    }
    __shared__ float red[16];
    int lane = threadIdx.x & 31, wid = threadIdx.x >> 5;
    #pragma unroll
    for (int o = 16; o > 0; o >>= 1) {
        s  += __shfl_xor_sync(0xffffffffu, s,  o);
        s2 += __shfl_xor_sync(0xffffffffu, s2, o);
    }
    if (lane == 0) { red[wid] = s; red[8 + wid] = s2; }
    __syncthreads();
    if (wid == 0) {
        float a = (lane < 8) ? red[lane] : 0.f;
        float a2 = (lane < 8) ? red[8 + lane] : 0.f;
        #pragma unroll
        for (int o = 4; o > 0; o >>= 1) {
            a  += __shfl_xor_sync(0xffffffffu, a,  o);
            a2 += __shfl_xor_sync(0xffffffffu, a2, o);
        }
        if (lane == 0) {
            const float inv_n = 1.f / (float)TOT;
            float mean = a * inv_n;
            float var = a2 * inv_n - mean * mean;
            st[blockIdx.x * 2]     = mean;
            st[blockIdx.x * 2 + 1] = rsqrtf(var + EPS);
        }
    }
}

// ---------------- mma helpers ------------------------------------------------
__device__ __forceinline__ uint32_t smem_u32(const void* p) {
    uint32_t a;
    asm("{ .reg .u64 t; cvta.to.shared.u64 t, %1; cvt.u32.u64 %0, t; }" : "=r"(a) : "l"(p));
    return a;
}
__device__ __forceinline__ void cpa16(uint32_t s, const void* g) {
    asm volatile("cp.async.cg.shared.global [%0], [%1], 16;" :: "r"(s), "l"(g));
}
#define CP_COMMIT() asm volatile("cp.async.commit_group;" ::: "memory")
#define CP_WAIT1()  asm volatile("cp.async.wait_group 1;" ::: "memory")
#define CP_WAIT0()  asm volatile("cp.async.wait_group 0;" ::: "memory")

__device__ __forceinline__ float ex2f(float f) {
    float r; asm("ex2.approx.f32 %0, %1;" : "=f"(r) : "f"(f)); return r;
}
__device__ __forceinline__ uint32_t bf2(float hi, float lo) {
    uint32_t r; asm("cvt.rn.bf16x2.f32 %0, %1, %2;" : "=r"(r) : "f"(hi), "f"(lo)); return r;
}
__device__ __forceinline__ void mma_bf16(float* c, uint32_t a0, uint32_t a1,
                                         uint32_t a2, uint32_t a3,
                                         uint32_t b0, uint32_t b1) {
    asm volatile(
        "mma.sync.aligned.m16n8k16.row.col.f32.bf16.bf16.f32 "
        "{%0,%1,%2,%3},{%4,%5,%6,%7},{%8,%9},{%0,%1,%2,%3};"
        : "+f"(c[0]), "+f"(c[1]), "+f"(c[2]), "+f"(c[3])
        : "r"(a0), "r"(a1), "r"(a2), "r"(a3), "r"(b0), "r"(b1));
}
__device__ __forceinline__ void ldm4(uint32_t& r0, uint32_t& r1, uint32_t& r2,
                                     uint32_t& r3, uint32_t addr) {
    asm volatile("ldmatrix.sync.aligned.m8n8.x4.shared.b16 {%0,%1,%2,%3}, [%4];"
                 : "=r"(r0), "=r"(r1), "=r"(r2), "=r"(r3) : "r"(addr));
}

// ============================================================================
//   fused GN + QKV projection (bf16 mma, 2 CTAs/SM)
// ============================================================================
#define PJ_HT   0                  // 34816
#define PJ_WS   34816              // 43520 (vstage overlay in epilogue)
#define PJ_BIAS 78336              // 640
#define PJ_SC   79104              // 1024
#define SMEM_PJ 80128

__global__ __launch_bounds__(256, 2) void qkv_proj_kernel(
    const float* __restrict__ qw, const float* __restrict__ qb,
    const float* __restrict__ kw, const float* __restrict__ kb,
    const float* __restrict__ vw, const float* __restrict__ vb,
    const float* __restrict__ gnw, const float* __restrict__ gnb,
    const float* __restrict__ st, const float* __restrict__ x,
    __nv_bfloat16* __restrict__ qt, __nv_bfloat16* __restrict__ kt,
    __nv_bfloat16* __restrict__ vout)
{
    extern __shared__ char sm[];
    uint32_t* hT = (uint32_t*)(sm + PJ_HT);    // [n][68] bf16x2 of (2c,2c+1)
    uint32_t* Ws = (uint32_t*)(sm + PJ_WS);    // [e][68] bf16x2
    float* bs = (float*)(sm + PJ_BIAS);
    float* sc = (float*)(sm + PJ_SC);
    float* sh = sc + 128;
    const int tid = threadIdx.x;
    const int w = tid >> 5, lane = tid & 31;
    const int g = lane >> 2, t = lane & 3;
    const int n0 = blockIdx.x * 128;
    const int b = blockIdx.y;

    if (tid < 128) {
        float mean = st[(b * G + (tid >> 2)) * 2];
        float inv  = st[(b * G + (tid >> 2)) * 2 + 1];
        float s = gnw[tid] * inv;
        sc[tid] = s;
        sh[tid] = gnb[tid] - mean * s;
    }
    for (int u = tid; u < 160 * 64; u += 256) {
        int e = u >> 6, c2 = u & 63;
        const float* wsrc;
        if (e < 16)      wsrc = qw + e * C;
        else if (e < 32) wsrc = kw + (e - 16) * C;
        else             wsrc = vw + (e - 32) * C;
        Ws[e * 68 + c2] = bf2(wsrc[2 * c2 + 1], wsrc[2 * c2]);
    }
    if (tid < 160) {
        float bv;
        if (tid < 16)      bv = qb[tid];
        else if (tid < 32) bv = kb[tid - 16];
        else               bv = vb[tid - 32];
        bs[tid] = bv;
    }
    __syncthreads();

    for (int u = tid; u < 128 * 64; u += 256) {
        int n = u & 127, c2 = u >> 7;
        float h0 = fmaf(x[((size_t)b * C + 2 * c2)     * NN + n0 + n], sc[2 * c2],     sh[2 * c2]);
        float h1 = fmaf(x[((size_t)b * C + 2 * c2 + 1) * NN + n0 + n], sc[2 * c2 + 1], sh[2 * c2 + 1]);
        hT[n * 68 + c2] = bf2(h1, h0);
    }
    __syncthreads();

    float pr[20][4];
    #pragma unroll
    for (int nb = 0; nb < 20; nb++)
        #pragma unroll
        for (int i = 0; i < 4; i++) pr[nb][i] = 0.f;

    #pragma unroll
    for (int kc = 0; kc < 8; kc++) {
        uint32_t a0 = hT[(16 * w + g    ) * 68 + 8 * kc + t    ];
        uint32_t a1 = hT[(16 * w + g + 8) * 68 + 8 * kc + t    ];
        uint32_t a2 = hT[(16 * w + g    ) * 68 + 8 * kc + t + 4];
        uint32_t a3 = hT[(16 * w + g + 8) * 68 + 8 * kc + t + 4];
        #pragma unroll
        for (int nb = 0; nb < 20; nb++) {
            uint32_t b0 = Ws[(8 * nb + g) * 68 + 8 * kc + t    ];
            uint32_t b1 = Ws[(8 * nb + g) * 68 + 8 * kc + t + 4];
            mma_bf16(pr[nb], a0, a1, a2, a3, b0, b1);
        }
    }

    const int r0 = 16 * w + g, r1 = r0 + 8;
    #pragma unroll
    for (int nb = 0; nb < 4; nb++) {
        int e = 8 * nb + 2 * t;
        float b0 = bs[e], b1 = bs[e + 1];
        if (e < 16) {
            *(uint32_t*)&qt[((size_t)b * NN + n0 + r0) * D + e] =
                bf2((pr[nb][1] + b1) * SCALE_Q, (pr[nb][0] + b0) * SCALE_Q);
            *(uint32_t*)&qt[((size_t)b * NN + n0 + r1) * D + e] =
                bf2((pr[nb][3] + b1) * SCALE_Q, (pr[nb][2] + b0) * SCALE_Q);
        } else {
            int E = e - 16;
            *(uint32_t*)&kt[((size_t)b * NN + n0 + r0) * D + E] =
                bf2(pr[nb][1] + b1, pr[nb][0] + b0);
            *(uint32_t*)&kt[((size_t)b * NN + n0 + r1) * D + E] =
                bf2(pr[nb][3] + b1, pr[nb][2] + b0);
        }
    }
    __syncthreads();

    __nv_bfloat16* vstage = (__nv_bfloat16*)(sm + PJ_WS);
    #pragma unroll
    for (int nb = 4; nb < 20; nb++) {
        int e = 8 * nb + 2 * t;
        int cv = e - 32;
        float b0 = bs[e], b1 = bs[e + 1];
        vstage[(cv    ) * 132 + r0] = __float2bfloat16_rn(pr[nb][0] + b0);
        vstage[(cv + 1) * 132 + r0] = __float2bfloat16_rn(pr[nb][1] + b1);
        vstage[(cv    ) * 132 + r1] = __float2bfloat16_rn(pr[nb][2] + b0);
        vstage[(cv + 1) * 132 + r1] = __float2bfloat16_rn(pr[nb][3] + b1);
    }
    __syncthreads();
    for (int u = tid; u < 128 * 32; u += 256) {
        int c = u >> 5, nc = u & 31;
        *(uint64_t*)&vout[((size_t)b * C + c) * NN + n0 + nc * 4] =
            *(const uint64_t*)&vstage[c * 132 + nc * 4];
    }
}

// ============================================================================
//   flash attention: bf16 S + pipelined ldmatrix K, bf16 PV, ones-mma rowsums
// ============================================================================
#define OFF_Q   0        // bf16 [128][16]  4096
#define OFF_K0  4096
#define OFF_K1  8192
#define OFF_V0  12288    // bf16 [128][136] 34816 (pw overlay at tt==31)
#define OFF_V1  47104
#define OFF_STG 0        // f32 [128][132] 67584 (post-proj overlay)
#define SMEM_FL 81920

__device__ __forceinline__ void issue_tile(uint32_t sb, int buf,
    const __nv_bfloat16* __restrict__ kt, const __nv_bfloat16* __restrict__ vb,
    int b, int j0, int tid)
{
    uint32_t kdst = sb + (buf ? OFF_K1 : OFF_K0);
    {
        int row = tid >> 1, cc = tid & 1;
        cpa16(kdst + row * 32 + cc * 16,
              kt + ((size_t)(b * NN + j0 + row)) * D + cc * 8);
    }
    uint32_t vdst = sb + (buf ? OFF_V1 : OFF_V0);
    #pragma unroll
    for (int u = tid; u < 2048; u += 256) {
        int c = u >> 4, cc = u & 15;
        cpa16(vdst + c * 272 + cc * 16,
              vb + ((size_t)(b * C + c)) * NN + j0 + cc * 8);
    }
}

__global__ __launch_bounds__(256, 2) void flash_mma_kernel(
    const __nv_bfloat16* __restrict__ qt, const __nv_bfloat16* __restrict__ kt,
    const __nv_bfloat16* __restrict__ vb, const __nv_bfloat16* __restrict__ pwb,
    const float* __restrict__ pb, const float* __restrict__ x,
    float* __restrict__ out)
{
    extern __shared__ char sm[];
    const uint32_t sb = smem_u32(sm);
    const int tid = threadIdx.x;
    const int w = tid >> 5;
    const int lane = tid & 31;
    const int g = lane >> 2, t = lane & 3;
    const int b = blockIdx.x >> 5;
    const int q0 = (blockIdx.x & 31) * 128;

    const int rowsel = (lane & 7) + ((lane >> 4) << 3);
    const int ksel = (lane >> 3) & 1;
    const uint32_t vlane = (uint32_t)(rowsel * 272 + ksel * 16);
    const uint32_t klane = (uint32_t)(rowsel * 32 + ksel * 16);
    const uint32_t qlane = (uint32_t)(
        (16 * w + (lane & 7) + (((lane >> 3) & 1) << 3)) * 32 + ((lane >> 4) & 1) * 16);

    {
        int row = tid >> 1, cc = tid & 1;
        cpa16(sb + OFF_Q + row * 32 + cc * 16,
              qt + ((size_t)(b * NN + q0 + row)) * D + cc * 8);
    }
    issue_tile(sb, 0, kt, vb, b, 0, tid);
    CP_COMMIT();

    uint32_t qa[4];
    float o[16][4];
    #pragma unroll
    for (int nb = 0; nb < 16; nb++)
        #pragma unroll
        for (int i = 0; i < 4; i++) o[nb][i] = 0.f;
    float ls[4] = {0.f, 0.f, 0.f, 0.f};
    const uint32_t ONES2 = 0x3F803F80u;

    for (int tt = 0; tt < 32; tt++) {
        const int buf = tt & 1;
        if (tt < 31) {
            issue_tile(sb, buf ^ 1, kt, vb, b, (tt + 1) * 128, tid);
            CP_COMMIT();
            CP_WAIT1();
        } else {
            CP_WAIT0();
        }
        __syncthreads();

        if (tt == 0) {
            ldm4(qa[0], qa[1], qa[2], qa[3], sb + OFF_Q + qlane);
        }
        if (tt == 31) {
            #pragma unroll
            for (int u = tid; u < 2048; u += 256) {
                int row = u >> 4, cc = u & 15;
                cpa16(sb + OFF_V0 + row * 272 + cc * 16, pwb + row * C + cc * 8);
            }
            CP_COMMIT();
        }

        const uint32_t kbase = sb + (buf ? OFF_K1 : OFF_K0) + klane;
        const uint32_t vbase = sb + (buf ? OFF_V1 : OFF_V0) + vlane;

        // ---- fused per-s-block, K-frag software pipelined
        uint32_t kf0, kf1, kf2, kf3;
        ldm4(kf0, kf1, kf2, kf3, kbase);
        #pragma unroll
        for (int s = 0; s < 8; s++) {
            float sc0[4] = {0.f, 0.f, 0.f, 0.f};
            float sc1[4] = {0.f, 0.f, 0.f, 0.f};
            mma_bf16(sc0, qa[0], qa[1], qa[2], qa[3], kf0, kf1);
            mma_bf16(sc1, qa[0], qa[1], qa[2], qa[3], kf2, kf3);
            if (s < 7) ldm4(kf0, kf1, kf2, kf3, kbase + (uint32_t)((s + 1) * 512));
            uint32_t a0 = bf2(ex2f(sc0[1]), ex2f(sc0[0]));
            uint32_t a1 = bf2(ex2f(sc0[3]), ex2f(sc0[2]));
            uint32_t a2 = bf2(ex2f(sc1[1]), ex2f(sc1[0]));
            uint32_t a3 = bf2(ex2f(sc1[3]), ex2f(sc1[2]));
            mma_bf16(ls, a0, a1, a2, a3, ONES2, ONES2);
            #pragma unroll
            for (int nbp = 0; nbp < 8; nbp++) {
                uint32_t r0, r1, r2, r3;
                ldm4(r0, r1, r2, r3, vbase + (uint32_t)(nbp * 4352 + s * 32));
                mma_bf16(o[2*nbp],     a0, a1, a2, a3, r0, r1);
                mma_bf16(o[2*nbp + 1], a0, a1, a2, a3, r2, r3);
            }
        }
        __syncthreads();
    }

    const float il0 = 1.f / ls[0], il1 = 1.f / ls[2];

    uint32_t oa0[16], oa1[16];
    #pragma unroll
    for (int nb = 0; nb < 16; nb++) {
        oa0[nb] = bf2(o[nb][1] * il0, o[nb][0] * il0);
        oa1[nb] = bf2(o[nb][3] * il1, o[nb][2] * il1);
    }

    CP_WAIT0();
    __syncthreads();

    float pr[16][4];
    #pragma unroll
    for (int nb = 0; nb < 16; nb++)
        #pragma unroll
        for (int i = 0; i < 4; i++) pr[nb][i] = 0.f;
    const uint32_t pwbase = sb + OFF_V0 + vlane;
    #pragma unroll
    for (int s = 0; s < 8; s++) {
        const uint32_t a0 = oa0[2*s], a1 = oa1[2*s];
        const uint32_t a2 = oa0[2*s+1], a3 = oa1[2*s+1];
        #pragma unroll
        for (int nbp = 0; nbp < 8; nbp++) {
            uint32_t r0, r1, r2, r3;
            ldm4(r0, r1, r2, r3, pwbase + (uint32_t)(nbp * 4352 + s * 32));
            mma_bf16(pr[2*nbp],     a0, a1, a2, a3, r0, r1);
            mma_bf16(pr[2*nbp + 1], a0, a1, a2, a3, r2, r3);
        }
    }
    __syncthreads();

    float* stg = (float*)(sm + OFF_STG);
    #pragma unroll
    for (int nb = 0; nb < 16; nb++) {
        int e = 8*nb + 2*t;
        stg[(e    ) * 132 + 16*w + g    ] = pr[nb][0];
        stg[(e + 1) * 132 + 16*w + g    ] = pr[nb][1];
        stg[(e    ) * 132 + 16*w + g + 8] = pr[nb][2];
        stg[(e + 1) * 132 + 16*w + g + 8] = pr[nb][3];
    }
    __syncthreads();

    #pragma unroll
    for (int it = 0; it < 16; it++) {
        int idx = tid + it * 256;
        int e = idx >> 5, qq = idx & 31;
        float4 v4 = *(float4*)&stg[e * 132 + qq * 4];
        float bias = __ldg(pb + e);
        size_t gi = ((size_t)b * C + e) * NN + q0 + qq * 4;
        float4 xr = *(const float4*)&x[gi];
        v4.x += bias + xr.x; v4.y += bias + xr.y;
        v4.z += bias + xr.z; v4.w += bias + xr.w;
        *(float4*)&out[gi] = v4;
    }
}

// ---------------- launch -----------------------------------------------------
extern "C" void kernel_launch(void* const* d_in, const int* in_sizes, int n_in,
                              void* d_out, int out_size)
{
    const float* x    = (const float*)d_in[0];
    const float* gn_w = (const float*)d_in[1];
    const float* gn_b = (const float*)d_in[2];
    const float* q_w  = (const float*)d_in[3];
    const float* q_b  = (const float*)d_in[4];
    const float* k_w  = (const float*)d_in[5];
    const float* k_b  = (const float*)d_in[6];
    const float* v_w  = (const float*)d_in[7];
    const float* v_b  = (const float*)d_in[8];
    const float* p_w  = (const float*)d_in[9];
    const float* p_b  = (const float*)d_in[10];
    float* out = (float*)d_out;

    float* st;
    __nv_bfloat16 *qt, *kt, *v, *pwb;
    cudaGetSymbolAddress((void**)&qt,  g_qt);
    cudaGetSymbolAddress((void**)&kt,  g_kt);
    cudaGetSymbolAddress((void**)&v,   g_v);
    cudaGetSymbolAddress((void**)&pwb, g_pwb);
    cudaGetSymbolAddress((void**)&st,  g_st);

    cudaFuncSetAttribute(flash_mma_kernel,
                         cudaFuncAttributeMaxDynamicSharedMemorySize, SMEM_FL);
    cudaFuncSetAttribute(qkv_proj_kernel,
                         cudaFuncAttributeMaxDynamicSharedMemorySize, SMEM_PJ);

    gn_stats_kernel<<<BATCH * G, 256>>>(x, st, p_w, pwb);

    qkv_proj_kernel<<<dim3(NN / 128, BATCH), 256, SMEM_PJ>>>(
        q_w, q_b, k_w, k_b, v_w, v_b, gn_w, gn_b, st, x, qt, kt, v);

    flash_mma_kernel<<<BATCH * 32, 256, SMEM_FL>>>(qt, kt, v, pwb, p_b, x, out);
}

// round 15
// speedup vs baseline: 1.5849x; 1.0753x over previous
#include <cuda_runtime.h>
#include <cuda_bf16.h>
#include <cstdint>
#include <math.h>

#define BATCH 8
#define C 128
#define NN 4096
#define D 16
#define G 32
#define CPG (C / G)
#define EPS 1e-5f
#define SCALE_Q 0.36067376022224085f   // 0.25 * log2(e)

// ---------------- scratch ----------------------------------------------------
__device__ __nv_bfloat16  g_qt [BATCH * NN * D];   // q [B,N,16] bf16, pre-scaled
__device__ __nv_bfloat16  g_kt [BATCH * NN * D];   // k [B,N,16] bf16
__device__ __nv_bfloat16  g_v  [BATCH * C * NN];   // v [B,C,N] bf16
__device__ __nv_bfloat16  g_pwb[C * C];            // p_w bf16 [e][c]
__device__ float          g_st [BATCH * G * 2];    // groupnorm (mean, rstd)

// ---------------- GroupNorm stats (+ p_w bf16 convert piggyback) -------------
__global__ __launch_bounds__(512) void gn_stats_kernel(
    const float* __restrict__ x, float* __restrict__ st,
    const float* __restrict__ pw, __nv_bfloat16* __restrict__ pwb)
{
    const int b = blockIdx.x >> 5;
    const int g = blockIdx.x & 31;
    const float* xp = x + ((size_t)b * C + g * CPG) * NN;

    if (threadIdx.x < 64) {   // 256 blocks x 64 = 16384 = C*C
        int i = blockIdx.x * 64 + threadIdx.x;
        pwb[i] = __float2bfloat16_rn(pw[i]);
    }

    const int TOT = CPG * NN;
    float s = 0.f, s2 = 0.f;
    for (int idx = threadIdx.x; idx < TOT; idx += 512) {
        float v = xp[idx];
        s += v; s2 += v * v;
    }
    __shared__ float red[32];
    int lane = threadIdx.x & 31, wid = threadIdx.x >> 5;
    #pragma unroll
    for (int o = 16; o > 0; o >>= 1) {
        s  += __shfl_xor_sync(0xffffffffu, s,  o);
        s2 += __shfl_xor_sync(0xffffffffu, s2, o);
    }
    if (lane == 0) { red[wid] = s; red[16 + wid] = s2; }
    __syncthreads();
    if (wid == 0) {
        float a = (lane < 16) ? red[lane] : 0.f;
        float a2 = (lane < 16) ? red[16 + lane] : 0.f;
        #pragma unroll
        for (int o = 8; o > 0; o >>= 1) {
            a  += __shfl_xor_sync(0xffffffffu, a,  o);
            a2 += __shfl_xor_sync(0xffffffffu, a2, o);
        }
        if (lane == 0) {
            const float inv_n = 1.f / (float)TOT;
            float mean = a * inv_n;
            float var = a2 * inv_n - mean * mean;
            st[blockIdx.x * 2]     = mean;
            st[blockIdx.x * 2 + 1] = rsqrtf(var + EPS);
        }
    }
}

// ---------------- mma helpers ------------------------------------------------
__device__ __forceinline__ uint32_t smem_u32(const void* p) {
    uint32_t a;
    asm("{ .reg .u64 t; cvta.to.shared.u64 t, %1; cvt.u32.u64 %0, t; }" : "=r"(a) : "l"(p));
    return a;
}
__device__ __forceinline__ void cpa16(uint32_t s, const void* g) {
    asm volatile("cp.async.cg.shared.global [%0], [%1], 16;" :: "r"(s), "l"(g));
}
#define CP_COMMIT() asm volatile("cp.async.commit_group;" ::: "memory")
#define CP_WAIT1()  asm volatile("cp.async.wait_group 1;" ::: "memory")
#define CP_WAIT0()  asm volatile("cp.async.wait_group 0;" ::: "memory")

__device__ __forceinline__ float ex2f(float f) {
    float r; asm("ex2.approx.f32 %0, %1;" : "=f"(r) : "f"(f)); return r;
}
__device__ __forceinline__ uint32_t bf2(float hi, float lo) {
    uint32_t r; asm("cvt.rn.bf16x2.f32 %0, %1, %2;" : "=r"(r) : "f"(hi), "f"(lo)); return r;
}
__device__ __forceinline__ void mma_bf16(float* c, uint32_t a0, uint32_t a1,
                                         uint32_t a2, uint32_t a3,
                                         uint32_t b0, uint32_t b1) {
    asm volatile(
        "mma.sync.aligned.m16n8k16.row.col.f32.bf16.bf16.f32 "
        "{%0,%1,%2,%3},{%4,%5,%6,%7},{%8,%9},{%0,%1,%2,%3};"
        : "+f"(c[0]), "+f"(c[1]), "+f"(c[2]), "+f"(c[3])
        : "r"(a0), "r"(a1), "r"(a2), "r"(a3), "r"(b0), "r"(b1));
}
__device__ __forceinline__ void ldm4(uint32_t& r0, uint32_t& r1, uint32_t& r2,
                                     uint32_t& r3, uint32_t addr) {
    asm volatile("ldmatrix.sync.aligned.m8n8.x4.shared.b16 {%0,%1,%2,%3}, [%4];"
                 : "=r"(r0), "=r"(r1), "=r"(r2), "=r"(r3) : "r"(addr));
}

// ============================================================================
//   fused GN + QKV projection (bf16 mma, 2 CTAs/SM)
// ============================================================================
#define PJ_HT   0                  // 34816
#define PJ_WS   34816              // 43520 (vstage overlay in epilogue)
#define PJ_BIAS 78336              // 640
#define PJ_SC   79104              // 1024
#define SMEM_PJ 80128

__global__ __launch_bounds__(256, 2) void qkv_proj_kernel(
    const float* __restrict__ qw, const float* __restrict__ qb,
    const float* __restrict__ kw, const float* __restrict__ kb,
    const float* __restrict__ vw, const float* __restrict__ vb,
    const float* __restrict__ gnw, const float* __restrict__ gnb,
    const float* __restrict__ st, const float* __restrict__ x,
    __nv_bfloat16* __restrict__ qt, __nv_bfloat16* __restrict__ kt,
    __nv_bfloat16* __restrict__ vout)
{
    extern __shared__ char sm[];
    uint32_t* hT = (uint32_t*)(sm + PJ_HT);    // [n][68] bf16x2 of (2c,2c+1)
    uint32_t* Ws = (uint32_t*)(sm + PJ_WS);    // [e][68] bf16x2
    float* bs = (float*)(sm + PJ_BIAS);
    float* sc = (float*)(sm + PJ_SC);
    float* sh = sc + 128;
    const int tid = threadIdx.x;
    const int w = tid >> 5, lane = tid & 31;
    const int g = lane >> 2, t = lane & 3;
    const int n0 = blockIdx.x * 128;
    const int b = blockIdx.y;

    if (tid < 128) {
        float mean = st[(b * G + (tid >> 2)) * 2];
        float inv  = st[(b * G + (tid >> 2)) * 2 + 1];
        float s = gnw[tid] * inv;
        sc[tid] = s;
        sh[tid] = gnb[tid] - mean * s;
    }
    for (int u = tid; u < 160 * 64; u += 256) {
        int e = u >> 6, c2 = u & 63;
        const float* wsrc;
        if (e < 16)      wsrc = qw + e * C;
        else if (e < 32) wsrc = kw + (e - 16) * C;
        else             wsrc = vw + (e - 32) * C;
        Ws[e * 68 + c2] = bf2(wsrc[2 * c2 + 1], wsrc[2 * c2]);
    }
    if (tid < 160) {
        float bv;
        if (tid < 16)      bv = qb[tid];
        else if (tid < 32) bv = kb[tid - 16];
        else               bv = vb[tid - 32];
        bs[tid] = bv;
    }
    __syncthreads();

    for (int u = tid; u < 128 * 64; u += 256) {
        int n = u & 127, c2 = u >> 7;
        float h0 = fmaf(x[((size_t)b * C + 2 * c2)     * NN + n0 + n], sc[2 * c2],     sh[2 * c2]);
        float h1 = fmaf(x[((size_t)b * C + 2 * c2 + 1) * NN + n0 + n], sc[2 * c2 + 1], sh[2 * c2 + 1]);
        hT[n * 68 + c2] = bf2(h1, h0);
    }
    __syncthreads();

    float pr[20][4];
    #pragma unroll
    for (int nb = 0; nb < 20; nb++)
        #pragma unroll
        for (int i = 0; i < 4; i++) pr[nb][i] = 0.f;

    #pragma unroll
    for (int kc = 0; kc < 8; kc++) {
        uint32_t a0 = hT[(16 * w + g    ) * 68 + 8 * kc + t    ];
        uint32_t a1 = hT[(16 * w + g + 8) * 68 + 8 * kc + t    ];
        uint32_t a2 = hT[(16 * w + g    ) * 68 + 8 * kc + t + 4];
        uint32_t a3 = hT[(16 * w + g + 8) * 68 + 8 * kc + t + 4];
        #pragma unroll
        for (int nb = 0; nb < 20; nb++) {
            uint32_t b0 = Ws[(8 * nb + g) * 68 + 8 * kc + t    ];
            uint32_t b1 = Ws[(8 * nb + g) * 68 + 8 * kc + t + 4];
            mma_bf16(pr[nb], a0, a1, a2, a3, b0, b1);
        }
    }

    const int r0 = 16 * w + g, r1 = r0 + 8;
    #pragma unroll
    for (int nb = 0; nb < 4; nb++) {
        int e = 8 * nb + 2 * t;
        float b0 = bs[e], b1 = bs[e + 1];
        if (e < 16) {
            *(uint32_t*)&qt[((size_t)b * NN + n0 + r0) * D + e] =
                bf2((pr[nb][1] + b1) * SCALE_Q, (pr[nb][0] + b0) * SCALE_Q);
            *(uint32_t*)&qt[((size_t)b * NN + n0 + r1) * D + e] =
                bf2((pr[nb][3] + b1) * SCALE_Q, (pr[nb][2] + b0) * SCALE_Q);
        } else {
            int E = e - 16;
            *(uint32_t*)&kt[((size_t)b * NN + n0 + r0) * D + E] =
                bf2(pr[nb][1] + b1, pr[nb][0] + b0);
            *(uint32_t*)&kt[((size_t)b * NN + n0 + r1) * D + E] =
                bf2(pr[nb][3] + b1, pr[nb][2] + b0);
        }
    }
    __syncthreads();

    __nv_bfloat16* vstage = (__nv_bfloat16*)(sm + PJ_WS);
    #pragma unroll
    for (int nb = 4; nb < 20; nb++) {
        int e = 8 * nb + 2 * t;
        int cv = e - 32;
        float b0 = bs[e], b1 = bs[e + 1];
        vstage[(cv    ) * 132 + r0] = __float2bfloat16_rn(pr[nb][0] + b0);
        vstage[(cv + 1) * 132 + r0] = __float2bfloat16_rn(pr[nb][1] + b1);
        vstage[(cv    ) * 132 + r1] = __float2bfloat16_rn(pr[nb][2] + b0);
        vstage[(cv + 1) * 132 + r1] = __float2bfloat16_rn(pr[nb][3] + b1);
    }
    __syncthreads();
    for (int u = tid; u < 128 * 32; u += 256) {
        int c = u >> 5, nc = u & 31;
        *(uint64_t*)&vout[((size_t)b * C + c) * NN + n0 + nc * 4] =
            *(const uint64_t*)&vstage[c * 132 + nc * 4];
    }
}

// ============================================================================
//   flash attention: triple-buffered K/V rings (ONE barrier/tile), swizzled V
// ============================================================================
#define OFF_Q   0        // bf16 [128][16]  4096
#define OFF_K0  4096     // 3 x 4096   (K ring)
#define OFF_V0  16384    // 3 x 32768  (V ring, swizzled 256B pitch)
#define V_STRIDE 32768
#define OFF_STG 0        // f32 [128][132] 67584 (post-proj; disjoint from V2)
#define SMEM_FL 114688

__device__ __forceinline__ void issue_tile(uint32_t sb, int buf,
    const __nv_bfloat16* __restrict__ kt, const __nv_bfloat16* __restrict__ vb,
    int b, int j0, int tid)
{
    uint32_t kdst = sb + OFF_K0 + (uint32_t)buf * 4096;
    {
        int row = tid >> 1, cc = tid & 1;
        cpa16(kdst + row * 32 + cc * 16,
              kt + ((size_t)(b * NN + j0 + row)) * D + cc * 8);
    }
    uint32_t vdst = sb + OFF_V0 + (uint32_t)buf * V_STRIDE;
    #pragma unroll
    for (int u = tid; u < 2048; u += 256) {
        int c = u >> 4, cc = u & 15;
        cpa16(vdst + c * 256 + (((cc ^ (c & 7))) << 4),
              vb + ((size_t)(b * C + c)) * NN + j0 + cc * 8);
    }
}

__global__ __launch_bounds__(256, 2) void flash_mma_kernel(
    const __nv_bfloat16* __restrict__ qt, const __nv_bfloat16* __restrict__ kt,
    const __nv_bfloat16* __restrict__ vb, const __nv_bfloat16* __restrict__ pwb,
    const float* __restrict__ pb, const float* __restrict__ x,
    float* __restrict__ out)
{
    extern __shared__ char sm[];
    const uint32_t sb = smem_u32(sm);
    const int tid = threadIdx.x;
    const int w = tid >> 5;
    const int lane = tid & 31;
    const int g = lane >> 2, t = lane & 3;
    const int b = blockIdx.x >> 5;
    const int q0 = (blockIdx.x & 31) * 128;

    const int rowsel = (lane & 7) + ((lane >> 4) << 3);
    const int ksel = (lane >> 3) & 1;
    const int sx = lane & 7;                               // V swizzle xor (row&7)
    const uint32_t vlane = (uint32_t)(rowsel * 256);       // swizzled V tiles
    const uint32_t klane = (uint32_t)(rowsel * 32 + ksel * 16);
    const uint32_t qlane = (uint32_t)(
        (16 * w + (lane & 7) + (((lane >> 3) & 1) << 3)) * 32 + ((lane >> 4) & 1) * 16);

    {
        int row = tid >> 1, cc = tid & 1;
        cpa16(sb + OFF_Q + row * 32 + cc * 16,
              qt + ((size_t)(b * NN + q0 + row)) * D + cc * 8);
    }
    issue_tile(sb, 0, kt, vb, b, 0, tid);
    CP_COMMIT();

    uint32_t qa[4];
    float o[16][4];
    #pragma unroll
    for (int nb = 0; nb < 16; nb++)
        #pragma unroll
        for (int i = 0; i < 4; i++) o[nb][i] = 0.f;
    float ls[4] = {0.f, 0.f, 0.f, 0.f};
    const uint32_t ONES2 = 0x3F803F80u;

    int vb3 = 0;   // tt % 3
    for (int tt = 0; tt < 32; tt++) {
        if (tt < 31) {
            int nb3 = vb3 + 1; if (nb3 == 3) nb3 = 0;
            issue_tile(sb, nb3, kt, vb, b, (tt + 1) * 128, tid);
            CP_COMMIT();
        } else {
            // pw -> V2 ring slot (buf 2: last read at tile 29, safe per barrier)
            #pragma unroll
            for (int u = tid; u < 2048; u += 256) {
                int row = u >> 4, cc = u & 15;
                cpa16(sb + OFF_V0 + 2 * V_STRIDE + row * 256 + (((cc ^ (row & 7))) << 4),
                      pwb + row * C + cc * 8);
            }
            CP_COMMIT();
        }
        CP_WAIT1();         // tile tt data complete (pw/newest still in flight)
        __syncthreads();    // single barrier: publishes data + protects ring reuse

        if (tt == 0) {
            ldm4(qa[0], qa[1], qa[2], qa[3], sb + OFF_Q + qlane);
        }

        const uint32_t kbase = sb + OFF_K0 + (uint32_t)vb3 * 4096 + klane;
        const uint32_t vbase = sb + OFF_V0 + (uint32_t)vb3 * V_STRIDE + vlane;

        // ---- fused per-s-block, K-frag software pipelined
        uint32_t kf0, kf1, kf2, kf3;
        ldm4(kf0, kf1, kf2, kf3, kbase);
        #pragma unroll
        for (int s = 0; s < 8; s++) {
            float sc0[4] = {0.f, 0.f, 0.f, 0.f};
            float sc1[4] = {0.f, 0.f, 0.f, 0.f};
            mma_bf16(sc0, qa[0], qa[1], qa[2], qa[3], kf0, kf1);
            mma_bf16(sc1, qa[0], qa[1], qa[2], qa[3], kf2, kf3);
            if (s < 7) ldm4(kf0, kf1, kf2, kf3, kbase + (uint32_t)((s + 1) * 512));
            uint32_t a0 = bf2(ex2f(sc0[1]), ex2f(sc0[0]));
            uint32_t a1 = bf2(ex2f(sc0[3]), ex2f(sc0[2]));
            uint32_t a2 = bf2(ex2f(sc1[1]), ex2f(sc1[0]));
            uint32_t a3 = bf2(ex2f(sc1[3]), ex2f(sc1[2]));
            mma_bf16(ls, a0, a1, a2, a3, ONES2, ONES2);
            const uint32_t cs = (uint32_t)(((2 * s + ksel) ^ sx) << 4);
            #pragma unroll
            for (int nbp = 0; nbp < 8; nbp++) {
                uint32_t r0, r1, r2, r3;
                ldm4(r0, r1, r2, r3, vbase + (uint32_t)(nbp * 4096) + cs);
                mma_bf16(o[2*nbp],     a0, a1, a2, a3, r0, r1);
                mma_bf16(o[2*nbp + 1], a0, a1, a2, a3, r2, r3);
            }
        }
        vb3++; if (vb3 == 3) vb3 = 0;
    }

    const float il0 = 1.f / ls[0], il1 = 1.f / ls[2];

    uint32_t oa0[16], oa1[16];
    #pragma unroll
    for (int nb = 0; nb < 16; nb++) {
        oa0[nb] = bf2(o[nb][1] * il0, o[nb][0] * il0);
        oa1[nb] = bf2(o[nb][3] * il1, o[nb][2] * il1);
    }

    CP_WAIT0();          // pw arrived in V2
    __syncthreads();     // also: all warps done with tile-31 V1 reads

    float pr[16][4];
    #pragma unroll
    for (int nb = 0; nb < 16; nb++)
        #pragma unroll
        for (int i = 0; i < 4; i++) pr[nb][i] = 0.f;
    const uint32_t pwbase = sb + OFF_V0 + 2 * V_STRIDE + vlane;
    #pragma unroll
    for (int s = 0; s < 8; s++) {
        const uint32_t a0 = oa0[2*s], a1 = oa1[2*s];
        const uint32_t a2 = oa0[2*s+1], a3 = oa1[2*s+1];
        const uint32_t cs = (uint32_t)(((2 * s + ksel) ^ sx) << 4);
        #pragma unroll
        for (int nbp = 0; nbp < 8; nbp++) {
            uint32_t r0, r1, r2, r3;
            ldm4(r0, r1, r2, r3, pwbase + (uint32_t)(nbp * 4096) + cs);
            mma_bf16(pr[2*nbp],     a0, a1, a2, a3, r0, r1);
            mma_bf16(pr[2*nbp + 1], a0, a1, a2, a3, r2, r3);
        }
    }
    __syncthreads();

    float* stg = (float*)(sm + OFF_STG);
    #pragma unroll
    for (int nb = 0; nb < 16; nb++) {
        int e = 8*nb + 2*t;
        stg[(e    ) * 132 + 16*w + g    ] = pr[nb][0];
        stg[(e + 1) * 132 + 16*w + g    ] = pr[nb][1];
        stg[(e    ) * 132 + 16*w + g + 8] = pr[nb][2];
        stg[(e + 1) * 132 + 16*w + g + 8] = pr[nb][3];
    }
    __syncthreads();

    #pragma unroll
    for (int it = 0; it < 16; it++) {
        int idx = tid + it * 256;
        int e = idx >> 5, qq = idx & 31;
        float4 v4 = *(float4*)&stg[e * 132 + qq * 4];
        float bias = __ldg(pb + e);
        size_t gi = ((size_t)b * C + e) * NN + q0 + qq * 4;
        float4 xr = *(const float4*)&x[gi];
        v4.x += bias + xr.x; v4.y += bias + xr.y;
        v4.z += bias + xr.z; v4.w += bias + xr.w;
        *(float4*)&out[gi] = v4;
    }
}

// ---------------- launch -----------------------------------------------------
extern "C" void kernel_launch(void* const* d_in, const int* in_sizes, int n_in,
                              void* d_out, int out_size)
{
    const float* x    = (const float*)d_in[0];
    const float* gn_w = (const float*)d_in[1];
    const float* gn_b = (const float*)d_in[2];
    const float* q_w  = (const float*)d_in[3];
    const float* q_b  = (const float*)d_in[4];
    const float* k_w  = (const float*)d_in[5];
    const float* k_b  = (const float*)d_in[6];
    const float* v_w  = (const float*)d_in[7];
    const float* v_b  = (const float*)d_in[8];
    const float* p_w  = (const float*)d_in[9];
    const float* p_b  = (const float*)d_in[10];
    float* out = (float*)d_out;

    float* st;
    __nv_bfloat16 *qt, *kt, *v, *pwb;
    cudaGetSymbolAddress((void**)&qt,  g_qt);
    cudaGetSymbolAddress((void**)&kt,  g_kt);
    cudaGetSymbolAddress((void**)&v,   g_v);
    cudaGetSymbolAddress((void**)&pwb, g_pwb);
    cudaGetSymbolAddress((void**)&st,  g_st);

    cudaFuncSetAttribute(flash_mma_kernel,
                         cudaFuncAttributeMaxDynamicSharedMemorySize, SMEM_FL);
    cudaFuncSetAttribute(qkv_proj_kernel,
                         cudaFuncAttributeMaxDynamicSharedMemorySize, SMEM_PJ);

    gn_stats_kernel<<<BATCH * G, 512>>>(x, st, p_w, pwb);

    qkv_proj_kernel<<<dim3(NN / 128, BATCH), 256, SMEM_PJ>>>(
        q_w, q_b, k_w, k_b, v_w, v_b, gn_w, gn_b, st, x, qt, kt, v);

    flash_mma_kernel<<<BATCH * 32, 256, SMEM_FL>>>(qt, kt, v, pwb, p_b, x, out);
}

// round 16
// speedup vs baseline: 1.6089x; 1.0151x over previous
#include <cuda_runtime.h>
#include <cuda_bf16.h>
#include <cstdint>
#include <math.h>

#define BATCH 8
#define C 128
#define NN 4096
#define D 16
#define G 32
#define CPG (C / G)
#define EPS 1e-5f
#define SCALE_Q 0.36067376022224085f   // 0.25 * log2(e)

// ---------------- scratch ----------------------------------------------------
__device__ __nv_bfloat16  g_qt [BATCH * NN * D];   // q [B,N,16] bf16, pre-scaled
__device__ __nv_bfloat16  g_kt [BATCH * NN * D];   // k [B,N,16] bf16
__device__ __nv_bfloat16  g_v  [BATCH * C * NN];   // v [B,C,N] bf16
__device__ __nv_bfloat16  g_pwb[C * C];            // p_w bf16 [e][c]
__device__ float          g_st [BATCH * G * 2];    // groupnorm (mean, rstd)

// ---------------- GroupNorm stats (+ p_w bf16 convert piggyback) -------------
__global__ __launch_bounds__(1024) void gn_stats_kernel(
    const float* __restrict__ x, float* __restrict__ st,
    const float* __restrict__ pw, __nv_bfloat16* __restrict__ pwb)
{
    const int b = blockIdx.x >> 5;
    const int g = blockIdx.x & 31;
    const float* xp = x + ((size_t)b * C + g * CPG) * NN;

    if (threadIdx.x < 64) {   // 256 blocks x 64 = 16384 = C*C
        int i = blockIdx.x * 64 + threadIdx.x;
        pwb[i] = __float2bfloat16_rn(pw[i]);
    }

    const int TOT = CPG * NN;
    float s = 0.f, s2 = 0.f;
    for (int idx = threadIdx.x; idx < TOT; idx += 1024) {
        float v = xp[idx];
        s += v; s2 += v * v;
    }
    __shared__ float red[64];
    int lane = threadIdx.x & 31, wid = threadIdx.x >> 5;
    #pragma unroll
    for (int o = 16; o > 0; o >>= 1) {
        s  += __shfl_xor_sync(0xffffffffu, s,  o);
        s2 += __shfl_xor_sync(0xffffffffu, s2, o);
    }
    if (lane == 0) { red[wid] = s; red[32 + wid] = s2; }
    __syncthreads();
    if (wid == 0) {
        float a  = red[lane];
        float a2 = red[32 + lane];
        #pragma unroll
        for (int o = 16; o > 0; o >>= 1) {
            a  += __shfl_xor_sync(0xffffffffu, a,  o);
            a2 += __shfl_xor_sync(0xffffffffu, a2, o);
        }
        if (lane == 0) {
            const float inv_n = 1.f / (float)TOT;
            float mean = a * inv_n;
            float var = a2 * inv_n - mean * mean;
            st[blockIdx.x * 2]     = mean;
            st[blockIdx.x * 2 + 1] = rsqrtf(var + EPS);
        }
    }
}

// ---------------- mma helpers ------------------------------------------------
__device__ __forceinline__ uint32_t smem_u32(const void* p) {
    uint32_t a;
    asm("{ .reg .u64 t; cvta.to.shared.u64 t, %1; cvt.u32.u64 %0, t; }" : "=r"(a) : "l"(p));
    return a;
}
__device__ __forceinline__ void cpa16(uint32_t s, const void* g) {
    asm volatile("cp.async.cg.shared.global [%0], [%1], 16;" :: "r"(s), "l"(g));
}
#define CP_COMMIT() asm volatile("cp.async.commit_group;" ::: "memory")
#define CP_WAIT1()  asm volatile("cp.async.wait_group 1;" ::: "memory")
#define CP_WAIT0()  asm volatile("cp.async.wait_group 0;" ::: "memory")

__device__ __forceinline__ uint32_t bf2(float hi, float lo) {
    uint32_t r; asm("cvt.rn.bf16x2.f32 %0, %1, %2;" : "=r"(r) : "f"(hi), "f"(lo)); return r;
}
__device__ __forceinline__ uint32_t ex2x2(uint32_t v) {
    uint32_t r; asm("ex2.approx.ftz.bf16x2 %0, %1;" : "=r"(r) : "r"(v)); return r;
}
__device__ __forceinline__ void mma_bf16(float* c, uint32_t a0, uint32_t a1,
                                         uint32_t a2, uint32_t a3,
                                         uint32_t b0, uint32_t b1) {
    asm volatile(
        "mma.sync.aligned.m16n8k16.row.col.f32.bf16.bf16.f32 "
        "{%0,%1,%2,%3},{%4,%5,%6,%7},{%8,%9},{%0,%1,%2,%3};"
        : "+f"(c[0]), "+f"(c[1]), "+f"(c[2]), "+f"(c[3])
        : "r"(a0), "r"(a1), "r"(a2), "r"(a3), "r"(b0), "r"(b1));
}
__device__ __forceinline__ void ldm4(uint32_t& r0, uint32_t& r1, uint32_t& r2,
                                     uint32_t& r3, uint32_t addr) {
    asm volatile("ldmatrix.sync.aligned.m8n8.x4.shared.b16 {%0,%1,%2,%3}, [%4];"
                 : "=r"(r0), "=r"(r1), "=r"(r2), "=r"(r3) : "r"(addr));
}

// ============================================================================
//   fused GN + QKV projection (bf16 mma, 2 CTAs/SM)
// ============================================================================
#define PJ_HT   0                  // 34816
#define PJ_WS   34816              // 43520 (vstage overlay in epilogue)
#define PJ_BIAS 78336              // 640
#define PJ_SC   79104              // 1024
#define SMEM_PJ 80128

__global__ __launch_bounds__(256, 2) void qkv_proj_kernel(
    const float* __restrict__ qw, const float* __restrict__ qb,
    const float* __restrict__ kw, const float* __restrict__ kb,
    const float* __restrict__ vw, const float* __restrict__ vb,
    const float* __restrict__ gnw, const float* __restrict__ gnb,
    const float* __restrict__ st, const float* __restrict__ x,
    __nv_bfloat16* __restrict__ qt, __nv_bfloat16* __restrict__ kt,
    __nv_bfloat16* __restrict__ vout)
{
    extern __shared__ char sm[];
    uint32_t* hT = (uint32_t*)(sm + PJ_HT);    // [n][68] bf16x2 of (2c,2c+1)
    uint32_t* Ws = (uint32_t*)(sm + PJ_WS);    // [e][68] bf16x2
    float* bs = (float*)(sm + PJ_BIAS);
    float* sc = (float*)(sm + PJ_SC);
    float* sh = sc + 128;
    const int tid = threadIdx.x;
    const int w = tid >> 5, lane = tid & 31;
    const int g = lane >> 2, t = lane & 3;
    const int n0 = blockIdx.x * 128;
    const int b = blockIdx.y;

    if (tid < 128) {
        float mean = st[(b * G + (tid >> 2)) * 2];
        float inv  = st[(b * G + (tid >> 2)) * 2 + 1];
        float s = gnw[tid] * inv;
        sc[tid] = s;
        sh[tid] = gnb[tid] - mean * s;
    }
    for (int u = tid; u < 160 * 64; u += 256) {
        int e = u >> 6, c2 = u & 63;
        const float* wsrc;
        if (e < 16)      wsrc = qw + e * C;
        else if (e < 32) wsrc = kw + (e - 16) * C;
        else             wsrc = vw + (e - 32) * C;
        Ws[e * 68 + c2] = bf2(wsrc[2 * c2 + 1], wsrc[2 * c2]);
    }
    if (tid < 160) {
        float bv;
        if (tid < 16)      bv = qb[tid];
        else if (tid < 32) bv = kb[tid - 16];
        else               bv = vb[tid - 32];
        bs[tid] = bv;
    }
    __syncthreads();

    for (int u = tid; u < 128 * 64; u += 256) {
        int n = u & 127, c2 = u >> 7;
        float h0 = fmaf(x[((size_t)b * C + 2 * c2)     * NN + n0 + n], sc[2 * c2],     sh[2 * c2]);
        float h1 = fmaf(x[((size_t)b * C + 2 * c2 + 1) * NN + n0 + n], sc[2 * c2 + 1], sh[2 * c2 + 1]);
        hT[n * 68 + c2] = bf2(h1, h0);
    }
    __syncthreads();

    float pr[20][4];
    #pragma unroll
    for (int nb = 0; nb < 20; nb++)
        #pragma unroll
        for (int i = 0; i < 4; i++) pr[nb][i] = 0.f;

    #pragma unroll
    for (int kc = 0; kc < 8; kc++) {
        uint32_t a0 = hT[(16 * w + g    ) * 68 + 8 * kc + t    ];
        uint32_t a1 = hT[(16 * w + g + 8) * 68 + 8 * kc + t    ];
        uint32_t a2 = hT[(16 * w + g    ) * 68 + 8 * kc + t + 4];
        uint32_t a3 = hT[(16 * w + g + 8) * 68 + 8 * kc + t + 4];
        #pragma unroll
        for (int nb = 0; nb < 20; nb++) {
            uint32_t b0 = Ws[(8 * nb + g) * 68 + 8 * kc + t    ];
            uint32_t b1 = Ws[(8 * nb + g) * 68 + 8 * kc + t + 4];
            mma_bf16(pr[nb], a0, a1, a2, a3, b0, b1);
        }
    }

    const int r0 = 16 * w + g, r1 = r0 + 8;
    #pragma unroll
    for (int nb = 0; nb < 4; nb++) {
        int e = 8 * nb + 2 * t;
        float b0 = bs[e], b1 = bs[e + 1];
        if (e < 16) {
            *(uint32_t*)&qt[((size_t)b * NN + n0 + r0) * D + e] =
                bf2((pr[nb][1] + b1) * SCALE_Q, (pr[nb][0] + b0) * SCALE_Q);
            *(uint32_t*)&qt[((size_t)b * NN + n0 + r1) * D + e] =
                bf2((pr[nb][3] + b1) * SCALE_Q, (pr[nb][2] + b0) * SCALE_Q);
        } else {
            int E = e - 16;
            *(uint32_t*)&kt[((size_t)b * NN + n0 + r0) * D + E] =
                bf2(pr[nb][1] + b1, pr[nb][0] + b0);
            *(uint32_t*)&kt[((size_t)b * NN + n0 + r1) * D + E] =
                bf2(pr[nb][3] + b1, pr[nb][2] + b0);
        }
    }
    __syncthreads();

    __nv_bfloat16* vstage = (__nv_bfloat16*)(sm + PJ_WS);
    #pragma unroll
    for (int nb = 4; nb < 20; nb++) {
        int e = 8 * nb + 2 * t;
        int cv = e - 32;
        float b0 = bs[e], b1 = bs[e + 1];
        vstage[(cv    ) * 132 + r0] = __float2bfloat16_rn(pr[nb][0] + b0);
        vstage[(cv + 1) * 132 + r0] = __float2bfloat16_rn(pr[nb][1] + b1);
        vstage[(cv    ) * 132 + r1] = __float2bfloat16_rn(pr[nb][2] + b0);
        vstage[(cv + 1) * 132 + r1] = __float2bfloat16_rn(pr[nb][3] + b1);
    }
    __syncthreads();
    for (int u = tid; u < 128 * 32; u += 256) {
        int c = u >> 5, nc = u & 31;
        *(uint64_t*)&vout[((size_t)b * C + c) * NN + n0 + nc * 4] =
            *(const uint64_t*)&vstage[c * 132 + nc * 4];
    }
}

// ============================================================================
//   flash attention: triple-buffered rings, ONE barrier/tile, bf16x2 exp
// ============================================================================
#define OFF_Q   0        // bf16 [128][16]  4096
#define OFF_K0  4096     // 3 x 4096   (K ring)
#define OFF_V0  16384    // 3 x 32768  (V ring, swizzled 256B pitch)
#define V_STRIDE 32768
#define OFF_STG 0        // f32 [128][132] 67584 (post-proj; disjoint from V2)
#define SMEM_FL 114688

__device__ __forceinline__ void issue_tile(uint32_t sb, int buf,
    const __nv_bfloat16* __restrict__ kt, const __nv_bfloat16* __restrict__ vb,
    int b, int j0, int tid)
{
    uint32_t kdst = sb + OFF_K0 + (uint32_t)buf * 4096;
    {
        int row = tid >> 1, cc = tid & 1;
        cpa16(kdst + row * 32 + cc * 16,
              kt + ((size_t)(b * NN + j0 + row)) * D + cc * 8);
    }
    uint32_t vdst = sb + OFF_V0 + (uint32_t)buf * V_STRIDE;
    #pragma unroll
    for (int u = tid; u < 2048; u += 256) {
        int c = u >> 4, cc = u & 15;
        cpa16(vdst + c * 256 + (((cc ^ (c & 7))) << 4),
              vb + ((size_t)(b * C + c)) * NN + j0 + cc * 8);
    }
}

__global__ __launch_bounds__(256, 2) void flash_mma_kernel(
    const __nv_bfloat16* __restrict__ qt, const __nv_bfloat16* __restrict__ kt,
    const __nv_bfloat16* __restrict__ vb, const __nv_bfloat16* __restrict__ pwb,
    const float* __restrict__ pb, const float* __restrict__ x,
    float* __restrict__ out)
{
    extern __shared__ char sm[];
    const uint32_t sb = smem_u32(sm);
    const int tid = threadIdx.x;
    const int w = tid >> 5;
    const int lane = tid & 31;
    const int g = lane >> 2, t = lane & 3;
    const int b = blockIdx.x >> 5;
    const int q0 = (blockIdx.x & 31) * 128;

    const int rowsel = (lane & 7) + ((lane >> 4) << 3);
    const int ksel = (lane >> 3) & 1;
    const int sx = lane & 7;                               // V swizzle xor (row&7)
    const uint32_t vlane = (uint32_t)(rowsel * 256);       // swizzled V tiles
    const uint32_t klane = (uint32_t)(rowsel * 32 + ksel * 16);
    const uint32_t qlane = (uint32_t)(
        (16 * w + (lane & 7) + (((lane >> 3) & 1) << 3)) * 32 + ((lane >> 4) & 1) * 16);

    {
        int row = tid >> 1, cc = tid & 1;
        cpa16(sb + OFF_Q + row * 32 + cc * 16,
              qt + ((size_t)(b * NN + q0 + row)) * D + cc * 8);
    }
    issue_tile(sb, 0, kt, vb, b, 0, tid);
    CP_COMMIT();

    uint32_t qa[4];
    float o[16][4];
    #pragma unroll
    for (int nb = 0; nb < 16; nb++)
        #pragma unroll
        for (int i = 0; i < 4; i++) o[nb][i] = 0.f;
    float ls[4] = {0.f, 0.f, 0.f, 0.f};
    const uint32_t ONES2 = 0x3F803F80u;

    int vb3 = 0;   // tt % 3
    for (int tt = 0; tt < 32; tt++) {
        if (tt < 31) {
            int nb3 = vb3 + 1; if (nb3 == 3) nb3 = 0;
            issue_tile(sb, nb3, kt, vb, b, (tt + 1) * 128, tid);
            CP_COMMIT();
        } else {
            // pw -> V2 ring slot (buf 2: last read at tile 29, safe per barrier)
            #pragma unroll
            for (int u = tid; u < 2048; u += 256) {
                int row = u >> 4, cc = u & 15;
                cpa16(sb + OFF_V0 + 2 * V_STRIDE + row * 256 + (((cc ^ (row & 7))) << 4),
                      pwb + row * C + cc * 8);
            }
            CP_COMMIT();
        }
        CP_WAIT1();
        __syncthreads();    // single barrier: publishes data + protects ring reuse

        if (tt == 0) {
            ldm4(qa[0], qa[1], qa[2], qa[3], sb + OFF_Q + qlane);
        }

        const uint32_t kbase = sb + OFF_K0 + (uint32_t)vb3 * 4096 + klane;
        const uint32_t vbase = sb + OFF_V0 + (uint32_t)vb3 * V_STRIDE + vlane;

        // ---- fused per-s-block, K-frag pipelined, packed bf16x2 exp
        uint32_t kf0, kf1, kf2, kf3;
        ldm4(kf0, kf1, kf2, kf3, kbase);
        #pragma unroll
        for (int s = 0; s < 8; s++) {
            float sc0[4] = {0.f, 0.f, 0.f, 0.f};
            float sc1[4] = {0.f, 0.f, 0.f, 0.f};
            mma_bf16(sc0, qa[0], qa[1], qa[2], qa[3], kf0, kf1);
            mma_bf16(sc1, qa[0], qa[1], qa[2], qa[3], kf2, kf3);
            if (s < 7) ldm4(kf0, kf1, kf2, kf3, kbase + (uint32_t)((s + 1) * 512));
            // round scores to bf16 pairs, then 2-wide exp (MUFU ops halved)
            uint32_t a0 = ex2x2(bf2(sc0[1], sc0[0]));
            uint32_t a1 = ex2x2(bf2(sc0[3], sc0[2]));
            uint32_t a2 = ex2x2(bf2(sc1[1], sc1[0]));
            uint32_t a3 = ex2x2(bf2(sc1[3], sc1[2]));
            mma_bf16(ls, a0, a1, a2, a3, ONES2, ONES2);
            const uint32_t cs = (uint32_t)(((2 * s + ksel) ^ sx) << 4);
            #pragma unroll
            for (int nbp = 0; nbp < 8; nbp++) {
                uint32_t r0, r1, r2, r3;
                ldm4(r0, r1, r2, r3, vbase + (uint32_t)(nbp * 4096) + cs);
                mma_bf16(o[2*nbp],     a0, a1, a2, a3, r0, r1);
                mma_bf16(o[2*nbp + 1], a0, a1, a2, a3, r2, r3);
            }
        }
        vb3++; if (vb3 == 3) vb3 = 0;
    }

    const float il0 = 1.f / ls[0], il1 = 1.f / ls[2];

    uint32_t oa0[16], oa1[16];
    #pragma unroll
    for (int nb = 0; nb < 16; nb++) {
        oa0[nb] = bf2(o[nb][1] * il0, o[nb][0] * il0);
        oa1[nb] = bf2(o[nb][3] * il1, o[nb][2] * il1);
    }

    CP_WAIT0();          // pw arrived in V2
    __syncthreads();

    float pr[16][4];
    #pragma unroll
    for (int nb = 0; nb < 16; nb++)
        #pragma unroll
        for (int i = 0; i < 4; i++) pr[nb][i] = 0.f;
    const uint32_t pwbase = sb + OFF_V0 + 2 * V_STRIDE + vlane;
    #pragma unroll
    for (int s = 0; s < 8; s++) {
        const uint32_t a0 = oa0[2*s], a1 = oa1[2*s];
        const uint32_t a2 = oa0[2*s+1], a3 = oa1[2*s+1];
        const uint32_t cs = (uint32_t)(((2 * s + ksel) ^ sx) << 4);
        #pragma unroll
        for (int nbp = 0; nbp < 8; nbp++) {
            uint32_t r0, r1, r2, r3;
            ldm4(r0, r1, r2, r3, pwbase + (uint32_t)(nbp * 4096) + cs);
            mma_bf16(pr[2*nbp],     a0, a1, a2, a3, r0, r1);
            mma_bf16(pr[2*nbp + 1], a0, a1, a2, a3, r2, r3);
        }
    }
    __syncthreads();

    float* stg = (float*)(sm + OFF_STG);
    #pragma unroll
    for (int nb = 0; nb < 16; nb++) {
        int e = 8*nb + 2*t;
        stg[(e    ) * 132 + 16*w + g    ] = pr[nb][0];
        stg[(e + 1) * 132 + 16*w + g    ] = pr[nb][1];
        stg[(e    ) * 132 + 16*w + g + 8] = pr[nb][2];
        stg[(e + 1) * 132 + 16*w + g + 8] = pr[nb][3];
    }
    __syncthreads();

    #pragma unroll
    for (int it = 0; it < 16; it++) {
        int idx = tid + it * 256;
        int e = idx >> 5, qq = idx & 31;
        float4 v4 = *(float4*)&stg[e * 132 + qq * 4];
        float bias = __ldg(pb + e);
        size_t gi = ((size_t)b * C + e) * NN + q0 + qq * 4;
        float4 xr = *(const float4*)&x[gi];
        v4.x += bias + xr.x; v4.y += bias + xr.y;
        v4.z += bias + xr.z; v4.w += bias + xr.w;
        *(float4*)&out[gi] = v4;
    }
}

// ---------------- launch -----------------------------------------------------
extern "C" void kernel_launch(void* const* d_in, const int* in_sizes, int n_in,
                              void* d_out, int out_size)
{
    const float* x    = (const float*)d_in[0];
    const float* gn_w = (const float*)d_in[1];
    const float* gn_b = (const float*)d_in[2];
    const float* q_w  = (const float*)d_in[3];
    const float* q_b  = (const float*)d_in[4];
    const float* k_w  = (const float*)d_in[5];
    const float* k_b  = (const float*)d_in[6];
    const float* v_w  = (const float*)d_in[7];
    const float* v_b  = (const float*)d_in[8];
    const float* p_w  = (const float*)d_in[9];
    const float* p_b  = (const float*)d_in[10];
    float* out = (float*)d_out;

    float* st;
    __nv_bfloat16 *qt, *kt, *v, *pwb;
    cudaGetSymbolAddress((void**)&qt,  g_qt);
    cudaGetSymbolAddress((void**)&kt,  g_kt);
    cudaGetSymbolAddress((void**)&v,   g_v);
    cudaGetSymbolAddress((void**)&pwb, g_pwb);
    cudaGetSymbolAddress((void**)&st,  g_st);

    cudaFuncSetAttribute(flash_mma_kernel,
                         cudaFuncAttributeMaxDynamicSharedMemorySize, SMEM_FL);
    cudaFuncSetAttribute(qkv_proj_kernel,
                         cudaFuncAttributeMaxDynamicSharedMemorySize, SMEM_PJ);

    gn_stats_kernel<<<BATCH * G, 1024>>>(x, st, p_w, pwb);

    qkv_proj_kernel<<<dim3(NN / 128, BATCH), 256, SMEM_PJ>>>(
        q_w, q_b, k_w, k_b, v_w, v_b, gn_w, gn_b, st, x, qt, kt, v);

    flash_mma_kernel<<<BATCH * 32, 256, SMEM_FL>>>(qt, kt, v, pwb, p_b, x, out);
}

// round 17
// speedup vs baseline: 1.6332x; 1.0151x over previous
#include <cuda_runtime.h>
#include <cuda_bf16.h>
#include <cstdint>
#include <math.h>

#define BATCH 8
#define C 128
#define NN 4096
#define D 16
#define G 32
#define CPG (C / G)
#define EPS 1e-5f
#define SCALE_Q 0.36067376022224085f   // 0.25 * log2(e)

// ---------------- scratch ----------------------------------------------------
__device__ __nv_bfloat16  g_qt [BATCH * NN * D];   // q [B,N,16] bf16, pre-scaled
__device__ __nv_bfloat16  g_kt [BATCH * NN * D];   // k [B,N,16] bf16
__device__ __nv_bfloat16  g_v  [BATCH * C * NN];   // v [B,C,N] bf16
__device__ __nv_bfloat16  g_pwb[C * C];            // p_w bf16 [e][c]
__device__ float          g_st [BATCH * G * 2];    // groupnorm (mean, rstd)

// ---------------- GroupNorm stats (+ p_w bf16 convert piggyback) -------------
__global__ __launch_bounds__(512) void gn_stats_kernel(
    const float* __restrict__ x, float* __restrict__ st,
    const float* __restrict__ pw, __nv_bfloat16* __restrict__ pwb)
{
    const int b = blockIdx.x >> 5;
    const int g = blockIdx.x & 31;
    const float* xp = x + ((size_t)b * C + g * CPG) * NN;

    if (threadIdx.x < 64) {   // 256 blocks x 64 = 16384 = C*C
        int i = blockIdx.x * 64 + threadIdx.x;
        pwb[i] = __float2bfloat16_rn(pw[i]);
    }

    const int TOT = CPG * NN;
    float s = 0.f, s2 = 0.f;
    for (int idx = threadIdx.x; idx < TOT; idx += 512) {
        float v = xp[idx];
        s += v; s2 += v * v;
    }
    __shared__ float red[32];
    int lane = threadIdx.x & 31, wid = threadIdx.x >> 5;
    #pragma unroll
    for (int o = 16; o > 0; o >>= 1) {
        s  += __shfl_xor_sync(0xffffffffu, s,  o);
        s2 += __shfl_xor_sync(0xffffffffu, s2, o);
    }
    if (lane == 0) { red[wid] = s; red[16 + wid] = s2; }
    __syncthreads();
    if (wid == 0) {
        float a = (lane < 16) ? red[lane] : 0.f;
        float a2 = (lane < 16) ? red[16 + lane] : 0.f;
        #pragma unroll
        for (int o = 8; o > 0; o >>= 1) {
            a  += __shfl_xor_sync(0xffffffffu, a,  o);
            a2 += __shfl_xor_sync(0xffffffffu, a2, o);
        }
        if (lane == 0) {
            const float inv_n = 1.f / (float)TOT;
            float mean = a * inv_n;
            float var = a2 * inv_n - mean * mean;
            st[blockIdx.x * 2]     = mean;
            st[blockIdx.x * 2 + 1] = rsqrtf(var + EPS);
        }
    }
}

// ---------------- mma helpers ------------------------------------------------
__device__ __forceinline__ uint32_t smem_u32(const void* p) {
    uint32_t a;
    asm("{ .reg .u64 t; cvta.to.shared.u64 t, %1; cvt.u32.u64 %0, t; }" : "=r"(a) : "l"(p));
    return a;
}
__device__ __forceinline__ void cpa16(uint32_t s, const void* g) {
    asm volatile("cp.async.cg.shared.global [%0], [%1], 16;" :: "r"(s), "l"(g));
}
#define CP_COMMIT() asm volatile("cp.async.commit_group;" ::: "memory")
#define CP_WAIT1()  asm volatile("cp.async.wait_group 1;" ::: "memory")
#define CP_WAIT0()  asm volatile("cp.async.wait_group 0;" ::: "memory")

__device__ __forceinline__ uint32_t bf2(float hi, float lo) {
    uint32_t r; asm("cvt.rn.bf16x2.f32 %0, %1, %2;" : "=r"(r) : "f"(hi), "f"(lo)); return r;
}
__device__ __forceinline__ uint32_t ex2x2(uint32_t v) {
    uint32_t r; asm("ex2.approx.ftz.bf16x2 %0, %1;" : "=r"(r) : "r"(v)); return r;
}
__device__ __forceinline__ void mma_bf16(float* c, uint32_t a0, uint32_t a1,
                                         uint32_t a2, uint32_t a3,
                                         uint32_t b0, uint32_t b1) {
    asm volatile(
        "mma.sync.aligned.m16n8k16.row.col.f32.bf16.bf16.f32 "
        "{%0,%1,%2,%3},{%4,%5,%6,%7},{%8,%9},{%0,%1,%2,%3};"
        : "+f"(c[0]), "+f"(c[1]), "+f"(c[2]), "+f"(c[3])
        : "r"(a0), "r"(a1), "r"(a2), "r"(a3), "r"(b0), "r"(b1));
}
__device__ __forceinline__ void ldm4(uint32_t& r0, uint32_t& r1, uint32_t& r2,
                                     uint32_t& r3, uint32_t addr) {
    asm volatile("ldmatrix.sync.aligned.m8n8.x4.shared.b16 {%0,%1,%2,%3}, [%4];"
                 : "=r"(r0), "=r"(r1), "=r"(r2), "=r"(r3) : "r"(addr));
}

// ============================================================================
//   fused GN + QKV projection (bf16 mma, 2 CTAs/SM)
// ============================================================================
#define PJ_HT   0                  // 34816
#define PJ_WS   34816              // 43520 (vstage overlay in epilogue)
#define PJ_BIAS 78336              // 640
#define PJ_SC   79104              // 1024
#define SMEM_PJ 80128

__global__ __launch_bounds__(256, 2) void qkv_proj_kernel(
    const float* __restrict__ qw, const float* __restrict__ qb,
    const float* __restrict__ kw, const float* __restrict__ kb,
    const float* __restrict__ vw, const float* __restrict__ vb,
    const float* __restrict__ gnw, const float* __restrict__ gnb,
    const float* __restrict__ st, const float* __restrict__ x,
    __nv_bfloat16* __restrict__ qt, __nv_bfloat16* __restrict__ kt,
    __nv_bfloat16* __restrict__ vout)
{
    extern __shared__ char sm[];
    uint32_t* hT = (uint32_t*)(sm + PJ_HT);    // [n][68] bf16x2 of (2c,2c+1)
    uint32_t* Ws = (uint32_t*)(sm + PJ_WS);    // [e][68] bf16x2
    float* bs = (float*)(sm + PJ_BIAS);
    float* sc = (float*)(sm + PJ_SC);
    float* sh = sc + 128;
    const int tid = threadIdx.x;
    const int w = tid >> 5, lane = tid & 31;
    const int g = lane >> 2, t = lane & 3;
    const int n0 = blockIdx.x * 128;
    const int b = blockIdx.y;

    if (tid < 128) {
        float mean = st[(b * G + (tid >> 2)) * 2];
        float inv  = st[(b * G + (tid >> 2)) * 2 + 1];
        float s = gnw[tid] * inv;
        sc[tid] = s;
        sh[tid] = gnb[tid] - mean * s;
    }
    for (int u = tid; u < 160 * 64; u += 256) {
        int e = u >> 6, c2 = u & 63;
        const float* wsrc;
        if (e < 16)      wsrc = qw + e * C;
        else if (e < 32) wsrc = kw + (e - 16) * C;
        else             wsrc = vw + (e - 32) * C;
        Ws[e * 68 + c2] = bf2(wsrc[2 * c2 + 1], wsrc[2 * c2]);
    }
    if (tid < 160) {
        float bv;
        if (tid < 16)      bv = qb[tid];
        else if (tid < 32) bv = kb[tid - 16];
        else               bv = vb[tid - 32];
        bs[tid] = bv;
    }
    __syncthreads();

    for (int u = tid; u < 128 * 64; u += 256) {
        int n = u & 127, c2 = u >> 7;
        float h0 = fmaf(x[((size_t)b * C + 2 * c2)     * NN + n0 + n], sc[2 * c2],     sh[2 * c2]);
        float h1 = fmaf(x[((size_t)b * C + 2 * c2 + 1) * NN + n0 + n], sc[2 * c2 + 1], sh[2 * c2 + 1]);
        hT[n * 68 + c2] = bf2(h1, h0);
    }
    __syncthreads();

    float pr[20][4];
    #pragma unroll
    for (int nb = 0; nb < 20; nb++)
        #pragma unroll
        for (int i = 0; i < 4; i++) pr[nb][i] = 0.f;

    #pragma unroll
    for (int kc = 0; kc < 8; kc++) {
        uint32_t a0 = hT[(16 * w + g    ) * 68 + 8 * kc + t    ];
        uint32_t a1 = hT[(16 * w + g + 8) * 68 + 8 * kc + t    ];
        uint32_t a2 = hT[(16 * w + g    ) * 68 + 8 * kc + t + 4];
        uint32_t a3 = hT[(16 * w + g + 8) * 68 + 8 * kc + t + 4];
        #pragma unroll
        for (int nb = 0; nb < 20; nb++) {
            uint32_t b0 = Ws[(8 * nb + g) * 68 + 8 * kc + t    ];
            uint32_t b1 = Ws[(8 * nb + g) * 68 + 8 * kc + t + 4];
            mma_bf16(pr[nb], a0, a1, a2, a3, b0, b1);
        }
    }

    const int r0 = 16 * w + g, r1 = r0 + 8;
    #pragma unroll
    for (int nb = 0; nb < 4; nb++) {
        int e = 8 * nb + 2 * t;
        float b0 = bs[e], b1 = bs[e + 1];
        if (e < 16) {
            *(uint32_t*)&qt[((size_t)b * NN + n0 + r0) * D + e] =
                bf2((pr[nb][1] + b1) * SCALE_Q, (pr[nb][0] + b0) * SCALE_Q);
            *(uint32_t*)&qt[((size_t)b * NN + n0 + r1) * D + e] =
                bf2((pr[nb][3] + b1) * SCALE_Q, (pr[nb][2] + b0) * SCALE_Q);
        } else {
            int E = e - 16;
            *(uint32_t*)&kt[((size_t)b * NN + n0 + r0) * D + E] =
                bf2(pr[nb][1] + b1, pr[nb][0] + b0);
            *(uint32_t*)&kt[((size_t)b * NN + n0 + r1) * D + E] =
                bf2(pr[nb][3] + b1, pr[nb][2] + b0);
        }
    }
    __syncthreads();

    __nv_bfloat16* vstage = (__nv_bfloat16*)(sm + PJ_WS);
    #pragma unroll
    for (int nb = 4; nb < 20; nb++) {
        int e = 8 * nb + 2 * t;
        int cv = e - 32;
        float b0 = bs[e], b1 = bs[e + 1];
        vstage[(cv    ) * 132 + r0] = __float2bfloat16_rn(pr[nb][0] + b0);
        vstage[(cv + 1) * 132 + r0] = __float2bfloat16_rn(pr[nb][1] + b1);
        vstage[(cv    ) * 132 + r1] = __float2bfloat16_rn(pr[nb][2] + b0);
        vstage[(cv + 1) * 132 + r1] = __float2bfloat16_rn(pr[nb][3] + b1);
    }
    __syncthreads();
    for (int u = tid; u < 128 * 32; u += 256) {
        int c = u >> 5, nc = u & 31;
        *(uint64_t*)&vout[((size_t)b * C + c) * NN + n0 + nc * 4] =
            *(const uint64_t*)&vstage[c * 132 + nc * 4];
    }
}

// ============================================================================
//   flash attention: triple-buffered rings, ONE barrier/tile, bf16x2 exp
// ============================================================================
#define OFF_Q   0        // bf16 [128][16]  4096
#define OFF_K0  4096     // 3 x 4096   (K ring)
#define OFF_V0  16384    // 3 x 32768  (V ring, swizzled 256B pitch)
#define V_STRIDE 32768
#define OFF_STG 0        // f32 [128][132] 67584 (post-proj; disjoint from V2)
#define SMEM_FL 114688

__device__ __forceinline__ void issue_tile(uint32_t sb, int buf,
    const __nv_bfloat16* __restrict__ kt, const __nv_bfloat16* __restrict__ vb,
    int b, int j0, int tid)
{
    uint32_t kdst = sb + OFF_K0 + (uint32_t)buf * 4096;
    {
        int row = tid >> 1, cc = tid & 1;
        cpa16(kdst + row * 32 + cc * 16,
              kt + ((size_t)(b * NN + j0 + row)) * D + cc * 8);
    }
    uint32_t vdst = sb + OFF_V0 + (uint32_t)buf * V_STRIDE;
    #pragma unroll
    for (int u = tid; u < 2048; u += 256) {
        int c = u >> 4, cc = u & 15;
        cpa16(vdst + c * 256 + (((cc ^ (c & 7))) << 4),
              vb + ((size_t)(b * C + c)) * NN + j0 + cc * 8);
    }
}

__global__ __launch_bounds__(256, 2) void flash_mma_kernel(
    const __nv_bfloat16* __restrict__ qt, const __nv_bfloat16* __restrict__ kt,
    const __nv_bfloat16* __restrict__ vb, const __nv_bfloat16* __restrict__ pwb,
    const float* __restrict__ pb, const float* __restrict__ x,
    float* __restrict__ out)
{
    extern __shared__ char sm[];
    const uint32_t sb = smem_u32(sm);
    const int tid = threadIdx.x;
    const int w = tid >> 5;
    const int lane = tid & 31;
    const int g = lane >> 2, t = lane & 3;
    const int b = blockIdx.x >> 5;
    const int q0 = (blockIdx.x & 31) * 128;

    const int rowsel = (lane & 7) + ((lane >> 4) << 3);
    const int ksel = (lane >> 3) & 1;
    const int sx = lane & 7;                               // V swizzle xor (row&7)
    const uint32_t vlane = (uint32_t)(rowsel * 256);       // swizzled V tiles
    const uint32_t klane = (uint32_t)(rowsel * 32 + ksel * 16);
    const uint32_t qlane = (uint32_t)(
        (16 * w + (lane & 7) + (((lane >> 3) & 1) << 3)) * 32 + ((lane >> 4) & 1) * 16);

    {
        int row = tid >> 1, cc = tid & 1;
        cpa16(sb + OFF_Q + row * 32 + cc * 16,
              qt + ((size_t)(b * NN + q0 + row)) * D + cc * 8);
    }
    issue_tile(sb, 0, kt, vb, b, 0, tid);
    CP_COMMIT();

    uint32_t qa[4];
    float o[16][4];
    #pragma unroll
    for (int nb = 0; nb < 16; nb++)
        #pragma unroll
        for (int i = 0; i < 4; i++) o[nb][i] = 0.f;
    float ls[4] = {0.f, 0.f, 0.f, 0.f};
    const uint32_t ONES2 = 0x3F803F80u;

    int vb3 = 0;   // tt % 3
    for (int tt = 0; tt < 32; tt++) {
        if (tt < 31) {
            int nb3 = vb3 + 1; if (nb3 == 3) nb3 = 0;
            issue_tile(sb, nb3, kt, vb, b, (tt + 1) * 128, tid);
            CP_COMMIT();
        } else {
            // pw -> V2 ring slot (buf 2: last read at tile 29, safe per barrier)
            #pragma unroll
            for (int u = tid; u < 2048; u += 256) {
                int row = u >> 4, cc = u & 15;
                cpa16(sb + OFF_V0 + 2 * V_STRIDE + row * 256 + (((cc ^ (row & 7))) << 4),
                      pwb + row * C + cc * 8);
            }
            CP_COMMIT();
        }
        CP_WAIT1();
        __syncthreads();    // single barrier: publishes data + protects ring reuse

        if (tt == 0) {
            ldm4(qa[0], qa[1], qa[2], qa[3], sb + OFF_Q + qlane);
        }

        const uint32_t kbase = sb + OFF_K0 + (uint32_t)vb3 * 4096 + klane;
        const uint32_t vbase = sb + OFF_V0 + (uint32_t)vb3 * V_STRIDE + vlane;

        // ---- fused per-s-block, K-frag pipelined, packed bf16x2 exp
        uint32_t kf0, kf1, kf2, kf3;
        ldm4(kf0, kf1, kf2, kf3, kbase);
        #pragma unroll
        for (int s = 0; s < 8; s++) {
            float sc0[4] = {0.f, 0.f, 0.f, 0.f};
            float sc1[4] = {0.f, 0.f, 0.f, 0.f};
            mma_bf16(sc0, qa[0], qa[1], qa[2], qa[3], kf0, kf1);
            mma_bf16(sc1, qa[0], qa[1], qa[2], qa[3], kf2, kf3);
            if (s < 7) ldm4(kf0, kf1, kf2, kf3, kbase + (uint32_t)((s + 1) * 512));
            uint32_t a0 = ex2x2(bf2(sc0[1], sc0[0]));
            uint32_t a1 = ex2x2(bf2(sc0[3], sc0[2]));
            uint32_t a2 = ex2x2(bf2(sc1[1], sc1[0]));
            uint32_t a3 = ex2x2(bf2(sc1[3], sc1[2]));
            mma_bf16(ls, a0, a1, a2, a3, ONES2, ONES2);
            const uint32_t cs = (uint32_t)(((2 * s + ksel) ^ sx) << 4);
            #pragma unroll
            for (int nbp = 0; nbp < 8; nbp++) {
                uint32_t r0, r1, r2, r3;
                ldm4(r0, r1, r2, r3, vbase + (uint32_t)(nbp * 4096) + cs);
                mma_bf16(o[2*nbp],     a0, a1, a2, a3, r0, r1);
                mma_bf16(o[2*nbp + 1], a0, a1, a2, a3, r2, r3);
            }
        }
        vb3++; if (vb3 == 3) vb3 = 0;
    }

    const float il0 = 1.f / ls[0], il1 = 1.f / ls[2];

    uint32_t oa0[16], oa1[16];
    #pragma unroll
    for (int nb = 0; nb < 16; nb++) {
        oa0[nb] = bf2(o[nb][1] * il0, o[nb][0] * il0);
        oa1[nb] = bf2(o[nb][3] * il1, o[nb][2] * il1);
    }

    CP_WAIT0();          // pw arrived in V2
    __syncthreads();

    float pr[16][4];
    #pragma unroll
    for (int nb = 0; nb < 16; nb++)
        #pragma unroll
        for (int i = 0; i < 4; i++) pr[nb][i] = 0.f;
    const uint32_t pwbase = sb + OFF_V0 + 2 * V_STRIDE + vlane;
    #pragma unroll
    for (int s = 0; s < 8; s++) {
        const uint32_t a0 = oa0[2*s], a1 = oa1[2*s];
        const uint32_t a2 = oa0[2*s+1], a3 = oa1[2*s+1];
        const uint32_t cs = (uint32_t)(((2 * s + ksel) ^ sx) << 4);
        #pragma unroll
        for (int nbp = 0; nbp < 8; nbp++) {
            uint32_t r0, r1, r2, r3;
            ldm4(r0, r1, r2, r3, pwbase + (uint32_t)(nbp * 4096) + cs);
            mma_bf16(pr[2*nbp],     a0, a1, a2, a3, r0, r1);
            mma_bf16(pr[2*nbp + 1], a0, a1, a2, a3, r2, r3);
        }
    }
    __syncthreads();

    float* stg = (float*)(sm + OFF_STG);
    #pragma unroll
    for (int nb = 0; nb < 16; nb++) {
        int e = 8*nb + 2*t;
        stg[(e    ) * 132 + 16*w + g    ] = pr[nb][0];
        stg[(e + 1) * 132 + 16*w + g    ] = pr[nb][1];
        stg[(e    ) * 132 + 16*w + g + 8] = pr[nb][2];
        stg[(e + 1) * 132 + 16*w + g + 8] = pr[nb][3];
    }
    __syncthreads();

    #pragma unroll
    for (int it = 0; it < 16; it++) {
        int idx = tid + it * 256;
        int e = idx >> 5, qq = idx & 31;
        float4 v4 = *(float4*)&stg[e * 132 + qq * 4];
        float bias = __ldg(pb + e);
        size_t gi = ((size_t)b * C + e) * NN + q0 + qq * 4;
        float4 xr = *(const float4*)&x[gi];
        v4.x += bias + xr.x; v4.y += bias + xr.y;
        v4.z += bias + xr.z; v4.w += bias + xr.w;
        *(float4*)&out[gi] = v4;
    }
}

// ---------------- launch -----------------------------------------------------
extern "C" void kernel_launch(void* const* d_in, const int* in_sizes, int n_in,
                              void* d_out, int out_size)
{
    const float* x    = (const float*)d_in[0];
    const float* gn_w = (const float*)d_in[1];
    const float* gn_b = (const float*)d_in[2];
    const float* q_w  = (const float*)d_in[3];
    const float* q_b  = (const float*)d_in[4];
    const float* k_w  = (const float*)d_in[5];
    const float* k_b  = (const float*)d_in[6];
    const float* v_w  = (const float*)d_in[7];
    const float* v_b  = (const float*)d_in[8];
    const float* p_w  = (const float*)d_in[9];
    const float* p_b  = (const float*)d_in[10];
    float* out = (float*)d_out;

    float* st;
    __nv_bfloat16 *qt, *kt, *v, *pwb;
    cudaGetSymbolAddress((void**)&qt,  g_qt);
    cudaGetSymbolAddress((void**)&kt,  g_kt);
    cudaGetSymbolAddress((void**)&v,   g_v);
    cudaGetSymbolAddress((void**)&pwb, g_pwb);
    cudaGetSymbolAddress((void**)&st,  g_st);

    cudaFuncSetAttribute(flash_mma_kernel,
                         cudaFuncAttributeMaxDynamicSharedMemorySize, SMEM_FL);
    cudaFuncSetAttribute(qkv_proj_kernel,
                         cudaFuncAttributeMaxDynamicSharedMemorySize, SMEM_PJ);

    gn_stats_kernel<<<BATCH * G, 512>>>(x, st, p_w, pwb);

    qkv_proj_kernel<<<dim3(NN / 128, BATCH), 256, SMEM_PJ>>>(
        q_w, q_b, k_w, k_b, v_w, v_b, gn_w, gn_b, st, x, qt, kt, v);

    flash_mma_kernel<<<BATCH * 32, 256, SMEM_FL>>>(qt, kt, v, pwb, p_b, x, out);
}